// round 4
// baseline (speedup 1.0000x reference)
#include <cuda_runtime.h>
#include <math.h>
#include <stdint.h>

// ---------------- problem constants ----------------
#define BB 4
#define SS 4096
#define DD 1024
#define KW 4
#define MM (BB * SS)      // 16384
#define N1 (2 * DD)       // 2048
#define EPSV 1e-6f
#define LCH 128           // scan chunk length
#define NCH (SS / LCH)    // 32

// ---------------- scratch (__device__ globals; no allocs) ----------------
__device__ float g_h  [(size_t)MM * DD];   // rmsnorm(x) -> later gated y (tf32-rounded)
__device__ float g_xz [(size_t)MM * N1];   // GEMM1 out [xb | z]
__device__ float g_hs [(size_t)MM * DD];   // scan output
__device__ float g_wt1[(size_t)N1 * DD];   // in_w^T  [2048,1024] tf32-rounded
__device__ float g_wt2[(size_t)DD * DD];   // out_w^T [1024,1024] tf32-rounded
__device__ float g_last[(size_t)BB * NCH * DD];
__device__ float g_sin [(size_t)BB * NCH * DD];

// ---------------- helpers ----------------
__device__ __forceinline__ float tf32r(float x) {
    uint32_t u; asm("cvt.rn.tf32.f32 %0, %1;" : "=r"(u) : "f"(x));
    return __uint_as_float(u);
}
__device__ __forceinline__ float silu_f(float v) { return v / (1.f + __expf(-v)); }

__device__ __forceinline__ uint32_t smem_u32(const void* p) {
    uint32_t a;
    asm("{ .reg .u64 t; cvta.to.shared.u64 t, %1; cvt.u32.u64 %0, t; }" : "=r"(a) : "l"(p));
    return a;
}
__device__ __forceinline__ void cp16(uint32_t s, const void* g) {
    asm volatile("cp.async.cg.shared.global [%0], [%1], 16;" :: "r"(s), "l"(g) : "memory");
}
__device__ __forceinline__ void cp_commit() {
    asm volatile("cp.async.commit_group;" ::: "memory");
}
__device__ __forceinline__ void cp_wait2() {
    asm volatile("cp.async.wait_group 2;" ::: "memory");
}
__device__ __forceinline__ void cp_wait0() {
    asm volatile("cp.async.wait_group 0;" ::: "memory");
}

__device__ __forceinline__ void mma_tf32(float* c, const uint32_t* a, uint32_t b0, uint32_t b1) {
    asm volatile(
        "mma.sync.aligned.m16n8k8.row.col.f32.tf32.tf32.f32 "
        "{%0,%1,%2,%3}, {%4,%5,%6,%7}, {%8,%9}, {%0,%1,%2,%3};"
        : "+f"(c[0]), "+f"(c[1]), "+f"(c[2]), "+f"(c[3])
        : "r"(a[0]), "r"(a[1]), "r"(a[2]), "r"(a[3]), "r"(b0), "r"(b1));
}

// ---------------- block reduction (256 threads) ----------------
__device__ __forceinline__ float block_reduce_sum(float v) {
    __shared__ float red[8];
    int lane = threadIdx.x & 31, wid = threadIdx.x >> 5;
    #pragma unroll
    for (int o = 16; o > 0; o >>= 1) v += __shfl_xor_sync(0xffffffffu, v, o);
    if (lane == 0) red[wid] = v;
    __syncthreads();
    if (wid == 0) {
        v = (lane < 8) ? red[lane] : 0.f;
        #pragma unroll
        for (int o = 4; o > 0; o >>= 1) v += __shfl_xor_sync(0xffffffffu, v, o);
        if (lane == 0) red[0] = v;
    }
    __syncthreads();
    return red[0];
}

// ---------------- weight transpose + tf32 round: out[N,K] = round(in[K,N]^T) ----------------
__global__ __launch_bounds__(256) void transpose_kernel(
    const float* __restrict__ in, float* __restrict__ out, int Nn)
{
    __shared__ float tile[32][33];
    int n0 = blockIdx.x * 32, k0 = blockIdx.y * 32;
    int tx = threadIdx.x & 31, ty = threadIdx.x >> 5;
    #pragma unroll
    for (int i = 0; i < 32; i += 8)
        tile[ty + i][tx] = in[(size_t)(k0 + ty + i) * Nn + n0 + tx];
    __syncthreads();
    #pragma unroll
    for (int i = 0; i < 32; i += 8)
        out[(size_t)(n0 + ty + i) * DD + k0 + tx] = tf32r(tile[tx][ty + i]);
}

// ---------------- rmsnorm (tf32-rounded output) ----------------
__global__ __launch_bounds__(256) void rmsnorm_kernel(
    const float* __restrict__ x, const float* __restrict__ w, float* __restrict__ out)
{
    size_t row = blockIdx.x;
    float4 v = ((const float4*)(x + row * DD))[threadIdx.x];
    float ss = v.x * v.x + v.y * v.y + v.z * v.z + v.w * v.w;
    ss = block_reduce_sum(ss);
    float s = rsqrtf(ss * (1.f / DD) + EPSV);
    float4 wv = ((const float4*)w)[threadIdx.x];
    float4 o;
    o.x = tf32r(v.x * s * wv.x); o.y = tf32r(v.y * s * wv.y);
    o.z = tf32r(v.z * s * wv.z); o.w = tf32r(v.w * s * wv.w);
    ((float4*)(out + row * DD))[threadIdx.x] = o;
}

// ---------------- tf32 mma.sync GEMM ----------------
// C[M,N] = A[M,1024] @ Bt[N,1024]^T ; optional C += rs*resid
// 128x128 tile, BK=32, 4-stage cp.async, 16 warps (4x4), warp tile 32x32.
#define BKK 32
#define ASTR 36                      // padded float stride
#define SSTRIDE (128 * ASTR)         // floats per (A or B) stage
#define GSTG 4
#define GEMM_SMEM (GSTG * 2 * SSTRIDE * 4)

__global__ __launch_bounds__(512, 1) void gemm_tc_kernel(
    int Nn, const float* __restrict__ A, const float* __restrict__ Bt,
    float* __restrict__ C,
    const float* __restrict__ resid, const float* __restrict__ rs_ptr)
{
    extern __shared__ float sm[];
    const int tid = threadIdx.x, lane = tid & 31, wid = tid >> 5;
    const int mtile = blockIdx.y * 128, ntile = blockIdx.x * 128;
    const int wm = (wid & 3) * 32, wn = (wid >> 2) * 32;

    // loader mapping: 64 rows per pass, 2 passes per matrix; 8 threads x 16B per row
    const int lr = tid >> 3;            // 0..63
    const int lc = (tid & 7) * 4;       // 0,4,...,28

    const float* Ag = A  + (size_t)(mtile + lr) * DD + lc;
    const float* Bg = Bt + (size_t)(ntile + lr) * DD + lc;

    uint32_t smb = smem_u32(sm);

    auto stage_load = [&](int s, int kc) {
        uint32_t as = smb + (uint32_t)(s * 2 * SSTRIDE) * 4;
        uint32_t bs = as + SSTRIDE * 4;
        #pragma unroll
        for (int i = 0; i < 2; i++) {
            uint32_t so = (uint32_t)((lr + i * 64) * ASTR + lc) * 4;
            cp16(as + so, Ag + (size_t)i * 64 * DD + kc * BKK);
            cp16(bs + so, Bg + (size_t)i * 64 * DD + kc * BKK);
        }
        cp_commit();
    };

    float acc[2][4][4];
    #pragma unroll
    for (int mi = 0; mi < 2; mi++)
        #pragma unroll
        for (int ni = 0; ni < 4; ni++)
            #pragma unroll
            for (int j = 0; j < 4; j++) acc[mi][ni][j] = 0.f;

    const int NKC = DD / BKK;           // 32
    stage_load(0, 0);
    stage_load(1, 1);
    stage_load(2, 2);

    const int fr = lane >> 2, fc = lane & 3;

    for (int kc = 0; kc < NKC; kc++) {
        cp_wait2();
        __syncthreads();
        if (kc + 3 < NKC) stage_load((kc + 3) & (GSTG - 1), kc + 3);

        const float* as = sm + (kc & (GSTG - 1)) * 2 * SSTRIDE + (wm + fr) * ASTR + fc;
        const float* bs = sm + (kc & (GSTG - 1)) * 2 * SSTRIDE + SSTRIDE + (wn + fr) * ASTR + fc;

        #pragma unroll
        for (int kk = 0; kk < 4; kk++) {
            const int k0 = kk * 8;
            uint32_t a[2][4];
            #pragma unroll
            for (int mi = 0; mi < 2; mi++) {
                const float* ap = as + mi * 16 * ASTR + k0;
                a[mi][0] = __float_as_uint(ap[0]);
                a[mi][1] = __float_as_uint(ap[8 * ASTR]);
                a[mi][2] = __float_as_uint(ap[4]);
                a[mi][3] = __float_as_uint(ap[8 * ASTR + 4]);
            }
            #pragma unroll
            for (int ni = 0; ni < 4; ni++) {
                const float* bp = bs + ni * 8 * ASTR + k0;
                uint32_t b0 = __float_as_uint(bp[0]);
                uint32_t b1 = __float_as_uint(bp[4]);
                mma_tf32(acc[0][ni], a[0], b0, b1);
                mma_tf32(acc[1][ni], a[1], b0, b1);
            }
        }
        __syncthreads();
    }
    cp_wait0();

    // epilogue
    float rs = 0.f;
    if (resid) rs = __ldg(rs_ptr);
    #pragma unroll
    for (int mi = 0; mi < 2; mi++) {
        #pragma unroll
        for (int half = 0; half < 2; half++) {
            int row = mtile + wm + mi * 16 + half * 8 + fr;
            #pragma unroll
            for (int ni = 0; ni < 4; ni++) {
                int col = ntile + wn + ni * 8 + fc * 2;
                size_t off = (size_t)row * Nn + col;
                float2 v = make_float2(acc[mi][ni][half * 2], acc[mi][ni][half * 2 + 1]);
                if (resid) {
                    float2 rv = *(const float2*)(resid + off);
                    v.x = fmaf(rs, rv.x, v.x);
                    v.y = fmaf(rs, rv.y, v.y);
                }
                *(float2*)(C + off) = v;
            }
        }
    }
}

// ---------------- scan phase 1: local conv+silu+scan per 128-chunk ----------------
__global__ __launch_bounds__(256) void conv_local_kernel(
    const float* __restrict__ xz, const float* __restrict__ conv_w,
    const float* __restrict__ conv_b, const float* __restrict__ decay,
    float* __restrict__ hs, float* __restrict__ last)
{
    int idx = blockIdx.x * blockDim.x + threadIdx.x;   // BB*NCH*DD
    int d = idx % DD;
    int ch = (idx / DD) % NCH;
    int b = idx / (DD * NCH);

    float w0 = conv_w[d * KW + 0], w1 = conv_w[d * KW + 1];
    float w2 = conv_w[d * KW + 2], w3 = conv_w[d * KW + 3];
    float bias = conv_b[d];
    float a = 1.f / (1.f + __expf(-decay[d]));

    int t0 = ch * LCH;
    const float* xb = xz + ((size_t)b * SS + t0) * N1 + d;
    float* out = hs + ((size_t)b * SS + t0) * DD + d;

    float x0 = 0.f, x1 = 0.f, x2 = 0.f;
    if (ch > 0) {
        x0 = xb[-3 * (ptrdiff_t)N1];
        x1 = xb[-2 * (ptrdiff_t)N1];
        x2 = xb[-1 * (ptrdiff_t)N1];
    }
    float h = 0.f;
    #pragma unroll 4
    for (int t = 0; t < LCH; t++) {
        float x3 = xb[(size_t)t * N1];
        float c = fmaf(w0, x0, fmaf(w1, x1, fmaf(w2, x2, fmaf(w3, x3, bias))));
        c = silu_f(c);
        h = fmaf(a, h, c);
        out[(size_t)t * DD] = h;
        x0 = x1; x1 = x2; x2 = x3;
    }
    last[((size_t)b * NCH + ch) * DD + d] = h;
}

// ---------------- scan phase 2: carry chain ----------------
__global__ __launch_bounds__(256) void carry_kernel(
    const float* __restrict__ decay, const float* __restrict__ last,
    float* __restrict__ sin_)
{
    int idx = blockIdx.x * blockDim.x + threadIdx.x;   // BB*DD
    int d = idx % DD, b = idx / DD;
    float a = 1.f / (1.f + __expf(-decay[d]));
    float aL = a;
    #pragma unroll
    for (int i = 0; i < 7; i++) aL *= aL;              // a^128
    float c = 0.f;
    for (int j = 0; j < NCH; j++) {
        size_t o = ((size_t)b * NCH + j) * DD + d;
        sin_[o] = c;
        c = fmaf(aL, c, last[o]);
    }
}

// ---------------- scan phase 3: apply carries ----------------
__global__ __launch_bounds__(256) void fix_kernel(
    const float* __restrict__ decay, const float* __restrict__ sin_,
    float* __restrict__ hs)
{
    int idx = blockIdx.x * blockDim.x + threadIdx.x;   // BB*NCH*DD
    int d = idx % DD;
    int ch = (idx / DD) % NCH;
    int b = idx / (DD * NCH);
    float s = sin_[((size_t)b * NCH + ch) * DD + d];
    if (s == 0.f) return;
    float a = 1.f / (1.f + __expf(-decay[d]));
    float f = a * s;
    float* p = hs + ((size_t)b * SS + ch * LCH) * DD + d;
    for (int t = 0; t < LCH; t++) {
        if (fabsf(f) < 1e-14f) break;
        p[(size_t)t * DD] += f;
        f *= a;
    }
}

// ---------------- gated rmsnorm (tf32-rounded output) ----------------
__global__ __launch_bounds__(256) void gate_kernel(
    const float* __restrict__ hs, const float* __restrict__ gate_w,
    const float* __restrict__ xz, float* __restrict__ y)
{
    size_t row = blockIdx.x;
    float4 v = ((const float4*)(hs + row * DD))[threadIdx.x];
    float ss = v.x * v.x + v.y * v.y + v.z * v.z + v.w * v.w;
    ss = block_reduce_sum(ss);
    float s = rsqrtf(ss * (1.f / DD) + EPSV);
    float4 gw = ((const float4*)gate_w)[threadIdx.x];
    float4 zv = ((const float4*)(xz + row * N1 + DD))[threadIdx.x];
    float4 o;
    o.x = tf32r(v.x * s * gw.x * silu_f(zv.x));
    o.y = tf32r(v.y * s * gw.y * silu_f(zv.y));
    o.z = tf32r(v.z * s * gw.z * silu_f(zv.z));
    o.w = tf32r(v.w * s * gw.w * silu_f(zv.w));
    ((float4*)(y + row * DD))[threadIdx.x] = o;
}

// ---------------- host ----------------
extern "C" void kernel_launch(void* const* d_in, const int* in_sizes, int n_in,
                              void* d_out, int out_size)
{
    const float* x         = (const float*)d_in[0];
    const float* norm_w    = (const float*)d_in[1];
    const float* in_w      = (const float*)d_in[2];
    const float* conv_w    = (const float*)d_in[3];
    const float* conv_b    = (const float*)d_in[4];
    const float* decay     = (const float*)d_in[5];
    const float* gate_w    = (const float*)d_in[6];
    const float* out_w     = (const float*)d_in[7];
    const float* res_scale = (const float*)d_in[8];
    float* out = (float*)d_out;

    float *p_h, *p_xz, *p_hs, *p_wt1, *p_wt2, *p_last, *p_sin;
    cudaGetSymbolAddress((void**)&p_h,    g_h);
    cudaGetSymbolAddress((void**)&p_xz,   g_xz);
    cudaGetSymbolAddress((void**)&p_hs,   g_hs);
    cudaGetSymbolAddress((void**)&p_wt1,  g_wt1);
    cudaGetSymbolAddress((void**)&p_wt2,  g_wt2);
    cudaGetSymbolAddress((void**)&p_last, g_last);
    cudaGetSymbolAddress((void**)&p_sin,  g_sin);

    static bool smem_set = false;
    if (!smem_set) {
        cudaFuncSetAttribute(gemm_tc_kernel,
                             cudaFuncAttributeMaxDynamicSharedMemorySize, GEMM_SMEM);
        smem_set = true;
    }

    // 0. transpose + tf32-round weights
    transpose_kernel<<<dim3(N1 / 32, DD / 32), 256>>>(in_w,  p_wt1, N1);
    transpose_kernel<<<dim3(DD / 32, DD / 32), 256>>>(out_w, p_wt2, DD);

    // 1. h = rmsnorm(x) (tf32-rounded)
    rmsnorm_kernel<<<MM, 256>>>(x, norm_w, p_h);

    // 2. xz = h @ in_w
    gemm_tc_kernel<<<dim3(N1 / 128, MM / 128), 512, GEMM_SMEM>>>(
        N1, p_h, p_wt1, p_xz, nullptr, nullptr);

    // 3. chunked conv + scan
    conv_local_kernel<<<(BB * NCH * DD) / 256, 256>>>(p_xz, conv_w, conv_b, decay, p_hs, p_last);
    carry_kernel<<<(BB * DD) / 256, 256>>>(decay, p_last, p_sin);
    fix_kernel<<<(BB * NCH * DD) / 256, 256>>>(decay, p_sin, p_hs);

    // 4. y = rmsnorm(hs)*silu(z) (tf32-rounded) -> g_h
    gate_kernel<<<MM, 256>>>(p_hs, gate_w, p_xz, p_h);

    // 5. out = res_scale*x + y @ out_w
    gemm_tc_kernel<<<dim3(DD / 128, MM / 128), 512, GEMM_SMEM>>>(
        DD, p_h, p_wt2, out, x, res_scale);
}

// round 5
// speedup vs baseline: 1.0102x; 1.0102x over previous
#include <cuda_runtime.h>
#include <math.h>
#include <stdint.h>

// ---------------- problem constants ----------------
#define BB 4
#define SS 4096
#define DD 1024
#define KW 4
#define MM (BB * SS)      // 16384
#define N1 (2 * DD)       // 2048
#define EPSV 1e-6f
#define LCH 128           // scan chunk length
#define NCH (SS / LCH)    // 32

// ---------------- scratch (__device__ globals; no allocs) ----------------
__device__ float g_h  [(size_t)MM * DD];   // rmsnorm(x) -> later gated y (tf32-rounded)
__device__ float g_xz [(size_t)MM * N1];   // GEMM1 out [xb | z]
__device__ float g_hs [(size_t)MM * DD];   // scan output
__device__ float g_wt1[(size_t)N1 * DD];   // in_w^T  [2048,1024] tf32-rounded
__device__ float g_wt2[(size_t)DD * DD];   // out_w^T [1024,1024] tf32-rounded
__device__ float g_last[(size_t)BB * NCH * DD];
__device__ float g_sin [(size_t)BB * NCH * DD];

// ---------------- helpers ----------------
__device__ __forceinline__ float tf32r(float x) {
    uint32_t u; asm("cvt.rn.tf32.f32 %0, %1;" : "=r"(u) : "f"(x));
    return __uint_as_float(u);
}
__device__ __forceinline__ float silu_f(float v) { return v / (1.f + __expf(-v)); }

__device__ __forceinline__ uint32_t smem_u32(const void* p) {
    uint32_t a;
    asm("{ .reg .u64 t; cvta.to.shared.u64 t, %1; cvt.u32.u64 %0, t; }" : "=r"(a) : "l"(p));
    return a;
}
__device__ __forceinline__ void cp16(uint32_t s, const void* g) {
    asm volatile("cp.async.cg.shared.global [%0], [%1], 16;" :: "r"(s), "l"(g) : "memory");
}
__device__ __forceinline__ void cp_commit() {
    asm volatile("cp.async.commit_group;" ::: "memory");
}
__device__ __forceinline__ void cp_wait2() {
    asm volatile("cp.async.wait_group 2;" ::: "memory");
}
__device__ __forceinline__ void cp_wait0() {
    asm volatile("cp.async.wait_group 0;" ::: "memory");
}

__device__ __forceinline__ void mma_tf32(float* c, const uint32_t* a, uint32_t b0, uint32_t b1) {
    asm volatile(
        "mma.sync.aligned.m16n8k8.row.col.f32.tf32.tf32.f32 "
        "{%0,%1,%2,%3}, {%4,%5,%6,%7}, {%8,%9}, {%0,%1,%2,%3};"
        : "+f"(c[0]), "+f"(c[1]), "+f"(c[2]), "+f"(c[3])
        : "r"(a[0]), "r"(a[1]), "r"(a[2]), "r"(a[3]), "r"(b0), "r"(b1));
}

// ---------------- block reduction (256 threads) ----------------
__device__ __forceinline__ float block_reduce_sum(float v) {
    __shared__ float red[8];
    int lane = threadIdx.x & 31, wid = threadIdx.x >> 5;
    #pragma unroll
    for (int o = 16; o > 0; o >>= 1) v += __shfl_xor_sync(0xffffffffu, v, o);
    if (lane == 0) red[wid] = v;
    __syncthreads();
    if (wid == 0) {
        v = (lane < 8) ? red[lane] : 0.f;
        #pragma unroll
        for (int o = 4; o > 0; o >>= 1) v += __shfl_xor_sync(0xffffffffu, v, o);
        if (lane == 0) red[0] = v;
    }
    __syncthreads();
    return red[0];
}

// ---------------- weight transpose + tf32 round: out[N,K] = round(in[K,N]^T) ----------------
__global__ __launch_bounds__(256) void transpose_kernel(
    const float* __restrict__ in, float* __restrict__ out, int Nn)
{
    __shared__ float tile[32][33];
    int n0 = blockIdx.x * 32, k0 = blockIdx.y * 32;
    int tx = threadIdx.x & 31, ty = threadIdx.x >> 5;
    #pragma unroll
    for (int i = 0; i < 32; i += 8)
        tile[ty + i][tx] = in[(size_t)(k0 + ty + i) * Nn + n0 + tx];
    __syncthreads();
    #pragma unroll
    for (int i = 0; i < 32; i += 8)
        out[(size_t)(n0 + ty + i) * DD + k0 + tx] = tf32r(tile[tx][ty + i]);
}

// ---------------- rmsnorm (tf32-rounded output) ----------------
__global__ __launch_bounds__(256) void rmsnorm_kernel(
    const float* __restrict__ x, const float* __restrict__ w, float* __restrict__ out)
{
    size_t row = blockIdx.x;
    float4 v = ((const float4*)(x + row * DD))[threadIdx.x];
    float ss = v.x * v.x + v.y * v.y + v.z * v.z + v.w * v.w;
    ss = block_reduce_sum(ss);
    float s = rsqrtf(ss * (1.f / DD) + EPSV);
    float4 wv = ((const float4*)w)[threadIdx.x];
    float4 o;
    o.x = tf32r(v.x * s * wv.x); o.y = tf32r(v.y * s * wv.y);
    o.z = tf32r(v.z * s * wv.z); o.w = tf32r(v.w * s * wv.w);
    ((float4*)(out + row * DD))[threadIdx.x] = o;
}

// ---------------- tf32 mma.sync GEMM ----------------
// C[M,N] = A[M,1024] @ Bt[N,1024]^T ; optional C += rs*resid
// Block tile 256x128, BK=16, 4-stage cp.async, 8 warps (4x2), warp tile 64x64.
// LDS/MMA = 1.0 (vs 1.5 in R3, 2.0 in R4) — attacks the measured LSU bound.
#define BKK 16
#define ASTR 20                       // padded float stride (16 + 4)
#define BM 256
#define BN 128
#define A_FLOATS (BM * ASTR)          // 5120
#define B_FLOATS (BN * ASTR)          // 2560
#define STG_FLOATS (A_FLOATS + B_FLOATS)  // 7680
#define GSTG 4
#define GEMM_SMEM (GSTG * STG_FLOATS * 4) // 122880 B

__global__ __launch_bounds__(256, 1) void gemm_tc_kernel(
    int Nn, const float* __restrict__ A, const float* __restrict__ Bt,
    float* __restrict__ C,
    const float* __restrict__ resid, const float* __restrict__ rs_ptr)
{
    extern __shared__ float sm[];
    const int tid = threadIdx.x, lane = tid & 31, wid = tid >> 5;
    const int mtile = blockIdx.y * BM, ntile = blockIdx.x * BN;
    const int wm = (wid & 3) * 64, wn = (wid >> 2) * 64;

    // loader mapping: 4 threads x 16B per 16-float row; 64 rows per pass
    const int lr = tid >> 2;            // 0..63
    const int lc = (tid & 3) * 4;       // 0,4,8,12

    const float* Ag = A  + (size_t)(mtile + lr) * DD + lc;
    const float* Bg = Bt + (size_t)(ntile + lr) * DD + lc;

    uint32_t smb = smem_u32(sm);

    auto stage_load = [&](int s, int kc) {
        uint32_t as = smb + (uint32_t)(s * STG_FLOATS) * 4;
        uint32_t bs = as + A_FLOATS * 4;
        #pragma unroll
        for (int i = 0; i < 4; i++)     // A: 256 rows
            cp16(as + (uint32_t)((lr + i * 64) * ASTR + lc) * 4,
                 Ag + (size_t)i * 64 * DD + kc * BKK);
        #pragma unroll
        for (int i = 0; i < 2; i++)     // B: 128 rows
            cp16(bs + (uint32_t)((lr + i * 64) * ASTR + lc) * 4,
                 Bg + (size_t)i * 64 * DD + kc * BKK);
        cp_commit();
    };

    float acc[4][8][4];
    #pragma unroll
    for (int mi = 0; mi < 4; mi++)
        #pragma unroll
        for (int ni = 0; ni < 8; ni++)
            #pragma unroll
            for (int j = 0; j < 4; j++) acc[mi][ni][j] = 0.f;

    const int NKC = DD / BKK;           // 64
    stage_load(0, 0);
    stage_load(1, 1);
    stage_load(2, 2);

    const int fr = lane >> 2, fc = lane & 3;

    for (int kc = 0; kc < NKC; kc++) {
        cp_wait2();
        __syncthreads();
        if (kc + 3 < NKC) stage_load((kc + 3) & (GSTG - 1), kc + 3);

        const float* as = sm + (kc & (GSTG - 1)) * STG_FLOATS + (wm + fr) * ASTR + fc;
        const float* bs = sm + (kc & (GSTG - 1)) * STG_FLOATS + A_FLOATS + (wn + fr) * ASTR + fc;

        #pragma unroll
        for (int kk = 0; kk < 2; kk++) {
            const int k0 = kk * 8;
            uint32_t a[4][4];
            #pragma unroll
            for (int mi = 0; mi < 4; mi++) {
                const float* ap = as + mi * 16 * ASTR + k0;
                a[mi][0] = __float_as_uint(ap[0]);
                a[mi][1] = __float_as_uint(ap[8 * ASTR]);
                a[mi][2] = __float_as_uint(ap[4]);
                a[mi][3] = __float_as_uint(ap[8 * ASTR + 4]);
            }
            #pragma unroll
            for (int ni = 0; ni < 8; ni++) {
                const float* bp = bs + ni * 8 * ASTR + k0;
                uint32_t b0 = __float_as_uint(bp[0]);
                uint32_t b1 = __float_as_uint(bp[4]);
                #pragma unroll
                for (int mi = 0; mi < 4; mi++)
                    mma_tf32(acc[mi][ni], a[mi], b0, b1);
            }
        }
        __syncthreads();
    }
    cp_wait0();

    // epilogue
    float rs = 0.f;
    if (resid) rs = __ldg(rs_ptr);
    #pragma unroll
    for (int mi = 0; mi < 4; mi++) {
        #pragma unroll
        for (int half = 0; half < 2; half++) {
            int row = mtile + wm + mi * 16 + half * 8 + fr;
            #pragma unroll
            for (int ni = 0; ni < 8; ni++) {
                int col = ntile + wn + ni * 8 + fc * 2;
                size_t off = (size_t)row * Nn + col;
                float2 v = make_float2(acc[mi][ni][half * 2], acc[mi][ni][half * 2 + 1]);
                if (resid) {
                    float2 rv = *(const float2*)(resid + off);
                    v.x = fmaf(rs, rv.x, v.x);
                    v.y = fmaf(rs, rv.y, v.y);
                }
                *(float2*)(C + off) = v;
            }
        }
    }
}

// ---------------- scan phase 1: local conv+silu+scan per 128-chunk ----------------
__global__ __launch_bounds__(256) void conv_local_kernel(
    const float* __restrict__ xz, const float* __restrict__ conv_w,
    const float* __restrict__ conv_b, const float* __restrict__ decay,
    float* __restrict__ hs, float* __restrict__ last)
{
    int idx = blockIdx.x * blockDim.x + threadIdx.x;   // BB*NCH*DD
    int d = idx % DD;
    int ch = (idx / DD) % NCH;
    int b = idx / (DD * NCH);

    float w0 = conv_w[d * KW + 0], w1 = conv_w[d * KW + 1];
    float w2 = conv_w[d * KW + 2], w3 = conv_w[d * KW + 3];
    float bias = conv_b[d];
    float a = 1.f / (1.f + __expf(-decay[d]));

    int t0 = ch * LCH;
    const float* xb = xz + ((size_t)b * SS + t0) * N1 + d;
    float* out = hs + ((size_t)b * SS + t0) * DD + d;

    float x0 = 0.f, x1 = 0.f, x2 = 0.f;
    if (ch > 0) {
        x0 = xb[-3 * (ptrdiff_t)N1];
        x1 = xb[-2 * (ptrdiff_t)N1];
        x2 = xb[-1 * (ptrdiff_t)N1];
    }
    float h = 0.f;
    #pragma unroll 4
    for (int t = 0; t < LCH; t++) {
        float x3 = xb[(size_t)t * N1];
        float c = fmaf(w0, x0, fmaf(w1, x1, fmaf(w2, x2, fmaf(w3, x3, bias))));
        c = silu_f(c);
        h = fmaf(a, h, c);
        out[(size_t)t * DD] = h;
        x0 = x1; x1 = x2; x2 = x3;
    }
    last[((size_t)b * NCH + ch) * DD + d] = h;
}

// ---------------- scan phase 2: carry chain ----------------
__global__ __launch_bounds__(256) void carry_kernel(
    const float* __restrict__ decay, const float* __restrict__ last,
    float* __restrict__ sin_)
{
    int idx = blockIdx.x * blockDim.x + threadIdx.x;   // BB*DD
    int d = idx % DD, b = idx / DD;
    float a = 1.f / (1.f + __expf(-decay[d]));
    float aL = a;
    #pragma unroll
    for (int i = 0; i < 7; i++) aL *= aL;              // a^128
    float c = 0.f;
    for (int j = 0; j < NCH; j++) {
        size_t o = ((size_t)b * NCH + j) * DD + d;
        sin_[o] = c;
        c = fmaf(aL, c, last[o]);
    }
}

// ---------------- scan phase 3: apply carries ----------------
__global__ __launch_bounds__(256) void fix_kernel(
    const float* __restrict__ decay, const float* __restrict__ sin_,
    float* __restrict__ hs)
{
    int idx = blockIdx.x * blockDim.x + threadIdx.x;   // BB*NCH*DD
    int d = idx % DD;
    int ch = (idx / DD) % NCH;
    int b = idx / (DD * NCH);
    float s = sin_[((size_t)b * NCH + ch) * DD + d];
    if (s == 0.f) return;
    float a = 1.f / (1.f + __expf(-decay[d]));
    float f = a * s;
    float* p = hs + ((size_t)b * SS + ch * LCH) * DD + d;
    for (int t = 0; t < LCH; t++) {
        if (fabsf(f) < 1e-14f) break;
        p[(size_t)t * DD] += f;
        f *= a;
    }
}

// ---------------- gated rmsnorm (tf32-rounded output) ----------------
__global__ __launch_bounds__(256) void gate_kernel(
    const float* __restrict__ hs, const float* __restrict__ gate_w,
    const float* __restrict__ xz, float* __restrict__ y)
{
    size_t row = blockIdx.x;
    float4 v = ((const float4*)(hs + row * DD))[threadIdx.x];
    float ss = v.x * v.x + v.y * v.y + v.z * v.z + v.w * v.w;
    ss = block_reduce_sum(ss);
    float s = rsqrtf(ss * (1.f / DD) + EPSV);
    float4 gw = ((const float4*)gate_w)[threadIdx.x];
    float4 zv = ((const float4*)(xz + row * N1 + DD))[threadIdx.x];
    float4 o;
    o.x = tf32r(v.x * s * gw.x * silu_f(zv.x));
    o.y = tf32r(v.y * s * gw.y * silu_f(zv.y));
    o.z = tf32r(v.z * s * gw.z * silu_f(zv.z));
    o.w = tf32r(v.w * s * gw.w * silu_f(zv.w));
    ((float4*)(y + row * DD))[threadIdx.x] = o;
}

// ---------------- host ----------------
extern "C" void kernel_launch(void* const* d_in, const int* in_sizes, int n_in,
                              void* d_out, int out_size)
{
    const float* x         = (const float*)d_in[0];
    const float* norm_w    = (const float*)d_in[1];
    const float* in_w      = (const float*)d_in[2];
    const float* conv_w    = (const float*)d_in[3];
    const float* conv_b    = (const float*)d_in[4];
    const float* decay     = (const float*)d_in[5];
    const float* gate_w    = (const float*)d_in[6];
    const float* out_w     = (const float*)d_in[7];
    const float* res_scale = (const float*)d_in[8];
    float* out = (float*)d_out;

    float *p_h, *p_xz, *p_hs, *p_wt1, *p_wt2, *p_last, *p_sin;
    cudaGetSymbolAddress((void**)&p_h,    g_h);
    cudaGetSymbolAddress((void**)&p_xz,   g_xz);
    cudaGetSymbolAddress((void**)&p_hs,   g_hs);
    cudaGetSymbolAddress((void**)&p_wt1,  g_wt1);
    cudaGetSymbolAddress((void**)&p_wt2,  g_wt2);
    cudaGetSymbolAddress((void**)&p_last, g_last);
    cudaGetSymbolAddress((void**)&p_sin,  g_sin);

    static bool smem_set = false;
    if (!smem_set) {
        cudaFuncSetAttribute(gemm_tc_kernel,
                             cudaFuncAttributeMaxDynamicSharedMemorySize, GEMM_SMEM);
        smem_set = true;
    }

    // 0. transpose + tf32-round weights
    transpose_kernel<<<dim3(N1 / 32, DD / 32), 256>>>(in_w,  p_wt1, N1);
    transpose_kernel<<<dim3(DD / 32, DD / 32), 256>>>(out_w, p_wt2, DD);

    // 1. h = rmsnorm(x) (tf32-rounded)
    rmsnorm_kernel<<<MM, 256>>>(x, norm_w, p_h);

    // 2. xz = h @ in_w
    gemm_tc_kernel<<<dim3(N1 / BN, MM / BM), 256, GEMM_SMEM>>>(
        N1, p_h, p_wt1, p_xz, nullptr, nullptr);

    // 3. chunked conv + scan
    conv_local_kernel<<<(BB * NCH * DD) / 256, 256>>>(p_xz, conv_w, conv_b, decay, p_hs, p_last);
    carry_kernel<<<(BB * DD) / 256, 256>>>(decay, p_last, p_sin);
    fix_kernel<<<(BB * NCH * DD) / 256, 256>>>(decay, p_sin, p_hs);

    // 4. y = rmsnorm(hs)*silu(z) (tf32-rounded) -> g_h
    gate_kernel<<<MM, 256>>>(p_hs, gate_w, p_xz, p_h);

    // 5. out = res_scale*x + y @ out_w
    gemm_tc_kernel<<<dim3(DD / BN, MM / BM), 256, GEMM_SMEM>>>(
        DD, p_h, p_wt2, out, x, res_scale);
}

// round 6
// speedup vs baseline: 1.1364x; 1.1249x over previous
#include <cuda_runtime.h>
#include <math.h>
#include <stdint.h>

// ---------------- problem constants ----------------
#define BB 4
#define SS 4096
#define DD 1024
#define KW 4
#define MM (BB * SS)      // 16384
#define N1 (2 * DD)       // 2048
#define EPSV 1e-6f
#define LCH 128           // scan chunk length
#define NCH (SS / LCH)    // 32

// ---------------- scratch (__device__ globals; no allocs) ----------------
__device__ float g_h  [(size_t)MM * DD];   // rmsnorm(x) -> later gated y (tf32-rounded)
__device__ float g_xz [(size_t)MM * N1];   // GEMM1 out [xb | z]
__device__ float g_hs [(size_t)MM * DD];   // scan output
__device__ float g_wt1[(size_t)N1 * DD];   // in_w^T  [2048,1024] tf32-rounded
__device__ float g_wt2[(size_t)DD * DD];   // out_w^T [1024,1024] tf32-rounded
__device__ float g_last[(size_t)BB * NCH * DD];
__device__ float g_sin [(size_t)BB * NCH * DD];

// ---------------- helpers ----------------
__device__ __forceinline__ float tf32r(float x) {
    uint32_t u; asm("cvt.rn.tf32.f32 %0, %1;" : "=r"(u) : "f"(x));
    return __uint_as_float(u);
}
__device__ __forceinline__ float silu_f(float v) { return v / (1.f + __expf(-v)); }

__device__ __forceinline__ uint32_t smem_u32(const void* p) {
    uint32_t a;
    asm("{ .reg .u64 t; cvta.to.shared.u64 t, %1; cvt.u32.u64 %0, t; }" : "=r"(a) : "l"(p));
    return a;
}
__device__ __forceinline__ void cp16(uint32_t s, const void* g) {
    asm volatile("cp.async.cg.shared.global [%0], [%1], 16;" :: "r"(s), "l"(g) : "memory");
}
__device__ __forceinline__ void cp_commit() {
    asm volatile("cp.async.commit_group;" ::: "memory");
}
__device__ __forceinline__ void cp_wait1() {
    asm volatile("cp.async.wait_group 1;" ::: "memory");
}
__device__ __forceinline__ void cp_wait0() {
    asm volatile("cp.async.wait_group 0;" ::: "memory");
}

__device__ __forceinline__ void mma_tf32(float* c, const uint32_t* a, uint32_t b0, uint32_t b1) {
    asm volatile(
        "mma.sync.aligned.m16n8k8.row.col.f32.tf32.tf32.f32 "
        "{%0,%1,%2,%3}, {%4,%5,%6,%7}, {%8,%9}, {%0,%1,%2,%3};"
        : "+f"(c[0]), "+f"(c[1]), "+f"(c[2]), "+f"(c[3])
        : "r"(a[0]), "r"(a[1]), "r"(a[2]), "r"(a[3]), "r"(b0), "r"(b1));
}

// ---------------- block reduction (256 threads) ----------------
__device__ __forceinline__ float block_reduce_sum(float v) {
    __shared__ float red[8];
    int lane = threadIdx.x & 31, wid = threadIdx.x >> 5;
    #pragma unroll
    for (int o = 16; o > 0; o >>= 1) v += __shfl_xor_sync(0xffffffffu, v, o);
    if (lane == 0) red[wid] = v;
    __syncthreads();
    if (wid == 0) {
        v = (lane < 8) ? red[lane] : 0.f;
        #pragma unroll
        for (int o = 4; o > 0; o >>= 1) v += __shfl_xor_sync(0xffffffffu, v, o);
        if (lane == 0) red[0] = v;
    }
    __syncthreads();
    return red[0];
}

// ---------------- weight transpose + tf32 round: out[N,K] = round(in[K,N]^T) ----------------
__global__ __launch_bounds__(256) void transpose_kernel(
    const float* __restrict__ in, float* __restrict__ out, int Nn)
{
    __shared__ float tile[32][33];
    int n0 = blockIdx.x * 32, k0 = blockIdx.y * 32;
    int tx = threadIdx.x & 31, ty = threadIdx.x >> 5;
    #pragma unroll
    for (int i = 0; i < 32; i += 8)
        tile[ty + i][tx] = in[(size_t)(k0 + ty + i) * Nn + n0 + tx];
    __syncthreads();
    #pragma unroll
    for (int i = 0; i < 32; i += 8)
        out[(size_t)(n0 + ty + i) * DD + k0 + tx] = tf32r(tile[tx][ty + i]);
}

// ---------------- rmsnorm (tf32-rounded output) ----------------
__global__ __launch_bounds__(256) void rmsnorm_kernel(
    const float* __restrict__ x, const float* __restrict__ w, float* __restrict__ out)
{
    size_t row = blockIdx.x;
    float4 v = ((const float4*)(x + row * DD))[threadIdx.x];
    float ss = v.x * v.x + v.y * v.y + v.z * v.z + v.w * v.w;
    ss = block_reduce_sum(ss);
    float s = rsqrtf(ss * (1.f / DD) + EPSV);
    float4 wv = ((const float4*)w)[threadIdx.x];
    float4 o;
    o.x = tf32r(v.x * s * wv.x); o.y = tf32r(v.y * s * wv.y);
    o.z = tf32r(v.z * s * wv.z); o.w = tf32r(v.w * s * wv.w);
    ((float4*)(out + row * DD))[threadIdx.x] = o;
}

// ---------------- tf32 mma.sync GEMM ----------------
// C[M,N] = A[M,1024] @ Bt[N,1024]^T ; optional C += rs*resid
// Block 256x128, BK=32, 3-stage cp.async, 8 warps (4x2), warp tile 64x64.
// Register double-buffered fragments: LDS for slice kk+1 overlaps MMA of kk.
#define BKK 32
#define ASTR 36                       // padded float stride (32 + 4)
#define BM 256
#define BN 128
#define A_FLOATS (BM * ASTR)          // 9216
#define B_FLOATS (BN * ASTR)          // 4608
#define STG_FLOATS (A_FLOATS + B_FLOATS)  // 13824
#define GSTG 3
#define GEMM_SMEM (GSTG * STG_FLOATS * 4) // 165888 B

__global__ __launch_bounds__(256, 1) void gemm_tc_kernel(
    int Nn, const float* __restrict__ A, const float* __restrict__ Bt,
    float* __restrict__ C,
    const float* __restrict__ resid, const float* __restrict__ rs_ptr)
{
    extern __shared__ float sm[];
    const int tid = threadIdx.x, lane = tid & 31, wid = tid >> 5;
    const int mtile = blockIdx.y * BM, ntile = blockIdx.x * BN;
    const int wm = (wid & 3) * 64, wn = (wid >> 2) * 64;

    // loader mapping: 8 threads x 16B per 32-float row; 32 rows per pass
    const int lr = tid >> 3;            // 0..31
    const int lc = (tid & 7) * 4;       // 0..28

    const float* Ag = A  + (size_t)(mtile + lr) * DD + lc;
    const float* Bg = Bt + (size_t)(ntile + lr) * DD + lc;

    uint32_t smb = smem_u32(sm);

    auto stage_load = [&](int s, int kc) {
        uint32_t as = smb + (uint32_t)(s * STG_FLOATS) * 4;
        uint32_t bs = as + A_FLOATS * 4;
        #pragma unroll
        for (int i = 0; i < 8; i++)     // A: 256 rows
            cp16(as + (uint32_t)((lr + i * 32) * ASTR + lc) * 4,
                 Ag + (size_t)i * 32 * DD + kc * BKK);
        #pragma unroll
        for (int i = 0; i < 4; i++)     // B: 128 rows
            cp16(bs + (uint32_t)((lr + i * 32) * ASTR + lc) * 4,
                 Bg + (size_t)i * 32 * DD + kc * BKK);
        cp_commit();
    };

    float acc[4][8][4];
    #pragma unroll
    for (int mi = 0; mi < 4; mi++)
        #pragma unroll
        for (int ni = 0; ni < 8; ni++)
            #pragma unroll
            for (int j = 0; j < 4; j++) acc[mi][ni][j] = 0.f;

    const int NKC = DD / BKK;           // 32
    stage_load(0, 0);
    stage_load(1, 1);

    const int fr = lane >> 2, fc = lane & 3;

    uint32_t a[2][4][4];
    uint32_t b[2][8][2];

    for (int kc = 0; kc < NKC; kc++) {
        cp_wait1();                      // chunk kc resident
        __syncthreads();
        if (kc + 2 < NKC) stage_load((kc + 2) % GSTG, kc + 2);
        else cp_commit();                // keep group accounting exact

        const float* as = sm + (kc % GSTG) * STG_FLOATS + (wm + fr) * ASTR + fc;
        const float* bs = sm + (kc % GSTG) * STG_FLOATS + A_FLOATS + (wn + fr) * ASTR + fc;

        // prime k-slice 0
        #pragma unroll
        for (int mi = 0; mi < 4; mi++) {
            const float* ap = as + mi * 16 * ASTR;
            a[0][mi][0] = __float_as_uint(ap[0]);
            a[0][mi][1] = __float_as_uint(ap[8 * ASTR]);
            a[0][mi][2] = __float_as_uint(ap[4]);
            a[0][mi][3] = __float_as_uint(ap[8 * ASTR + 4]);
        }
        #pragma unroll
        for (int ni = 0; ni < 8; ni++) {
            const float* bp = bs + ni * 8 * ASTR;
            b[0][ni][0] = __float_as_uint(bp[0]);
            b[0][ni][1] = __float_as_uint(bp[4]);
        }

        #pragma unroll
        for (int kk = 0; kk < 4; kk++) {
            const int cur = kk & 1, nxt = cur ^ 1;
            if (kk < 3) {                // prefetch slice kk+1 while MMAing kk
                const int k0 = (kk + 1) * 8;
                #pragma unroll
                for (int mi = 0; mi < 4; mi++) {
                    const float* ap = as + mi * 16 * ASTR + k0;
                    a[nxt][mi][0] = __float_as_uint(ap[0]);
                    a[nxt][mi][1] = __float_as_uint(ap[8 * ASTR]);
                    a[nxt][mi][2] = __float_as_uint(ap[4]);
                    a[nxt][mi][3] = __float_as_uint(ap[8 * ASTR + 4]);
                }
                #pragma unroll
                for (int ni = 0; ni < 8; ni++) {
                    const float* bp = bs + ni * 8 * ASTR + k0;
                    b[nxt][ni][0] = __float_as_uint(bp[0]);
                    b[nxt][ni][1] = __float_as_uint(bp[4]);
                }
            }
            #pragma unroll
            for (int ni = 0; ni < 8; ni++)
                #pragma unroll
                for (int mi = 0; mi < 4; mi++)
                    mma_tf32(acc[mi][ni], a[cur][mi], b[cur][ni][0], b[cur][ni][1]);
        }
        __syncthreads();
    }
    cp_wait0();

    // epilogue
    float rs = 0.f;
    if (resid) rs = __ldg(rs_ptr);
    #pragma unroll
    for (int mi = 0; mi < 4; mi++) {
        #pragma unroll
        for (int half = 0; half < 2; half++) {
            int row = mtile + wm + mi * 16 + half * 8 + fr;
            #pragma unroll
            for (int ni = 0; ni < 8; ni++) {
                int col = ntile + wn + ni * 8 + fc * 2;
                size_t off = (size_t)row * Nn + col;
                float2 v = make_float2(acc[mi][ni][half * 2], acc[mi][ni][half * 2 + 1]);
                if (resid) {
                    float2 rv = *(const float2*)(resid + off);
                    v.x = fmaf(rs, rv.x, v.x);
                    v.y = fmaf(rs, rv.y, v.y);
                }
                *(float2*)(C + off) = v;
            }
        }
    }
}

// ---------------- scan phase 1: local conv+silu+scan per 128-chunk ----------------
__global__ __launch_bounds__(256) void conv_local_kernel(
    const float* __restrict__ xz, const float* __restrict__ conv_w,
    const float* __restrict__ conv_b, const float* __restrict__ decay,
    float* __restrict__ hs, float* __restrict__ last)
{
    int idx = blockIdx.x * blockDim.x + threadIdx.x;   // BB*NCH*DD
    int d = idx % DD;
    int ch = (idx / DD) % NCH;
    int b = idx / (DD * NCH);

    float w0 = conv_w[d * KW + 0], w1 = conv_w[d * KW + 1];
    float w2 = conv_w[d * KW + 2], w3 = conv_w[d * KW + 3];
    float bias = conv_b[d];
    float a = 1.f / (1.f + __expf(-decay[d]));

    int t0 = ch * LCH;
    const float* xb = xz + ((size_t)b * SS + t0) * N1 + d;
    float* out = hs + ((size_t)b * SS + t0) * DD + d;

    float x0 = 0.f, x1 = 0.f, x2 = 0.f;
    if (ch > 0) {
        x0 = xb[-3 * (ptrdiff_t)N1];
        x1 = xb[-2 * (ptrdiff_t)N1];
        x2 = xb[-1 * (ptrdiff_t)N1];
    }
    float h = 0.f;
    #pragma unroll 4
    for (int t = 0; t < LCH; t++) {
        float x3 = xb[(size_t)t * N1];
        float c = fmaf(w0, x0, fmaf(w1, x1, fmaf(w2, x2, fmaf(w3, x3, bias))));
        c = silu_f(c);
        h = fmaf(a, h, c);
        out[(size_t)t * DD] = h;
        x0 = x1; x1 = x2; x2 = x3;
    }
    last[((size_t)b * NCH + ch) * DD + d] = h;
}

// ---------------- scan phase 2: carry chain ----------------
__global__ __launch_bounds__(256) void carry_kernel(
    const float* __restrict__ decay, const float* __restrict__ last,
    float* __restrict__ sin_)
{
    int idx = blockIdx.x * blockDim.x + threadIdx.x;   // BB*DD
    int d = idx % DD, b = idx / DD;
    float a = 1.f / (1.f + __expf(-decay[d]));
    float aL = a;
    #pragma unroll
    for (int i = 0; i < 7; i++) aL *= aL;              // a^128
    float c = 0.f;
    for (int j = 0; j < NCH; j++) {
        size_t o = ((size_t)b * NCH + j) * DD + d;
        sin_[o] = c;
        c = fmaf(aL, c, last[o]);
    }
}

// ---------------- scan phase 3: apply carries ----------------
__global__ __launch_bounds__(256) void fix_kernel(
    const float* __restrict__ decay, const float* __restrict__ sin_,
    float* __restrict__ hs)
{
    int idx = blockIdx.x * blockDim.x + threadIdx.x;   // BB*NCH*DD
    int d = idx % DD;
    int ch = (idx / DD) % NCH;
    int b = idx / (DD * NCH);
    float s = sin_[((size_t)b * NCH + ch) * DD + d];
    if (s == 0.f) return;
    float a = 1.f / (1.f + __expf(-decay[d]));
    float f = a * s;
    float* p = hs + ((size_t)b * SS + ch * LCH) * DD + d;
    for (int t = 0; t < LCH; t++) {
        if (fabsf(f) < 1e-14f) break;
        p[(size_t)t * DD] += f;
        f *= a;
    }
}

// ---------------- gated rmsnorm (tf32-rounded output) ----------------
__global__ __launch_bounds__(256) void gate_kernel(
    const float* __restrict__ hs, const float* __restrict__ gate_w,
    const float* __restrict__ xz, float* __restrict__ y)
{
    size_t row = blockIdx.x;
    float4 v = ((const float4*)(hs + row * DD))[threadIdx.x];
    float ss = v.x * v.x + v.y * v.y + v.z * v.z + v.w * v.w;
    ss = block_reduce_sum(ss);
    float s = rsqrtf(ss * (1.f / DD) + EPSV);
    float4 gw = ((const float4*)gate_w)[threadIdx.x];
    float4 zv = ((const float4*)(xz + row * N1 + DD))[threadIdx.x];
    float4 o;
    o.x = tf32r(v.x * s * gw.x * silu_f(zv.x));
    o.y = tf32r(v.y * s * gw.y * silu_f(zv.y));
    o.z = tf32r(v.z * s * gw.z * silu_f(zv.z));
    o.w = tf32r(v.w * s * gw.w * silu_f(zv.w));
    ((float4*)(y + row * DD))[threadIdx.x] = o;
}

// ---------------- host ----------------
extern "C" void kernel_launch(void* const* d_in, const int* in_sizes, int n_in,
                              void* d_out, int out_size)
{
    const float* x         = (const float*)d_in[0];
    const float* norm_w    = (const float*)d_in[1];
    const float* in_w      = (const float*)d_in[2];
    const float* conv_w    = (const float*)d_in[3];
    const float* conv_b    = (const float*)d_in[4];
    const float* decay     = (const float*)d_in[5];
    const float* gate_w    = (const float*)d_in[6];
    const float* out_w     = (const float*)d_in[7];
    const float* res_scale = (const float*)d_in[8];
    float* out = (float*)d_out;

    float *p_h, *p_xz, *p_hs, *p_wt1, *p_wt2, *p_last, *p_sin;
    cudaGetSymbolAddress((void**)&p_h,    g_h);
    cudaGetSymbolAddress((void**)&p_xz,   g_xz);
    cudaGetSymbolAddress((void**)&p_hs,   g_hs);
    cudaGetSymbolAddress((void**)&p_wt1,  g_wt1);
    cudaGetSymbolAddress((void**)&p_wt2,  g_wt2);
    cudaGetSymbolAddress((void**)&p_last, g_last);
    cudaGetSymbolAddress((void**)&p_sin,  g_sin);

    static bool smem_set = false;
    if (!smem_set) {
        cudaFuncSetAttribute(gemm_tc_kernel,
                             cudaFuncAttributeMaxDynamicSharedMemorySize, GEMM_SMEM);
        smem_set = true;
    }

    // 0. transpose + tf32-round weights
    transpose_kernel<<<dim3(N1 / 32, DD / 32), 256>>>(in_w,  p_wt1, N1);
    transpose_kernel<<<dim3(DD / 32, DD / 32), 256>>>(out_w, p_wt2, DD);

    // 1. h = rmsnorm(x) (tf32-rounded)
    rmsnorm_kernel<<<MM, 256>>>(x, norm_w, p_h);

    // 2. xz = h @ in_w
    gemm_tc_kernel<<<dim3(N1 / BN, MM / BM), 256, GEMM_SMEM>>>(
        N1, p_h, p_wt1, p_xz, nullptr, nullptr);

    // 3. chunked conv + scan
    conv_local_kernel<<<(BB * NCH * DD) / 256, 256>>>(p_xz, conv_w, conv_b, decay, p_hs, p_last);
    carry_kernel<<<(BB * DD) / 256, 256>>>(decay, p_last, p_sin);
    fix_kernel<<<(BB * NCH * DD) / 256, 256>>>(decay, p_sin, p_hs);

    // 4. y = rmsnorm(hs)*silu(z) (tf32-rounded) -> g_h
    gate_kernel<<<MM, 256>>>(p_hs, gate_w, p_xz, p_h);

    // 5. out = res_scale*x + y @ out_w
    gemm_tc_kernel<<<dim3(DD / BN, MM / BM), 256, GEMM_SMEM>>>(
        DD, p_h, p_wt2, out, x, res_scale);
}

// round 7
// speedup vs baseline: 1.1670x; 1.0269x over previous
#include <cuda_runtime.h>
#include <math.h>
#include <stdint.h>

// ---------------- problem constants ----------------
#define BB 4
#define SS 4096
#define DD 1024
#define KW 4
#define MM (BB * SS)      // 16384
#define N1 (2 * DD)       // 2048
#define EPSV 1e-6f
#define LCH 128           // scan chunk length
#define NCH (SS / LCH)    // 32

// ---------------- scratch (__device__ globals; no allocs) ----------------
__device__ float g_h  [(size_t)MM * DD];   // rmsnorm(x) -> later gated y (tf32-rounded)
__device__ float g_xz [(size_t)MM * N1];   // GEMM1 out [xb | z]
__device__ float g_hs [(size_t)MM * DD];   // scan output
__device__ float g_wt1[(size_t)N1 * DD];   // in_w^T  [2048,1024] tf32-rounded
__device__ float g_wt2[(size_t)DD * DD];   // out_w^T [1024,1024] tf32-rounded
__device__ float g_last[(size_t)BB * NCH * DD];
__device__ float g_sin [(size_t)BB * NCH * DD];

// ---------------- helpers ----------------
__device__ __forceinline__ float tf32r(float x) {
    uint32_t u; asm("cvt.rn.tf32.f32 %0, %1;" : "=r"(u) : "f"(x));
    return __uint_as_float(u);
}
__device__ __forceinline__ float silu_f(float v) { return v / (1.f + __expf(-v)); }

__device__ __forceinline__ uint32_t smem_u32(const void* p) {
    uint32_t a;
    asm("{ .reg .u64 t; cvta.to.shared.u64 t, %1; cvt.u32.u64 %0, t; }" : "=r"(a) : "l"(p));
    return a;
}
__device__ __forceinline__ void cp16(uint32_t s, const void* g) {
    asm volatile("cp.async.cg.shared.global [%0], [%1], 16;" :: "r"(s), "l"(g) : "memory");
}
__device__ __forceinline__ void cp_commit() {
    asm volatile("cp.async.commit_group;" ::: "memory");
}
__device__ __forceinline__ void cp_wait1() {
    asm volatile("cp.async.wait_group 1;" ::: "memory");
}
__device__ __forceinline__ void cp_wait0() {
    asm volatile("cp.async.wait_group 0;" ::: "memory");
}

__device__ __forceinline__ void mma_tf32(float* c, const uint32_t* a, uint32_t b0, uint32_t b1) {
    asm volatile(
        "mma.sync.aligned.m16n8k8.row.col.f32.tf32.tf32.f32 "
        "{%0,%1,%2,%3}, {%4,%5,%6,%7}, {%8,%9}, {%0,%1,%2,%3};"
        : "+f"(c[0]), "+f"(c[1]), "+f"(c[2]), "+f"(c[3])
        : "r"(a[0]), "r"(a[1]), "r"(a[2]), "r"(a[3]), "r"(b0), "r"(b1));
}

// ---------------- block reduction (256 threads) ----------------
__device__ __forceinline__ float block_reduce_sum(float v) {
    __shared__ float red[8];
    int lane = threadIdx.x & 31, wid = threadIdx.x >> 5;
    #pragma unroll
    for (int o = 16; o > 0; o >>= 1) v += __shfl_xor_sync(0xffffffffu, v, o);
    if (lane == 0) red[wid] = v;
    __syncthreads();
    if (wid == 0) {
        v = (lane < 8) ? red[lane] : 0.f;
        #pragma unroll
        for (int o = 4; o > 0; o >>= 1) v += __shfl_xor_sync(0xffffffffu, v, o);
        if (lane == 0) red[0] = v;
    }
    __syncthreads();
    return red[0];
}

// ---------------- weight transpose + tf32 round: out[N,K] = round(in[K,N]^T) ----------------
__global__ __launch_bounds__(256) void transpose_kernel(
    const float* __restrict__ in, float* __restrict__ out, int Nn)
{
    __shared__ float tile[32][33];
    int n0 = blockIdx.x * 32, k0 = blockIdx.y * 32;
    int tx = threadIdx.x & 31, ty = threadIdx.x >> 5;
    #pragma unroll
    for (int i = 0; i < 32; i += 8)
        tile[ty + i][tx] = in[(size_t)(k0 + ty + i) * Nn + n0 + tx];
    __syncthreads();
    #pragma unroll
    for (int i = 0; i < 32; i += 8)
        out[(size_t)(n0 + ty + i) * DD + k0 + tx] = tf32r(tile[tx][ty + i]);
}

// ---------------- rmsnorm (tf32-rounded output) ----------------
__global__ __launch_bounds__(256) void rmsnorm_kernel(
    const float* __restrict__ x, const float* __restrict__ w, float* __restrict__ out)
{
    size_t row = blockIdx.x;
    float4 v = ((const float4*)(x + row * DD))[threadIdx.x];
    float ss = v.x * v.x + v.y * v.y + v.z * v.z + v.w * v.w;
    ss = block_reduce_sum(ss);
    float s = rsqrtf(ss * (1.f / DD) + EPSV);
    float4 wv = ((const float4*)w)[threadIdx.x];
    float4 o;
    o.x = tf32r(v.x * s * wv.x); o.y = tf32r(v.y * s * wv.y);
    o.z = tf32r(v.z * s * wv.z); o.w = tf32r(v.w * s * wv.w);
    ((float4*)(out + row * DD))[threadIdx.x] = o;
}

// ---------------- tf32 mma.sync GEMM ----------------
// C[M,N] = A[M,1024] @ Bt[N,1024]^T ; optional C += rs*resid
// Block 128x128, BK=32, 3-stage cp.async, 8 warps (2x4), warp tile 64x32.
// 2 CTAs/SM (4 warps/SMSP) -> cross-CTA latency hiding for barriers/primes.
#define BKK 32
#define ASTR 36                       // padded float stride (32 + 4)
#define BM 128
#define BN 128
#define A_FLOATS (BM * ASTR)          // 4608
#define B_FLOATS (BN * ASTR)          // 4608
#define STG_FLOATS (A_FLOATS + B_FLOATS)  // 9216
#define GSTG 3
#define GEMM_SMEM (GSTG * STG_FLOATS * 4) // 110592 B

__global__ __launch_bounds__(256, 2) void gemm_tc_kernel(
    int Nn, const float* __restrict__ A, const float* __restrict__ Bt,
    float* __restrict__ C,
    const float* __restrict__ resid, const float* __restrict__ rs_ptr)
{
    extern __shared__ float sm[];
    const int tid = threadIdx.x, lane = tid & 31, wid = tid >> 5;
    const int mtile = blockIdx.y * BM, ntile = blockIdx.x * BN;
    const int wm = (wid & 1) * 64, wn = (wid >> 1) * 32;

    // loader mapping: 8 threads x 16B per 32-float row; 32 rows per pass
    const int lr = tid >> 3;            // 0..31
    const int lc = (tid & 7) * 4;       // 0..28

    const float* Ag = A  + (size_t)(mtile + lr) * DD + lc;
    const float* Bg = Bt + (size_t)(ntile + lr) * DD + lc;

    uint32_t smb = smem_u32(sm);

    auto stage_load = [&](int s, int kc) {
        uint32_t as = smb + (uint32_t)(s * STG_FLOATS) * 4;
        uint32_t bs = as + A_FLOATS * 4;
        #pragma unroll
        for (int i = 0; i < 4; i++)     // A: 128 rows
            cp16(as + (uint32_t)((lr + i * 32) * ASTR + lc) * 4,
                 Ag + (size_t)i * 32 * DD + kc * BKK);
        #pragma unroll
        for (int i = 0; i < 4; i++)     // B: 128 rows
            cp16(bs + (uint32_t)((lr + i * 32) * ASTR + lc) * 4,
                 Bg + (size_t)i * 32 * DD + kc * BKK);
        cp_commit();
    };

    float acc[4][4][4];
    #pragma unroll
    for (int mi = 0; mi < 4; mi++)
        #pragma unroll
        for (int ni = 0; ni < 4; ni++)
            #pragma unroll
            for (int j = 0; j < 4; j++) acc[mi][ni][j] = 0.f;

    const int NKC = DD / BKK;           // 32
    stage_load(0, 0);
    stage_load(1, 1);

    const int fr = lane >> 2, fc = lane & 3;

    for (int kc = 0; kc < NKC; kc++) {
        cp_wait1();                      // chunk kc resident
        __syncthreads();
        if (kc + 2 < NKC) stage_load((kc + 2) % GSTG, kc + 2);
        else cp_commit();                // keep group accounting exact

        const float* as = sm + (kc % GSTG) * STG_FLOATS + (wm + fr) * ASTR + fc;
        const float* bs = sm + (kc % GSTG) * STG_FLOATS + A_FLOATS + (wn + fr) * ASTR + fc;

        #pragma unroll
        for (int kk = 0; kk < 4; kk++) {
            const int k0 = kk * 8;
            uint32_t a[4][4];
            #pragma unroll
            for (int mi = 0; mi < 4; mi++) {
                const float* ap = as + mi * 16 * ASTR + k0;
                a[mi][0] = __float_as_uint(ap[0]);
                a[mi][1] = __float_as_uint(ap[8 * ASTR]);
                a[mi][2] = __float_as_uint(ap[4]);
                a[mi][3] = __float_as_uint(ap[8 * ASTR + 4]);
            }
            #pragma unroll
            for (int ni = 0; ni < 4; ni++) {
                const float* bp = bs + ni * 8 * ASTR + k0;
                uint32_t b0 = __float_as_uint(bp[0]);
                uint32_t b1 = __float_as_uint(bp[4]);
                #pragma unroll
                for (int mi = 0; mi < 4; mi++)
                    mma_tf32(acc[mi][ni], a[mi], b0, b1);
            }
        }
        __syncthreads();
    }
    cp_wait0();

    // epilogue
    float rs = 0.f;
    if (resid) rs = __ldg(rs_ptr);
    #pragma unroll
    for (int mi = 0; mi < 4; mi++) {
        #pragma unroll
        for (int half = 0; half < 2; half++) {
            int row = mtile + wm + mi * 16 + half * 8 + fr;
            #pragma unroll
            for (int ni = 0; ni < 4; ni++) {
                int col = ntile + wn + ni * 8 + fc * 2;
                size_t off = (size_t)row * Nn + col;
                float2 v = make_float2(acc[mi][ni][half * 2], acc[mi][ni][half * 2 + 1]);
                if (resid) {
                    float2 rv = *(const float2*)(resid + off);
                    v.x = fmaf(rs, rv.x, v.x);
                    v.y = fmaf(rs, rv.y, v.y);
                }
                *(float2*)(C + off) = v;
            }
        }
    }
}

// ---------------- scan phase 1: local conv+silu+scan per 128-chunk ----------------
__global__ __launch_bounds__(256) void conv_local_kernel(
    const float* __restrict__ xz, const float* __restrict__ conv_w,
    const float* __restrict__ conv_b, const float* __restrict__ decay,
    float* __restrict__ hs, float* __restrict__ last)
{
    int idx = blockIdx.x * blockDim.x + threadIdx.x;   // BB*NCH*DD
    int d = idx % DD;
    int ch = (idx / DD) % NCH;
    int b = idx / (DD * NCH);

    float w0 = conv_w[d * KW + 0], w1 = conv_w[d * KW + 1];
    float w2 = conv_w[d * KW + 2], w3 = conv_w[d * KW + 3];
    float bias = conv_b[d];
    float a = 1.f / (1.f + __expf(-decay[d]));

    int t0 = ch * LCH;
    const float* xb = xz + ((size_t)b * SS + t0) * N1 + d;
    float* out = hs + ((size_t)b * SS + t0) * DD + d;

    float x0 = 0.f, x1 = 0.f, x2 = 0.f;
    if (ch > 0) {
        x0 = xb[-3 * (ptrdiff_t)N1];
        x1 = xb[-2 * (ptrdiff_t)N1];
        x2 = xb[-1 * (ptrdiff_t)N1];
    }
    float h = 0.f;
    #pragma unroll 4
    for (int t = 0; t < LCH; t++) {
        float x3 = xb[(size_t)t * N1];
        float c = fmaf(w0, x0, fmaf(w1, x1, fmaf(w2, x2, fmaf(w3, x3, bias))));
        c = silu_f(c);
        h = fmaf(a, h, c);
        out[(size_t)t * DD] = h;
        x0 = x1; x1 = x2; x2 = x3;
    }
    last[((size_t)b * NCH + ch) * DD + d] = h;
}

// ---------------- scan phase 2: carry chain ----------------
__global__ __launch_bounds__(256) void carry_kernel(
    const float* __restrict__ decay, const float* __restrict__ last,
    float* __restrict__ sin_)
{
    int idx = blockIdx.x * blockDim.x + threadIdx.x;   // BB*DD
    int d = idx % DD, b = idx / DD;
    float a = 1.f / (1.f + __expf(-decay[d]));
    float aL = a;
    #pragma unroll
    for (int i = 0; i < 7; i++) aL *= aL;              // a^128
    float c = 0.f;
    for (int j = 0; j < NCH; j++) {
        size_t o = ((size_t)b * NCH + j) * DD + d;
        sin_[o] = c;
        c = fmaf(aL, c, last[o]);
    }
}

// ---------------- scan phase 3: apply carries ----------------
__global__ __launch_bounds__(256) void fix_kernel(
    const float* __restrict__ decay, const float* __restrict__ sin_,
    float* __restrict__ hs)
{
    int idx = blockIdx.x * blockDim.x + threadIdx.x;   // BB*NCH*DD
    int d = idx % DD;
    int ch = (idx / DD) % NCH;
    int b = idx / (DD * NCH);
    float s = sin_[((size_t)b * NCH + ch) * DD + d];
    if (s == 0.f) return;
    float a = 1.f / (1.f + __expf(-decay[d]));
    float f = a * s;
    float* p = hs + ((size_t)b * SS + ch * LCH) * DD + d;
    for (int t = 0; t < LCH; t++) {
        if (fabsf(f) < 1e-14f) break;
        p[(size_t)t * DD] += f;
        f *= a;
    }
}

// ---------------- gated rmsnorm (tf32-rounded output) ----------------
__global__ __launch_bounds__(256) void gate_kernel(
    const float* __restrict__ hs, const float* __restrict__ gate_w,
    const float* __restrict__ xz, float* __restrict__ y)
{
    size_t row = blockIdx.x;
    float4 v = ((const float4*)(hs + row * DD))[threadIdx.x];
    float ss = v.x * v.x + v.y * v.y + v.z * v.z + v.w * v.w;
    ss = block_reduce_sum(ss);
    float s = rsqrtf(ss * (1.f / DD) + EPSV);
    float4 gw = ((const float4*)gate_w)[threadIdx.x];
    float4 zv = ((const float4*)(xz + row * N1 + DD))[threadIdx.x];
    float4 o;
    o.x = tf32r(v.x * s * gw.x * silu_f(zv.x));
    o.y = tf32r(v.y * s * gw.y * silu_f(zv.y));
    o.z = tf32r(v.z * s * gw.z * silu_f(zv.z));
    o.w = tf32r(v.w * s * gw.w * silu_f(zv.w));
    ((float4*)(y + row * DD))[threadIdx.x] = o;
}

// ---------------- host ----------------
extern "C" void kernel_launch(void* const* d_in, const int* in_sizes, int n_in,
                              void* d_out, int out_size)
{
    const float* x         = (const float*)d_in[0];
    const float* norm_w    = (const float*)d_in[1];
    const float* in_w      = (const float*)d_in[2];
    const float* conv_w    = (const float*)d_in[3];
    const float* conv_b    = (const float*)d_in[4];
    const float* decay     = (const float*)d_in[5];
    const float* gate_w    = (const float*)d_in[6];
    const float* out_w     = (const float*)d_in[7];
    const float* res_scale = (const float*)d_in[8];
    float* out = (float*)d_out;

    float *p_h, *p_xz, *p_hs, *p_wt1, *p_wt2, *p_last, *p_sin;
    cudaGetSymbolAddress((void**)&p_h,    g_h);
    cudaGetSymbolAddress((void**)&p_xz,   g_xz);
    cudaGetSymbolAddress((void**)&p_hs,   g_hs);
    cudaGetSymbolAddress((void**)&p_wt1,  g_wt1);
    cudaGetSymbolAddress((void**)&p_wt2,  g_wt2);
    cudaGetSymbolAddress((void**)&p_last, g_last);
    cudaGetSymbolAddress((void**)&p_sin,  g_sin);

    static bool smem_set = false;
    if (!smem_set) {
        cudaFuncSetAttribute(gemm_tc_kernel,
                             cudaFuncAttributeMaxDynamicSharedMemorySize, GEMM_SMEM);
        smem_set = true;
    }

    // 0. transpose + tf32-round weights
    transpose_kernel<<<dim3(N1 / 32, DD / 32), 256>>>(in_w,  p_wt1, N1);
    transpose_kernel<<<dim3(DD / 32, DD / 32), 256>>>(out_w, p_wt2, DD);

    // 1. h = rmsnorm(x) (tf32-rounded)
    rmsnorm_kernel<<<MM, 256>>>(x, norm_w, p_h);

    // 2. xz = h @ in_w
    gemm_tc_kernel<<<dim3(N1 / BN, MM / BM), 256, GEMM_SMEM>>>(
        N1, p_h, p_wt1, p_xz, nullptr, nullptr);

    // 3. chunked conv + scan
    conv_local_kernel<<<(BB * NCH * DD) / 256, 256>>>(p_xz, conv_w, conv_b, decay, p_hs, p_last);
    carry_kernel<<<(BB * DD) / 256, 256>>>(decay, p_last, p_sin);
    fix_kernel<<<(BB * NCH * DD) / 256, 256>>>(decay, p_sin, p_hs);

    // 4. y = rmsnorm(hs)*silu(z) (tf32-rounded) -> g_h
    gate_kernel<<<MM, 256>>>(p_hs, gate_w, p_xz, p_h);

    // 5. out = res_scale*x + y @ out_w
    gemm_tc_kernel<<<dim3(DD / BN, MM / BM), 256, GEMM_SMEM>>>(
        DD, p_h, p_wt2, out, x, res_scale);
}

// round 8
// speedup vs baseline: 1.3026x; 1.1162x over previous
#include <cuda_runtime.h>
#include <math.h>
#include <stdint.h>

// ---------------- problem constants ----------------
#define BB 4
#define SS 4096
#define DD 1024
#define KW 4
#define MM (BB * SS)      // 16384
#define N1 (2 * DD)       // 2048
#define EPSV 1e-6f
#define LCH 128           // scan chunk length
#define NCH (SS / LCH)    // 32

// ---------------- scratch (__device__ globals; no allocs) ----------------
// g_h / g_wt1 / g_wt2 are stored in FRAGMENT-MAJOR (FM) layout (see below).
__device__ float g_h  [(size_t)MM * DD];
__device__ float g_xz [(size_t)MM * N1];   // row-major
__device__ float g_hs [(size_t)MM * DD];   // row-major
__device__ float g_wt1[(size_t)N1 * DD];   // in_w^T  FM
__device__ float g_wt2[(size_t)DD * DD];   // out_w^T FM
__device__ float g_last[(size_t)BB * NCH * DD];
__device__ float g_sin [(size_t)BB * NCH * DD];

// FM layout for A-type matrix X[R][K] (mma m16n8k8 .row operand):
//   rt=r>>4, kt=k>>3, fr=r&7, rh=(r>>3)&1, fc=k&3, ch=(k>>2)&1
//   off = ((rt*(K/8)+kt)*32 + fr*4+fc)*4 + (rh + 2*ch)
//   -> warp LDS.128 at (tile*32 + lane)*4 yields {a0,a1,a2,a3} in mma order.
// FM layout for B-type matrix Bt[N][K] (.col operand, stored as N x K):
//   nt=n>>3, kt=k>>3, fn=n&7, fc=k&3, ch=(k>>2)&1
//   off = ((nt*(K/8)+kt)*32 + fn*4+fc)*2 + ch
//   -> warp LDS.64 at (tile*32 + lane)*2 yields {b0,b1}.

// ---------------- helpers ----------------
__device__ __forceinline__ float tf32r(float x) {
    uint32_t u; asm("cvt.rn.tf32.f32 %0, %1;" : "=r"(u) : "f"(x));
    return __uint_as_float(u);
}
__device__ __forceinline__ float silu_f(float v) { return v / (1.f + __expf(-v)); }

__device__ __forceinline__ uint32_t smem_u32(const void* p) {
    uint32_t a;
    asm("{ .reg .u64 t; cvta.to.shared.u64 t, %1; cvt.u32.u64 %0, t; }" : "=r"(a) : "l"(p));
    return a;
}
__device__ __forceinline__ void cp16(uint32_t s, const void* g) {
    asm volatile("cp.async.cg.shared.global [%0], [%1], 16;" :: "r"(s), "l"(g) : "memory");
}
__device__ __forceinline__ void cp_commit() {
    asm volatile("cp.async.commit_group;" ::: "memory");
}
__device__ __forceinline__ void cp_wait1() {
    asm volatile("cp.async.wait_group 1;" ::: "memory");
}
__device__ __forceinline__ void cp_wait0() {
    asm volatile("cp.async.wait_group 0;" ::: "memory");
}

__device__ __forceinline__ void mma_tf32(float* c, const uint32_t* a, uint32_t b0, uint32_t b1) {
    asm volatile(
        "mma.sync.aligned.m16n8k8.row.col.f32.tf32.tf32.f32 "
        "{%0,%1,%2,%3}, {%4,%5,%6,%7}, {%8,%9}, {%0,%1,%2,%3};"
        : "+f"(c[0]), "+f"(c[1]), "+f"(c[2]), "+f"(c[3])
        : "r"(a[0]), "r"(a[1]), "r"(a[2]), "r"(a[3]), "r"(b0), "r"(b1));
}

// ---------------- block reduction (256 threads) ----------------
__device__ __forceinline__ float block_reduce_sum(float v) {
    __shared__ float red[8];
    int lane = threadIdx.x & 31, wid = threadIdx.x >> 5;
    #pragma unroll
    for (int o = 16; o > 0; o >>= 1) v += __shfl_xor_sync(0xffffffffu, v, o);
    if (lane == 0) red[wid] = v;
    __syncthreads();
    if (wid == 0) {
        v = (lane < 8) ? red[lane] : 0.f;
        #pragma unroll
        for (int o = 4; o > 0; o >>= 1) v += __shfl_xor_sync(0xffffffffu, v, o);
        if (lane == 0) red[0] = v;
    }
    __syncthreads();
    return red[0];
}

// ---------------- weight transpose + tf32 round -> FM B layout ----------------
__global__ __launch_bounds__(256) void transpose_kernel(
    const float* __restrict__ in, float* __restrict__ out, int Nn)
{
    __shared__ float tile[32][33];
    int n0 = blockIdx.x * 32, k0 = blockIdx.y * 32;
    int tx = threadIdx.x & 31, ty = threadIdx.x >> 5;
    #pragma unroll
    for (int i = 0; i < 32; i += 8)
        tile[ty + i][tx] = in[(size_t)(k0 + ty + i) * Nn + n0 + tx];
    __syncthreads();
    int k = k0 + tx;
    int kt = k >> 3, fc = k & 3, ch = (k >> 2) & 1;
    #pragma unroll
    for (int i = 0; i < 32; i += 8) {
        int n = n0 + ty + i;
        int nt = n >> 3, fn = n & 7;
        size_t off = ((size_t)(nt * (DD / 8) + kt) * 32 + fn * 4 + fc) * 2 + ch;
        out[off] = tf32r(tile[tx][ty + i]);
    }
}

// ---------------- rmsnorm (tf32-rounded, FM A output) ----------------
__global__ __launch_bounds__(256) void rmsnorm_kernel(
    const float* __restrict__ x, const float* __restrict__ w, float* __restrict__ out)
{
    size_t row = blockIdx.x;
    float4 v = ((const float4*)(x + row * DD))[threadIdx.x];
    float ss = v.x * v.x + v.y * v.y + v.z * v.z + v.w * v.w;
    ss = block_reduce_sum(ss);
    float s = rsqrtf(ss * (1.f / DD) + EPSV);
    float4 wv = ((const float4*)w)[threadIdx.x];
    int c0 = threadIdx.x * 4;
    int rt = (int)(row >> 4), fr = (int)(row & 7), rh = (int)((row >> 3) & 1);
    int kt = c0 >> 3, ch = (c0 >> 2) & 1;
    size_t base = ((size_t)(rt * (DD / 8) + kt) * 32 + fr * 4) * 4 + (rh + 2 * ch);
    out[base +  0] = tf32r(v.x * s * wv.x);
    out[base +  4] = tf32r(v.y * s * wv.y);
    out[base +  8] = tf32r(v.z * s * wv.z);
    out[base + 12] = tf32r(v.w * s * wv.w);
}

// ---------------- tf32 mma.sync GEMM (FM inputs) ----------------
// C[M,N] = A[M,1024] @ Bt[N,1024]^T ; optional C += rs*resid
// Block 128x128, BK=32, 3-stage cp.async, 8 warps (2x4), warp tile 64x32, 2 CTA/SM.
// A/B in FM layout: fragments load as LDS.128 / LDS.64.
#define BKK 32
#define BM 128
#define BN 128
#define A_FLOATS 4096                  // 128 rows x 32 k
#define B_FLOATS 4096
#define STG_FLOATS (A_FLOATS + B_FLOATS)   // 8192
#define GSTG 3
#define GEMM_SMEM (GSTG * STG_FLOATS * 4)  // 98304 B

__global__ __launch_bounds__(256, 2) void gemm_tc_kernel(
    int Nn, const float* __restrict__ A, const float* __restrict__ Bt,
    float* __restrict__ C,
    const float* __restrict__ resid, const float* __restrict__ rs_ptr)
{
    extern __shared__ float sm[];
    const int tid = threadIdx.x, lane = tid & 31, wid = tid >> 5;
    const int mtile = blockIdx.y * BM, ntile = blockIdx.x * BN;
    const int wmt = (wid & 1) * 4;      // A row-tile base (16-row tiles) within block
    const int wnt = (wid >> 1) * 4;     // B n-tile base (8-row tiles) within block

    uint32_t smb = smem_u32(sm);

    // loader: A per rt-tile chunk = 2048 B contiguous; B per nt-tile chunk = 1024 B.
    const int rtA = tid >> 5;                         // 0..7
    const float* AgBase = A + ((size_t)(blockIdx.y * 8 + rtA) * (DD / 8)) * 128
                            + (size_t)(tid & 31) * 4;
    const int ntB = tid >> 4;                         // 0..15
    const float* BgBase = Bt + ((size_t)(blockIdx.x * 16 + ntB) * (DD / 8)) * 64
                             + (size_t)(tid & 15) * 4;

    auto stage_load = [&](int s, int kc) {
        uint32_t as = smb + (uint32_t)(s * STG_FLOATS) * 4;
        uint32_t bs = as + A_FLOATS * 4;
        const float* ag = AgBase + kc * 512;   // 4 kt * 128 floats
        const float* bg = BgBase + kc * 256;   // 4 kt * 64 floats
        #pragma unroll
        for (int i = 0; i < 4; i++)
            cp16(as + (uint32_t)(rtA * 2048 + i * 512 + (tid & 31) * 16),
                 ag + i * 128);
        #pragma unroll
        for (int i = 0; i < 4; i++)
            cp16(bs + (uint32_t)(ntB * 1024 + i * 256 + (tid & 15) * 16),
                 bg + i * 64);
        cp_commit();
    };

    float acc[4][4][4];
    #pragma unroll
    for (int mi = 0; mi < 4; mi++)
        #pragma unroll
        for (int ni = 0; ni < 4; ni++)
            #pragma unroll
            for (int j = 0; j < 4; j++) acc[mi][ni][j] = 0.f;

    const int NKC = DD / BKK;           // 32
    stage_load(0, 0);
    stage_load(1, 1);

    for (int kc = 0; kc < NKC; kc++) {
        cp_wait1();
        __syncthreads();
        if (kc + 2 < NKC) stage_load((kc + 2) % GSTG, kc + 2);
        else cp_commit();

        const float* sA = sm + (kc % GSTG) * STG_FLOATS;
        const float* sB = sA + A_FLOATS;

        #pragma unroll
        for (int kk = 0; kk < 4; kk++) {
            uint32_t a[4][4];
            #pragma unroll
            for (int mi = 0; mi < 4; mi++) {
                float4 av = *(const float4*)(sA + (((wmt + mi) * 4 + kk) * 32 + lane) * 4);
                a[mi][0] = __float_as_uint(av.x);
                a[mi][1] = __float_as_uint(av.y);
                a[mi][2] = __float_as_uint(av.z);
                a[mi][3] = __float_as_uint(av.w);
            }
            #pragma unroll
            for (int ni = 0; ni < 4; ni++) {
                float2 bv = *(const float2*)(sB + (((wnt + ni) * 4 + kk) * 32 + lane) * 2);
                uint32_t b0 = __float_as_uint(bv.x);
                uint32_t b1 = __float_as_uint(bv.y);
                #pragma unroll
                for (int mi = 0; mi < 4; mi++)
                    mma_tf32(acc[mi][ni], a[mi], b0, b1);
            }
        }
        __syncthreads();
    }
    cp_wait0();

    // epilogue (row-major C)
    const int fr = lane >> 2, fc = lane & 3;
    const int wm = (wid & 1) * 64, wn = (wid >> 1) * 32;
    float rs = 0.f;
    if (resid) rs = __ldg(rs_ptr);
    #pragma unroll
    for (int mi = 0; mi < 4; mi++) {
        #pragma unroll
        for (int half = 0; half < 2; half++) {
            int row = mtile + wm + mi * 16 + half * 8 + fr;
            #pragma unroll
            for (int ni = 0; ni < 4; ni++) {
                int col = ntile + wn + ni * 8 + fc * 2;
                size_t off = (size_t)row * Nn + col;
                float2 v = make_float2(acc[mi][ni][half * 2], acc[mi][ni][half * 2 + 1]);
                if (resid) {
                    float2 rv = *(const float2*)(resid + off);
                    v.x = fmaf(rs, rv.x, v.x);
                    v.y = fmaf(rs, rv.y, v.y);
                }
                *(float2*)(C + off) = v;
            }
        }
    }
}

// ---------------- scan phase 1: local conv+silu+scan per 128-chunk ----------------
__global__ __launch_bounds__(256) void conv_local_kernel(
    const float* __restrict__ xz, const float* __restrict__ conv_w,
    const float* __restrict__ conv_b, const float* __restrict__ decay,
    float* __restrict__ hs, float* __restrict__ last)
{
    int idx = blockIdx.x * blockDim.x + threadIdx.x;   // BB*NCH*DD
    int d = idx % DD;
    int ch = (idx / DD) % NCH;
    int b = idx / (DD * NCH);

    float w0 = conv_w[d * KW + 0], w1 = conv_w[d * KW + 1];
    float w2 = conv_w[d * KW + 2], w3 = conv_w[d * KW + 3];
    float bias = conv_b[d];
    float a = 1.f / (1.f + __expf(-decay[d]));

    int t0 = ch * LCH;
    const float* xb = xz + ((size_t)b * SS + t0) * N1 + d;
    float* out = hs + ((size_t)b * SS + t0) * DD + d;

    float x0 = 0.f, x1 = 0.f, x2 = 0.f;
    if (ch > 0) {
        x0 = xb[-3 * (ptrdiff_t)N1];
        x1 = xb[-2 * (ptrdiff_t)N1];
        x2 = xb[-1 * (ptrdiff_t)N1];
    }
    float h = 0.f;
    #pragma unroll 4
    for (int t = 0; t < LCH; t++) {
        float x3 = xb[(size_t)t * N1];
        float c = fmaf(w0, x0, fmaf(w1, x1, fmaf(w2, x2, fmaf(w3, x3, bias))));
        c = silu_f(c);
        h = fmaf(a, h, c);
        out[(size_t)t * DD] = h;
        x0 = x1; x1 = x2; x2 = x3;
    }
    last[((size_t)b * NCH + ch) * DD + d] = h;
}

// ---------------- scan phase 2: carry chain ----------------
__global__ __launch_bounds__(256) void carry_kernel(
    const float* __restrict__ decay, const float* __restrict__ last,
    float* __restrict__ sin_)
{
    int idx = blockIdx.x * blockDim.x + threadIdx.x;   // BB*DD
    int d = idx % DD, b = idx / DD;
    float a = 1.f / (1.f + __expf(-decay[d]));
    float aL = a;
    #pragma unroll
    for (int i = 0; i < 7; i++) aL *= aL;              // a^128
    float c = 0.f;
    for (int j = 0; j < NCH; j++) {
        size_t o = ((size_t)b * NCH + j) * DD + d;
        sin_[o] = c;
        c = fmaf(aL, c, last[o]);
    }
}

// ---------------- scan phase 3: apply carries ----------------
__global__ __launch_bounds__(256) void fix_kernel(
    const float* __restrict__ decay, const float* __restrict__ sin_,
    float* __restrict__ hs)
{
    int idx = blockIdx.x * blockDim.x + threadIdx.x;   // BB*NCH*DD
    int d = idx % DD;
    int ch = (idx / DD) % NCH;
    int b = idx / (DD * NCH);
    float s = sin_[((size_t)b * NCH + ch) * DD + d];
    if (s == 0.f) return;
    float a = 1.f / (1.f + __expf(-decay[d]));
    float f = a * s;
    float* p = hs + ((size_t)b * SS + ch * LCH) * DD + d;
    for (int t = 0; t < LCH; t++) {
        if (fabsf(f) < 1e-14f) break;
        p[(size_t)t * DD] += f;
        f *= a;
    }
}

// ---------------- gated rmsnorm (tf32-rounded, FM A output) ----------------
__global__ __launch_bounds__(256) void gate_kernel(
    const float* __restrict__ hs, const float* __restrict__ gate_w,
    const float* __restrict__ xz, float* __restrict__ y)
{
    size_t row = blockIdx.x;
    float4 v = ((const float4*)(hs + row * DD))[threadIdx.x];
    float ss = v.x * v.x + v.y * v.y + v.z * v.z + v.w * v.w;
    ss = block_reduce_sum(ss);
    float s = rsqrtf(ss * (1.f / DD) + EPSV);
    float4 gw = ((const float4*)gate_w)[threadIdx.x];
    float4 zv = ((const float4*)(xz + row * N1 + DD))[threadIdx.x];
    int c0 = threadIdx.x * 4;
    int rt = (int)(row >> 4), fr = (int)(row & 7), rh = (int)((row >> 3) & 1);
    int kt = c0 >> 3, ch = (c0 >> 2) & 1;
    size_t base = ((size_t)(rt * (DD / 8) + kt) * 32 + fr * 4) * 4 + (rh + 2 * ch);
    y[base +  0] = tf32r(v.x * s * gw.x * silu_f(zv.x));
    y[base +  4] = tf32r(v.y * s * gw.y * silu_f(zv.y));
    y[base +  8] = tf32r(v.z * s * gw.z * silu_f(zv.z));
    y[base + 12] = tf32r(v.w * s * gw.w * silu_f(zv.w));
}

// ---------------- host ----------------
extern "C" void kernel_launch(void* const* d_in, const int* in_sizes, int n_in,
                              void* d_out, int out_size)
{
    const float* x         = (const float*)d_in[0];
    const float* norm_w    = (const float*)d_in[1];
    const float* in_w      = (const float*)d_in[2];
    const float* conv_w    = (const float*)d_in[3];
    const float* conv_b    = (const float*)d_in[4];
    const float* decay     = (const float*)d_in[5];
    const float* gate_w    = (const float*)d_in[6];
    const float* out_w     = (const float*)d_in[7];
    const float* res_scale = (const float*)d_in[8];
    float* out = (float*)d_out;

    float *p_h, *p_xz, *p_hs, *p_wt1, *p_wt2, *p_last, *p_sin;
    cudaGetSymbolAddress((void**)&p_h,    g_h);
    cudaGetSymbolAddress((void**)&p_xz,   g_xz);
    cudaGetSymbolAddress((void**)&p_hs,   g_hs);
    cudaGetSymbolAddress((void**)&p_wt1,  g_wt1);
    cudaGetSymbolAddress((void**)&p_wt2,  g_wt2);
    cudaGetSymbolAddress((void**)&p_last, g_last);
    cudaGetSymbolAddress((void**)&p_sin,  g_sin);

    static bool smem_set = false;
    if (!smem_set) {
        cudaFuncSetAttribute(gemm_tc_kernel,
                             cudaFuncAttributeMaxDynamicSharedMemorySize, GEMM_SMEM);
        smem_set = true;
    }

    // 0. transpose + tf32-round weights -> FM layout
    transpose_kernel<<<dim3(N1 / 32, DD / 32), 256>>>(in_w,  p_wt1, N1);
    transpose_kernel<<<dim3(DD / 32, DD / 32), 256>>>(out_w, p_wt2, DD);

    // 1. h = rmsnorm(x) (tf32-rounded, FM layout)
    rmsnorm_kernel<<<MM, 256>>>(x, norm_w, p_h);

    // 2. xz = h @ in_w
    gemm_tc_kernel<<<dim3(N1 / BN, MM / BM), 256, GEMM_SMEM>>>(
        N1, p_h, p_wt1, p_xz, nullptr, nullptr);

    // 3. chunked conv + scan
    conv_local_kernel<<<(BB * NCH * DD) / 256, 256>>>(p_xz, conv_w, conv_b, decay, p_hs, p_last);
    carry_kernel<<<(BB * DD) / 256, 256>>>(decay, p_last, p_sin);
    fix_kernel<<<(BB * NCH * DD) / 256, 256>>>(decay, p_sin, p_hs);

    // 4. y = rmsnorm(hs)*silu(z) (tf32-rounded, FM layout) -> g_h
    gate_kernel<<<MM, 256>>>(p_hs, gate_w, p_xz, p_h);

    // 5. out = res_scale*x + y @ out_w
    gemm_tc_kernel<<<dim3(DD / BN, MM / BM), 256, GEMM_SMEM>>>(
        DD, p_h, p_wt2, out, x, res_scale);
}

// round 9
// speedup vs baseline: 1.4253x; 1.0942x over previous
#include <cuda_runtime.h>
#include <math.h>
#include <stdint.h>

// ---------------- problem constants ----------------
#define BB 4
#define SS 4096
#define DD 1024
#define KW 4
#define MM (BB * SS)      // 16384
#define N1 (2 * DD)       // 2048
#define EPSV 1e-6f
#define LCH 128           // scan chunk length
#define NCH (SS / LCH)    // 32

// ---------------- scratch (__device__ globals; no allocs) ----------------
// g_h / g_wt1 / g_wt2 are stored in FRAGMENT-MAJOR (FM) layout.
__device__ float g_h  [(size_t)MM * DD];
__device__ float g_xz [(size_t)MM * N1];   // row-major
__device__ float g_hs [(size_t)MM * DD];   // row-major (local scan, pre-carry)
__device__ float g_wt1[(size_t)N1 * DD];   // in_w^T  FM
__device__ float g_wt2[(size_t)DD * DD];   // out_w^T FM
__device__ float g_last[(size_t)BB * NCH * DD];
__device__ float g_sin [(size_t)BB * NCH * DD];

// FM layout for A-type matrix X[R][K] (mma m16n8k8 .row operand):
//   rt=r>>4, kt=k>>3, fr=r&7, rh=(r>>3)&1, fc=k&3, ch=(k>>2)&1
//   off = ((rt*(K/8)+kt)*32 + fr*4+fc)*4 + (rh + 2*ch)
// FM layout for B-type matrix Bt[N][K] (.col operand):
//   off = ((nt*(K/8)+kt)*32 + fn*4+fc)*2 + ch

// ---------------- helpers ----------------
__device__ __forceinline__ float tf32r(float x) {
    uint32_t u; asm("cvt.rn.tf32.f32 %0, %1;" : "=r"(u) : "f"(x));
    return __uint_as_float(u);
}
__device__ __forceinline__ float silu_f(float v) { return v / (1.f + __expf(-v)); }

__device__ __forceinline__ uint32_t smem_u32(const void* p) {
    uint32_t a;
    asm("{ .reg .u64 t; cvta.to.shared.u64 t, %1; cvt.u32.u64 %0, t; }" : "=r"(a) : "l"(p));
    return a;
}
__device__ __forceinline__ void cp16(uint32_t s, const void* g) {
    asm volatile("cp.async.cg.shared.global [%0], [%1], 16;" :: "r"(s), "l"(g) : "memory");
}
__device__ __forceinline__ void cp_commit() {
    asm volatile("cp.async.commit_group;" ::: "memory");
}
__device__ __forceinline__ void cp_wait1() {
    asm volatile("cp.async.wait_group 1;" ::: "memory");
}
__device__ __forceinline__ void cp_wait0() {
    asm volatile("cp.async.wait_group 0;" ::: "memory");
}

__device__ __forceinline__ void mma_tf32(float* c, const uint32_t* a, uint32_t b0, uint32_t b1) {
    asm volatile(
        "mma.sync.aligned.m16n8k8.row.col.f32.tf32.tf32.f32 "
        "{%0,%1,%2,%3}, {%4,%5,%6,%7}, {%8,%9}, {%0,%1,%2,%3};"
        : "+f"(c[0]), "+f"(c[1]), "+f"(c[2]), "+f"(c[3])
        : "r"(a[0]), "r"(a[1]), "r"(a[2]), "r"(a[3]), "r"(b0), "r"(b1));
}

// ---------------- block reduction (256 threads) ----------------
__device__ __forceinline__ float block_reduce_sum(float v) {
    __shared__ float red[8];
    int lane = threadIdx.x & 31, wid = threadIdx.x >> 5;
    #pragma unroll
    for (int o = 16; o > 0; o >>= 1) v += __shfl_xor_sync(0xffffffffu, v, o);
    if (lane == 0) red[wid] = v;
    __syncthreads();
    if (wid == 0) {
        v = (lane < 8) ? red[lane] : 0.f;
        #pragma unroll
        for (int o = 4; o > 0; o >>= 1) v += __shfl_xor_sync(0xffffffffu, v, o);
        if (lane == 0) red[0] = v;
    }
    __syncthreads();
    return red[0];
}

// ---------------- weight transpose + tf32 round -> FM B layout ----------------
__global__ __launch_bounds__(256) void transpose_kernel(
    const float* __restrict__ in, float* __restrict__ out, int Nn)
{
    __shared__ float tile[32][33];
    int n0 = blockIdx.x * 32, k0 = blockIdx.y * 32;
    int tx = threadIdx.x & 31, ty = threadIdx.x >> 5;
    #pragma unroll
    for (int i = 0; i < 32; i += 8)
        tile[ty + i][tx] = in[(size_t)(k0 + ty + i) * Nn + n0 + tx];
    __syncthreads();
    int k = k0 + tx;
    int kt = k >> 3, fc = k & 3, ch = (k >> 2) & 1;
    #pragma unroll
    for (int i = 0; i < 32; i += 8) {
        int n = n0 + ty + i;
        int nt = n >> 3, fn = n & 7;
        size_t off = ((size_t)(nt * (DD / 8) + kt) * 32 + fn * 4 + fc) * 2 + ch;
        out[off] = tf32r(tile[tx][ty + i]);
    }
}

// ---------------- rmsnorm (tf32-rounded, FM A output) ----------------
__global__ __launch_bounds__(256) void rmsnorm_kernel(
    const float* __restrict__ x, const float* __restrict__ w, float* __restrict__ out)
{
    size_t row = blockIdx.x;
    float4 v = ((const float4*)(x + row * DD))[threadIdx.x];
    float ss = v.x * v.x + v.y * v.y + v.z * v.z + v.w * v.w;
    ss = block_reduce_sum(ss);
    float s = rsqrtf(ss * (1.f / DD) + EPSV);
    float4 wv = ((const float4*)w)[threadIdx.x];
    int c0 = threadIdx.x * 4;
    int rt = (int)(row >> 4), fr = (int)(row & 7), rh = (int)((row >> 3) & 1);
    int kt = c0 >> 3, ch = (c0 >> 2) & 1;
    size_t base = ((size_t)(rt * (DD / 8) + kt) * 32 + fr * 4) * 4 + (rh + 2 * ch);
    out[base +  0] = tf32r(v.x * s * wv.x);
    out[base +  4] = tf32r(v.y * s * wv.y);
    out[base +  8] = tf32r(v.z * s * wv.z);
    out[base + 12] = tf32r(v.w * s * wv.w);
}

// ---------------- tf32 mma.sync GEMM (FM inputs) ----------------
// Block 128x128, BK=32, 3-stage cp.async, 4 warps (2x2), warp tile 64x64, 2 CTA/SM.
#define BKK 32
#define BM 128
#define BN 128
#define A_FLOATS 4096
#define B_FLOATS 4096
#define STG_FLOATS (A_FLOATS + B_FLOATS)   // 8192
#define GSTG 3
#define GEMM_SMEM (GSTG * STG_FLOATS * 4)  // 98304 B

__global__ __launch_bounds__(128, 2) void gemm_tc_kernel(
    int Nn, const float* __restrict__ A, const float* __restrict__ Bt,
    float* __restrict__ C,
    const float* __restrict__ resid, const float* __restrict__ rs_ptr)
{
    extern __shared__ float sm[];
    const int tid = threadIdx.x, lane = tid & 31, wid = tid >> 5;
    const int mtile = blockIdx.y * BM, ntile = blockIdx.x * BN;
    const int wmt = (wid & 1) * 4;      // A row-tile base (16-row tiles)
    const int wnt = (wid >> 1) * 8;     // B n-tile base (8-row tiles)

    uint32_t smb = smem_u32(sm);

    // A loader: per rt (0..7), 2048B contiguous; 128 threads x 16B.
    const float* AgBase = A + (size_t)blockIdx.y * 8 * (DD / 8) * 128 + (size_t)tid * 4;
    // B loader: per nt (0..15), 1024B contiguous; 8 threads x 16B x 8 passes.
    const int ntB = tid >> 3, lane8 = tid & 7;
    const float* BgBase = Bt + ((size_t)(blockIdx.x * 16 + ntB) * (DD / 8)) * 64
                             + (size_t)lane8 * 4;

    auto stage_load = [&](int s, int kc) {
        uint32_t as = smb + (uint32_t)(s * STG_FLOATS) * 4;
        uint32_t bs = as + A_FLOATS * 4;
        const float* ag = AgBase + kc * 512;
        #pragma unroll
        for (int i = 0; i < 8; i++)      // A: 8 rt blocks, 2048B each
            cp16(as + (uint32_t)(i * 2048 + tid * 16),
                 ag + (size_t)i * (DD / 8) * 128);
        const float* bg = BgBase + kc * 256;
        #pragma unroll
        for (int i = 0; i < 8; i++)      // B: nt block, 8 x 128B passes
            cp16(bs + (uint32_t)(ntB * 1024 + i * 128 + lane8 * 16),
                 bg + i * 32);
        cp_commit();
    };

    float acc[4][8][4];
    #pragma unroll
    for (int mi = 0; mi < 4; mi++)
        #pragma unroll
        for (int ni = 0; ni < 8; ni++)
            #pragma unroll
            for (int j = 0; j < 4; j++) acc[mi][ni][j] = 0.f;

    const int NKC = DD / BKK;           // 32
    stage_load(0, 0);
    stage_load(1, 1);

    for (int kc = 0; kc < NKC; kc++) {
        cp_wait1();
        __syncthreads();
        if (kc + 2 < NKC) stage_load((kc + 2) % GSTG, kc + 2);
        else cp_commit();

        const float* sA = sm + (kc % GSTG) * STG_FLOATS;
        const float* sB = sA + A_FLOATS;

        #pragma unroll
        for (int kk = 0; kk < 4; kk++) {
            uint32_t a[4][4];
            #pragma unroll
            for (int mi = 0; mi < 4; mi++) {
                float4 av = *(const float4*)(sA + (((wmt + mi) * 4 + kk) * 32 + lane) * 4);
                a[mi][0] = __float_as_uint(av.x);
                a[mi][1] = __float_as_uint(av.y);
                a[mi][2] = __float_as_uint(av.z);
                a[mi][3] = __float_as_uint(av.w);
            }
            #pragma unroll
            for (int ni = 0; ni < 8; ni++) {
                float2 bv = *(const float2*)(sB + (((wnt + ni) * 4 + kk) * 32 + lane) * 2);
                uint32_t b0 = __float_as_uint(bv.x);
                uint32_t b1 = __float_as_uint(bv.y);
                #pragma unroll
                for (int mi = 0; mi < 4; mi++)
                    mma_tf32(acc[mi][ni], a[mi], b0, b1);
            }
        }
        __syncthreads();
    }
    cp_wait0();

    // epilogue (row-major C)
    const int fr = lane >> 2, fc = lane & 3;
    const int wm = (wid & 1) * 64, wn = (wid >> 1) * 64;
    float rs = 0.f;
    if (resid) rs = __ldg(rs_ptr);
    #pragma unroll
    for (int mi = 0; mi < 4; mi++) {
        #pragma unroll
        for (int half = 0; half < 2; half++) {
            int row = mtile + wm + mi * 16 + half * 8 + fr;
            #pragma unroll
            for (int ni = 0; ni < 8; ni++) {
                int col = ntile + wn + ni * 8 + fc * 2;
                size_t off = (size_t)row * Nn + col;
                float2 v = make_float2(acc[mi][ni][half * 2], acc[mi][ni][half * 2 + 1]);
                if (resid) {
                    float2 rv = *(const float2*)(resid + off);
                    v.x = fmaf(rs, rv.x, v.x);
                    v.y = fmaf(rs, rv.y, v.y);
                }
                *(float2*)(C + off) = v;
            }
        }
    }
}

// ---------------- scan phase 1: local conv+silu+scan per 128-chunk ----------------
__global__ __launch_bounds__(256) void conv_local_kernel(
    const float* __restrict__ xz, const float* __restrict__ conv_w,
    const float* __restrict__ conv_b, const float* __restrict__ decay,
    float* __restrict__ hs, float* __restrict__ last)
{
    int idx = blockIdx.x * blockDim.x + threadIdx.x;   // BB*NCH*DD
    int d = idx % DD;
    int ch = (idx / DD) % NCH;
    int b = idx / (DD * NCH);

    float w0 = conv_w[d * KW + 0], w1 = conv_w[d * KW + 1];
    float w2 = conv_w[d * KW + 2], w3 = conv_w[d * KW + 3];
    float bias = conv_b[d];
    float a = 1.f / (1.f + __expf(-decay[d]));

    int t0 = ch * LCH;
    const float* xb = xz + ((size_t)b * SS + t0) * N1 + d;
    float* out = hs + ((size_t)b * SS + t0) * DD + d;

    float x0 = 0.f, x1 = 0.f, x2 = 0.f;
    if (ch > 0) {
        x0 = xb[-3 * (ptrdiff_t)N1];
        x1 = xb[-2 * (ptrdiff_t)N1];
        x2 = xb[-1 * (ptrdiff_t)N1];
    }
    float h = 0.f;
    #pragma unroll 4
    for (int t = 0; t < LCH; t++) {
        float x3 = xb[(size_t)t * N1];
        float c = fmaf(w0, x0, fmaf(w1, x1, fmaf(w2, x2, fmaf(w3, x3, bias))));
        c = silu_f(c);
        h = fmaf(a, h, c);
        out[(size_t)t * DD] = h;
        x0 = x1; x1 = x2; x2 = x3;
    }
    last[((size_t)b * NCH + ch) * DD + d] = h;
}

// ---------------- scan phase 2: carry chain ----------------
__global__ __launch_bounds__(256) void carry_kernel(
    const float* __restrict__ decay, const float* __restrict__ last,
    float* __restrict__ sin_)
{
    int idx = blockIdx.x * blockDim.x + threadIdx.x;   // BB*DD
    int d = idx % DD, b = idx / DD;
    float a = 1.f / (1.f + __expf(-decay[d]));
    float aL = a;
    #pragma unroll
    for (int i = 0; i < 7; i++) aL *= aL;              // a^128
    float c = 0.f;
    for (int j = 0; j < NCH; j++) {
        size_t o = ((size_t)b * NCH + j) * DD + d;
        sin_[o] = c;
        c = fmaf(aL, c, last[o]);
    }
}

// ---------------- gated rmsnorm with fused carry (tf32-rounded, FM A output) ----
// v = hs_local + sin[b,ch,d] * a^(t+1);  y = rmsnorm(v)*gate*silu(z)
__global__ __launch_bounds__(256) void gate_kernel(
    const float* __restrict__ hs, const float* __restrict__ gate_w,
    const float* __restrict__ xz, const float* __restrict__ decay,
    const float* __restrict__ sin_, float* __restrict__ y)
{
    size_t row = blockIdx.x;
    int b = (int)(row / SS);
    int sidx = (int)(row % SS);
    int chk = sidx / LCH, tt = sidx % LCH;

    float4 v = ((const float4*)(hs + row * DD))[threadIdx.x];
    int d0 = threadIdx.x * 4;
    float4 sv = ((const float4*)(sin_ + ((size_t)b * NCH + chk) * DD))[threadIdx.x];
    float4 dc = ((const float4*)(decay))[threadIdx.x];
    float tp = (float)(tt + 1);
    // carry = sin * a^(t+1),  a = sigmoid(decay)
    {
        float a0 = 1.f / (1.f + __expf(-dc.x));
        float a1 = 1.f / (1.f + __expf(-dc.y));
        float a2 = 1.f / (1.f + __expf(-dc.z));
        float a3 = 1.f / (1.f + __expf(-dc.w));
        v.x += sv.x * exp2f(tp * __log2f(a0));
        v.y += sv.y * exp2f(tp * __log2f(a1));
        v.z += sv.z * exp2f(tp * __log2f(a2));
        v.w += sv.w * exp2f(tp * __log2f(a3));
    }
    float ss = v.x * v.x + v.y * v.y + v.z * v.z + v.w * v.w;
    ss = block_reduce_sum(ss);
    float s = rsqrtf(ss * (1.f / DD) + EPSV);
    float4 gw = ((const float4*)gate_w)[threadIdx.x];
    float4 zv = ((const float4*)(xz + row * N1 + DD))[threadIdx.x];
    int rt = (int)(row >> 4), fr = (int)(row & 7), rh = (int)((row >> 3) & 1);
    int kt = d0 >> 3, ch = (d0 >> 2) & 1;
    size_t base = ((size_t)(rt * (DD / 8) + kt) * 32 + fr * 4) * 4 + (rh + 2 * ch);
    y[base +  0] = tf32r(v.x * s * gw.x * silu_f(zv.x));
    y[base +  4] = tf32r(v.y * s * gw.y * silu_f(zv.y));
    y[base +  8] = tf32r(v.z * s * gw.z * silu_f(zv.z));
    y[base + 12] = tf32r(v.w * s * gw.w * silu_f(zv.w));
}

// ---------------- host ----------------
extern "C" void kernel_launch(void* const* d_in, const int* in_sizes, int n_in,
                              void* d_out, int out_size)
{
    const float* x         = (const float*)d_in[0];
    const float* norm_w    = (const float*)d_in[1];
    const float* in_w      = (const float*)d_in[2];
    const float* conv_w    = (const float*)d_in[3];
    const float* conv_b    = (const float*)d_in[4];
    const float* decay     = (const float*)d_in[5];
    const float* gate_w    = (const float*)d_in[6];
    const float* out_w     = (const float*)d_in[7];
    const float* res_scale = (const float*)d_in[8];
    float* out = (float*)d_out;

    float *p_h, *p_xz, *p_hs, *p_wt1, *p_wt2, *p_last, *p_sin;
    cudaGetSymbolAddress((void**)&p_h,    g_h);
    cudaGetSymbolAddress((void**)&p_xz,   g_xz);
    cudaGetSymbolAddress((void**)&p_hs,   g_hs);
    cudaGetSymbolAddress((void**)&p_wt1,  g_wt1);
    cudaGetSymbolAddress((void**)&p_wt2,  g_wt2);
    cudaGetSymbolAddress((void**)&p_last, g_last);
    cudaGetSymbolAddress((void**)&p_sin,  g_sin);

    static bool smem_set = false;
    if (!smem_set) {
        cudaFuncSetAttribute(gemm_tc_kernel,
                             cudaFuncAttributeMaxDynamicSharedMemorySize, GEMM_SMEM);
        smem_set = true;
    }

    // 0. transpose + tf32-round weights -> FM layout
    transpose_kernel<<<dim3(N1 / 32, DD / 32), 256>>>(in_w,  p_wt1, N1);
    transpose_kernel<<<dim3(DD / 32, DD / 32), 256>>>(out_w, p_wt2, DD);

    // 1. h = rmsnorm(x) (tf32-rounded, FM layout)
    rmsnorm_kernel<<<MM, 256>>>(x, norm_w, p_h);

    // 2. xz = h @ in_w
    gemm_tc_kernel<<<dim3(N1 / BN, MM / BM), 128, GEMM_SMEM>>>(
        N1, p_h, p_wt1, p_xz, nullptr, nullptr);

    // 3. chunked conv + local scan + carry chain (fix fused into gate)
    conv_local_kernel<<<(BB * NCH * DD) / 256, 256>>>(p_xz, conv_w, conv_b, decay, p_hs, p_last);
    carry_kernel<<<(BB * DD) / 256, 256>>>(decay, p_last, p_sin);

    // 4. y = rmsnorm(hs + carry)*silu(z) (tf32-rounded, FM layout) -> g_h
    gate_kernel<<<MM, 256>>>(p_hs, gate_w, p_xz, decay, p_sin, p_h);

    // 5. out = res_scale*x + y @ out_w
    gemm_tc_kernel<<<dim3(DD / BN, MM / BM), 128, GEMM_SMEM>>>(
        DD, p_h, p_wt2, out, x, res_scale);
}

// round 10
// speedup vs baseline: 2.4572x; 1.7240x over previous
#include <cuda_runtime.h>
#include <cuda_fp16.h>
#include <math.h>
#include <stdint.h>

// ---------------- problem constants ----------------
#define BB 4
#define SS 4096
#define DD 1024
#define KW 4
#define MM (BB * SS)      // 16384
#define N1 (2 * DD)       // 2048
#define EPSV 1e-6f
#define LCH 128           // scan chunk length
#define NCH (SS / LCH)    // 32
#define NKT (DD / 16)     // 64 fragment k-tiles

// ---------------- scratch (__device__ globals; no allocs) ----------------
// A/B GEMM operands in fp16 FRAGMENT-MAJOR (FM16) layout, stored as uint32 words.
__device__ uint32_t g_h  [(size_t)MM * DD / 2];   // rmsnorm(x) / gated y
__device__ float    g_xz [(size_t)MM * N1];       // GEMM1 out (fp32 row-major)
__device__ float    g_hs [(size_t)MM * DD];       // local scan out
__device__ uint32_t g_wt1[(size_t)N1 * DD / 2];   // in_w^T  FM16
__device__ uint32_t g_wt2[(size_t)DD * DD / 2];   // out_w^T FM16
__device__ float g_last[(size_t)BB * NCH * DD];
__device__ float g_sin [(size_t)BB * NCH * DD];

// FM16 A-type X[R][K] (m16n8k16 .row operand), 32-bit words:
//   rt=r>>4, kt=k>>4, lane=(r&7)*4+((k&15&7)>>1), j=((r>>3)&1)+2*((k&15)>=8), half=k&1
//   word = ((rt*(K/16)+kt)*32 + lane)*4 + j   -> LDS.128 gives {a0,a1,a2,a3}
// FM16 B-type Bt[N][K] (.col operand):
//   word = ((nt*(K/16)+kt)*32 + (n&7)*4+((k&15&7)>>1))*2 + ((k&15)>>3), half=k&1
//   -> LDS.64 gives {b0,b1}

// ---------------- helpers ----------------
__device__ __forceinline__ float silu_f(float v) { return v / (1.f + __expf(-v)); }

__device__ __forceinline__ uint32_t smem_u32(const void* p) {
    uint32_t a;
    asm("{ .reg .u64 t; cvta.to.shared.u64 t, %1; cvt.u32.u64 %0, t; }" : "=r"(a) : "l"(p));
    return a;
}
__device__ __forceinline__ void cp16(uint32_t s, const void* g) {
    asm volatile("cp.async.cg.shared.global [%0], [%1], 16;" :: "r"(s), "l"(g) : "memory");
}
__device__ __forceinline__ void cp_commit() {
    asm volatile("cp.async.commit_group;" ::: "memory");
}
__device__ __forceinline__ void cp_wait1() {
    asm volatile("cp.async.wait_group 1;" ::: "memory");
}
__device__ __forceinline__ void cp_wait0() {
    asm volatile("cp.async.wait_group 0;" ::: "memory");
}

__device__ __forceinline__ void mma_f16(float* c, const uint32_t* a, uint32_t b0, uint32_t b1) {
    asm volatile(
        "mma.sync.aligned.m16n8k16.row.col.f32.f16.f16.f32 "
        "{%0,%1,%2,%3}, {%4,%5,%6,%7}, {%8,%9}, {%0,%1,%2,%3};"
        : "+f"(c[0]), "+f"(c[1]), "+f"(c[2]), "+f"(c[3])
        : "r"(a[0]), "r"(a[1]), "r"(a[2]), "r"(a[3]), "r"(b0), "r"(b1));
}

__device__ __forceinline__ uint32_t pack_h2(float lo, float hi) {
    __half2 h = __floats2half2_rn(lo, hi);
    return *(uint32_t*)&h;
}

// ---------------- block reduction (256 threads) ----------------
__device__ __forceinline__ float block_reduce_sum(float v) {
    __shared__ float red[8];
    int lane = threadIdx.x & 31, wid = threadIdx.x >> 5;
    #pragma unroll
    for (int o = 16; o > 0; o >>= 1) v += __shfl_xor_sync(0xffffffffu, v, o);
    if (lane == 0) red[wid] = v;
    __syncthreads();
    if (wid == 0) {
        v = (lane < 8) ? red[lane] : 0.f;
        #pragma unroll
        for (int o = 4; o > 0; o >>= 1) v += __shfl_xor_sync(0xffffffffu, v, o);
        if (lane == 0) red[0] = v;
    }
    __syncthreads();
    return red[0];
}

// ---------------- weight transpose -> FM16 B layout ----------------
__global__ __launch_bounds__(256) void transpose_kernel(
    const float* __restrict__ in, __half* __restrict__ out, int Nn)
{
    __shared__ float tile[32][33];
    int n0 = blockIdx.x * 32, k0 = blockIdx.y * 32;
    int tx = threadIdx.x & 31, ty = threadIdx.x >> 5;
    #pragma unroll
    for (int i = 0; i < 32; i += 8)
        tile[ty + i][tx] = in[(size_t)(k0 + ty + i) * Nn + n0 + tx];
    __syncthreads();
    int k = k0 + tx;
    int kt = k >> 4, kk = k & 15;
    int fc = (kk & 7) >> 1, hi = kk >> 3, lo = kk & 1;
    #pragma unroll
    for (int i = 0; i < 32; i += 8) {
        int n = n0 + ty + i;
        int nt = n >> 3, fn = n & 7;
        size_t hoff = (((size_t)(nt * NKT + kt) * 32 + fn * 4 + fc) * 2 + hi) * 2 + lo;
        out[hoff] = __float2half_rn(tile[tx][ty + i]);
    }
}

// ---------------- rmsnorm (fp16 FM16 A output) ----------------
__global__ __launch_bounds__(256) void rmsnorm_kernel(
    const float* __restrict__ x, const float* __restrict__ w, uint32_t* __restrict__ out)
{
    size_t row = blockIdx.x;
    float4 v = ((const float4*)(x + row * DD))[threadIdx.x];
    float ss = v.x * v.x + v.y * v.y + v.z * v.z + v.w * v.w;
    ss = block_reduce_sum(ss);
    float s = rsqrtf(ss * (1.f / DD) + EPSV);
    float4 wv = ((const float4*)w)[threadIdx.x];
    int c0 = threadIdx.x * 4;
    int rt = (int)(row >> 4), fr = (int)(row & 7), rh = (int)((row >> 3) & 1);
    int kt = c0 >> 4, kk = c0 & 15, hi = kk >> 3, fc0 = (kk & 7) >> 1;
    size_t wb = ((size_t)(rt * NKT + kt) * 32 + fr * 4 + fc0) * 4 + rh + 2 * hi;
    out[wb]     = pack_h2(v.x * s * wv.x, v.y * s * wv.y);
    out[wb + 4] = pack_h2(v.z * s * wv.z, v.w * s * wv.w);
}

// ---------------- fp16 mma.sync GEMM (FM16 inputs) ----------------
// Block 128x128, BK=64 (4 k-tiles), 3-stage cp.async, 4 warps (2x2),
// warp tile 64x64, 2 CTA/SM.
#define BKK 64
#define STG_WORDS 8192                     // A 4096 + B 4096 uint32
#define GSTG 3
#define GEMM_SMEM (GSTG * STG_WORDS * 4)   // 98304 B

__global__ __launch_bounds__(128, 2) void gemm_tc_kernel(
    int Nn, const uint32_t* __restrict__ A, const uint32_t* __restrict__ Bt,
    float* __restrict__ C,
    const float* __restrict__ resid, const float* __restrict__ rs_ptr)
{
    extern __shared__ float sm[];
    const int tid = threadIdx.x, lane = tid & 31, wid = tid >> 5;
    const int mtile = blockIdx.y * 128, ntile = blockIdx.x * 128;
    const int wmt = (wid & 1) * 4;      // A 16-row tile base
    const int wnt = (wid >> 1) * 8;     // B 8-col tile base

    uint32_t smb = smem_u32(sm);

    // A: per rt block, chunk = 4 kt * 128 words = 2048B contiguous (gmem & smem)
    // B: per nt block, chunk = 4 kt * 64 words = 1024B contiguous
    auto stage_load = [&](int s, int kc) {
        uint32_t as = smb + (uint32_t)s * (STG_WORDS * 4);
        uint32_t bs = as + 4096 * 4;
        #pragma unroll
        for (int rt = 0; rt < 8; rt++)
            cp16(as + (uint32_t)(rt * 2048 + tid * 16),
                 A + (size_t)(blockIdx.y * 8 + rt) * (NKT * 128) + kc * 512 + tid * 4);
        #pragma unroll
        for (int i = 0; i < 8; i++) {
            int nt = i * 2 + (tid >> 6);
            cp16(bs + (uint32_t)(nt * 1024 + (tid & 63) * 16),
                 Bt + (size_t)(blockIdx.x * 16 + nt) * (NKT * 64) + kc * 256 + (tid & 63) * 4);
        }
        cp_commit();
    };

    float acc[4][8][4];
    #pragma unroll
    for (int mi = 0; mi < 4; mi++)
        #pragma unroll
        for (int ni = 0; ni < 8; ni++)
            #pragma unroll
            for (int j = 0; j < 4; j++) acc[mi][ni][j] = 0.f;

    const int NKC = DD / BKK;           // 16
    stage_load(0, 0);
    stage_load(1, 1);

    for (int kc = 0; kc < NKC; kc++) {
        cp_wait1();
        __syncthreads();
        if (kc + 2 < NKC) stage_load((kc + 2) % GSTG, kc + 2);
        else cp_commit();

        const uint32_t* sA = (const uint32_t*)sm + (kc % GSTG) * STG_WORDS;
        const uint32_t* sB = sA + 4096;

        #pragma unroll
        for (int kt = 0; kt < 4; kt++) {
            uint32_t a[4][4];
            #pragma unroll
            for (int mi = 0; mi < 4; mi++) {
                uint4 av = *(const uint4*)(sA + (((wmt + mi) * 4 + kt) * 32 + lane) * 4);
                a[mi][0] = av.x; a[mi][1] = av.y; a[mi][2] = av.z; a[mi][3] = av.w;
            }
            #pragma unroll
            for (int ni = 0; ni < 8; ni++) {
                uint2 bv = *(const uint2*)(sB + (((wnt + ni) * 4 + kt) * 32 + lane) * 2);
                #pragma unroll
                for (int mi = 0; mi < 4; mi++)
                    mma_f16(acc[mi][ni], a[mi], bv.x, bv.y);
            }
        }
        __syncthreads();
    }
    cp_wait0();

    // epilogue (row-major fp32 C)
    const int fr = lane >> 2, fc = lane & 3;
    const int wm = (wid & 1) * 64, wn = (wid >> 1) * 64;
    float rs = 0.f;
    if (resid) rs = __ldg(rs_ptr);
    #pragma unroll
    for (int mi = 0; mi < 4; mi++) {
        #pragma unroll
        for (int half = 0; half < 2; half++) {
            int row = mtile + wm + mi * 16 + half * 8 + fr;
            #pragma unroll
            for (int ni = 0; ni < 8; ni++) {
                int col = ntile + wn + ni * 8 + fc * 2;
                size_t off = (size_t)row * Nn + col;
                float2 v = make_float2(acc[mi][ni][half * 2], acc[mi][ni][half * 2 + 1]);
                if (resid) {
                    float2 rv = *(const float2*)(resid + off);
                    v.x = fmaf(rs, rv.x, v.x);
                    v.y = fmaf(rs, rv.y, v.y);
                }
                *(float2*)(C + off) = v;
            }
        }
    }
}

// ---------------- scan phase 1: local conv+silu+scan per 128-chunk ----------------
__global__ __launch_bounds__(256) void conv_local_kernel(
    const float* __restrict__ xz, const float* __restrict__ conv_w,
    const float* __restrict__ conv_b, const float* __restrict__ decay,
    float* __restrict__ hs, float* __restrict__ last)
{
    int idx = blockIdx.x * blockDim.x + threadIdx.x;   // BB*NCH*DD
    int d = idx % DD;
    int ch = (idx / DD) % NCH;
    int b = idx / (DD * NCH);

    float w0 = conv_w[d * KW + 0], w1 = conv_w[d * KW + 1];
    float w2 = conv_w[d * KW + 2], w3 = conv_w[d * KW + 3];
    float bias = conv_b[d];
    float a = 1.f / (1.f + __expf(-decay[d]));

    int t0 = ch * LCH;
    const float* xb = xz + ((size_t)b * SS + t0) * N1 + d;
    float* out = hs + ((size_t)b * SS + t0) * DD + d;

    float x0 = 0.f, x1 = 0.f, x2 = 0.f;
    if (ch > 0) {
        x0 = xb[-3 * (ptrdiff_t)N1];
        x1 = xb[-2 * (ptrdiff_t)N1];
        x2 = xb[-1 * (ptrdiff_t)N1];
    }
    float h = 0.f;
    #pragma unroll 4
    for (int t = 0; t < LCH; t++) {
        float x3 = xb[(size_t)t * N1];
        float c = fmaf(w0, x0, fmaf(w1, x1, fmaf(w2, x2, fmaf(w3, x3, bias))));
        c = silu_f(c);
        h = fmaf(a, h, c);
        out[(size_t)t * DD] = h;
        x0 = x1; x1 = x2; x2 = x3;
    }
    last[((size_t)b * NCH + ch) * DD + d] = h;
}

// ---------------- scan phase 2: carry chain ----------------
__global__ __launch_bounds__(256) void carry_kernel(
    const float* __restrict__ decay, const float* __restrict__ last,
    float* __restrict__ sin_)
{
    int idx = blockIdx.x * blockDim.x + threadIdx.x;   // BB*DD
    int d = idx % DD, b = idx / DD;
    float a = 1.f / (1.f + __expf(-decay[d]));
    float aL = a;
    #pragma unroll
    for (int i = 0; i < 7; i++) aL *= aL;              // a^128
    float c = 0.f;
    for (int j = 0; j < NCH; j++) {
        size_t o = ((size_t)b * NCH + j) * DD + d;
        sin_[o] = c;
        c = fmaf(aL, c, last[o]);
    }
}

// ---------------- gated rmsnorm with fused carry (fp16 FM16 A output) ----------
__global__ __launch_bounds__(256) void gate_kernel(
    const float* __restrict__ hs, const float* __restrict__ gate_w,
    const float* __restrict__ xz, const float* __restrict__ decay,
    const float* __restrict__ sin_, uint32_t* __restrict__ y)
{
    size_t row = blockIdx.x;
    int b = (int)(row / SS);
    int sidx = (int)(row % SS);
    int chk = sidx / LCH, tt = sidx % LCH;

    float4 v = ((const float4*)(hs + row * DD))[threadIdx.x];
    float4 sv = ((const float4*)(sin_ + ((size_t)b * NCH + chk) * DD))[threadIdx.x];
    float4 dc = ((const float4*)(decay))[threadIdx.x];
    float tp = (float)(tt + 1);
    {
        float a0 = 1.f / (1.f + __expf(-dc.x));
        float a1 = 1.f / (1.f + __expf(-dc.y));
        float a2 = 1.f / (1.f + __expf(-dc.z));
        float a3 = 1.f / (1.f + __expf(-dc.w));
        v.x += sv.x * exp2f(tp * __log2f(a0));
        v.y += sv.y * exp2f(tp * __log2f(a1));
        v.z += sv.z * exp2f(tp * __log2f(a2));
        v.w += sv.w * exp2f(tp * __log2f(a3));
    }
    float ss = v.x * v.x + v.y * v.y + v.z * v.z + v.w * v.w;
    ss = block_reduce_sum(ss);
    float s = rsqrtf(ss * (1.f / DD) + EPSV);
    float4 gw = ((const float4*)gate_w)[threadIdx.x];
    float4 zv = ((const float4*)(xz + row * N1 + DD))[threadIdx.x];
    int c0 = threadIdx.x * 4;
    int rt = (int)(row >> 4), fr = (int)(row & 7), rh = (int)((row >> 3) & 1);
    int kt = c0 >> 4, kk = c0 & 15, hi = kk >> 3, fc0 = (kk & 7) >> 1;
    size_t wb = ((size_t)(rt * NKT + kt) * 32 + fr * 4 + fc0) * 4 + rh + 2 * hi;
    y[wb]     = pack_h2(v.x * s * gw.x * silu_f(zv.x), v.y * s * gw.y * silu_f(zv.y));
    y[wb + 4] = pack_h2(v.z * s * gw.z * silu_f(zv.z), v.w * s * gw.w * silu_f(zv.w));
}

// ---------------- host ----------------
extern "C" void kernel_launch(void* const* d_in, const int* in_sizes, int n_in,
                              void* d_out, int out_size)
{
    const float* x         = (const float*)d_in[0];
    const float* norm_w    = (const float*)d_in[1];
    const float* in_w      = (const float*)d_in[2];
    const float* conv_w    = (const float*)d_in[3];
    const float* conv_b    = (const float*)d_in[4];
    const float* decay     = (const float*)d_in[5];
    const float* gate_w    = (const float*)d_in[6];
    const float* out_w     = (const float*)d_in[7];
    const float* res_scale = (const float*)d_in[8];
    float* out = (float*)d_out;

    uint32_t *p_h, *p_wt1, *p_wt2;
    float *p_xz, *p_hs, *p_last, *p_sin;
    cudaGetSymbolAddress((void**)&p_h,    g_h);
    cudaGetSymbolAddress((void**)&p_xz,   g_xz);
    cudaGetSymbolAddress((void**)&p_hs,   g_hs);
    cudaGetSymbolAddress((void**)&p_wt1,  g_wt1);
    cudaGetSymbolAddress((void**)&p_wt2,  g_wt2);
    cudaGetSymbolAddress((void**)&p_last, g_last);
    cudaGetSymbolAddress((void**)&p_sin,  g_sin);

    static bool smem_set = false;
    if (!smem_set) {
        cudaFuncSetAttribute(gemm_tc_kernel,
                             cudaFuncAttributeMaxDynamicSharedMemorySize, GEMM_SMEM);
        smem_set = true;
    }

    // 0. transpose weights -> fp16 FM16
    transpose_kernel<<<dim3(N1 / 32, DD / 32), 256>>>(in_w,  (__half*)p_wt1, N1);
    transpose_kernel<<<dim3(DD / 32, DD / 32), 256>>>(out_w, (__half*)p_wt2, DD);

    // 1. h = rmsnorm(x) (fp16 FM16)
    rmsnorm_kernel<<<MM, 256>>>(x, norm_w, p_h);

    // 2. xz = h @ in_w
    gemm_tc_kernel<<<dim3(N1 / 128, MM / 128), 128, GEMM_SMEM>>>(
        N1, p_h, p_wt1, p_xz, nullptr, nullptr);

    // 3. chunked conv + local scan + carry chain (fix fused into gate)
    conv_local_kernel<<<(BB * NCH * DD) / 256, 256>>>(p_xz, conv_w, conv_b, decay, p_hs, p_last);
    carry_kernel<<<(BB * DD) / 256, 256>>>(decay, p_last, p_sin);

    // 4. y = rmsnorm(hs + carry)*silu(z) (fp16 FM16) -> g_h
    gate_kernel<<<MM, 256>>>(p_hs, gate_w, p_xz, decay, p_sin, p_h);

    // 5. out = res_scale*x + y @ out_w
    gemm_tc_kernel<<<dim3(DD / 128, MM / 128), 128, GEMM_SMEM>>>(
        DD, p_h, p_wt2, out, x, res_scale);
}

// round 11
// speedup vs baseline: 2.4722x; 1.0061x over previous
#include <cuda_runtime.h>
#include <cuda_fp16.h>
#include <math.h>
#include <stdint.h>

// ---------------- problem constants ----------------
#define BB 4
#define SS 4096
#define DD 1024
#define KW 4
#define MM (BB * SS)      // 16384
#define N1 (2 * DD)       // 2048
#define EPSV 1e-6f
#define LCH 128           // scan chunk length
#define NCH (SS / LCH)    // 32
#define NKT (DD / 16)     // 64 fragment k-tiles

// ---------------- scratch (__device__ globals; no allocs) ----------------
__device__ uint32_t g_h  [(size_t)MM * DD / 2];   // rmsnorm(x) / gated y (FM16)
__device__ __half   g_xz [(size_t)MM * N1];       // GEMM1 out (fp16 row-major)
__device__ __half   g_hs [(size_t)MM * DD];       // local scan out (fp16)
__device__ uint32_t g_wt1[(size_t)N1 * DD / 2];   // in_w^T  FM16
__device__ uint32_t g_wt2[(size_t)DD * DD / 2];   // out_w^T FM16
__device__ float g_last[(size_t)BB * NCH * DD];
__device__ float g_sin [(size_t)BB * NCH * DD];

// FM16 A-type X[R][K] (m16n8k16 .row operand), 32-bit words:
//   word = ((rt*(K/16)+kt)*32 + (r&7)*4 + ((k&7)>>1))*4 + ((r>>3)&1) + 2*((k&15)>=8), half=k&1
// FM16 B-type Bt[N][K] (.col operand):
//   word = ((nt*(K/16)+kt)*32 + (n&7)*4 + ((k&7)>>1))*2 + ((k&15)>>3), half=k&1

// ---------------- helpers ----------------
__device__ __forceinline__ float silu_f(float v) { return v / (1.f + __expf(-v)); }

__device__ __forceinline__ uint32_t smem_u32(const void* p) {
    uint32_t a;
    asm("{ .reg .u64 t; cvta.to.shared.u64 t, %1; cvt.u32.u64 %0, t; }" : "=r"(a) : "l"(p));
    return a;
}
__device__ __forceinline__ void cp16(uint32_t s, const void* g) {
    asm volatile("cp.async.cg.shared.global [%0], [%1], 16;" :: "r"(s), "l"(g) : "memory");
}
__device__ __forceinline__ void cp_commit() {
    asm volatile("cp.async.commit_group;" ::: "memory");
}
__device__ __forceinline__ void cp_wait1() {
    asm volatile("cp.async.wait_group 1;" ::: "memory");
}
__device__ __forceinline__ void cp_wait0() {
    asm volatile("cp.async.wait_group 0;" ::: "memory");
}

__device__ __forceinline__ void mma_f16(float* c, const uint32_t* a, uint32_t b0, uint32_t b1) {
    asm volatile(
        "mma.sync.aligned.m16n8k16.row.col.f32.f16.f16.f32 "
        "{%0,%1,%2,%3}, {%4,%5,%6,%7}, {%8,%9}, {%0,%1,%2,%3};"
        : "+f"(c[0]), "+f"(c[1]), "+f"(c[2]), "+f"(c[3])
        : "r"(a[0]), "r"(a[1]), "r"(a[2]), "r"(a[3]), "r"(b0), "r"(b1));
}

__device__ __forceinline__ uint32_t pack_h2(float lo, float hi) {
    __half2 h = __floats2half2_rn(lo, hi);
    return *(uint32_t*)&h;
}

// ---------------- block reduction (256 threads) ----------------
__device__ __forceinline__ float block_reduce_sum(float v) {
    __shared__ float red[8];
    int lane = threadIdx.x & 31, wid = threadIdx.x >> 5;
    #pragma unroll
    for (int o = 16; o > 0; o >>= 1) v += __shfl_xor_sync(0xffffffffu, v, o);
    if (lane == 0) red[wid] = v;
    __syncthreads();
    if (wid == 0) {
        v = (lane < 8) ? red[lane] : 0.f;
        #pragma unroll
        for (int o = 4; o > 0; o >>= 1) v += __shfl_xor_sync(0xffffffffu, v, o);
        if (lane == 0) red[0] = v;
    }
    __syncthreads();
    return red[0];
}

// ---------------- weight transpose -> FM16 B layout ----------------
__global__ __launch_bounds__(256) void transpose_kernel(
    const float* __restrict__ in, __half* __restrict__ out, int Nn)
{
    __shared__ float tile[32][33];
    int n0 = blockIdx.x * 32, k0 = blockIdx.y * 32;
    int tx = threadIdx.x & 31, ty = threadIdx.x >> 5;
    #pragma unroll
    for (int i = 0; i < 32; i += 8)
        tile[ty + i][tx] = in[(size_t)(k0 + ty + i) * Nn + n0 + tx];
    __syncthreads();
    int k = k0 + tx;
    int kt = k >> 4, kk = k & 15;
    int fc = (kk & 7) >> 1, hi = kk >> 3, lo = kk & 1;
    #pragma unroll
    for (int i = 0; i < 32; i += 8) {
        int n = n0 + ty + i;
        int nt = n >> 3, fn = n & 7;
        size_t hoff = (((size_t)(nt * NKT + kt) * 32 + fn * 4 + fc) * 2 + hi) * 2 + lo;
        out[hoff] = __float2half_rn(tile[tx][ty + i]);
    }
}

// ---------------- rmsnorm (fp16 FM16 A output) ----------------
__global__ __launch_bounds__(256) void rmsnorm_kernel(
    const float* __restrict__ x, const float* __restrict__ w, uint32_t* __restrict__ out)
{
    size_t row = blockIdx.x;
    float4 v = ((const float4*)(x + row * DD))[threadIdx.x];
    float ss = v.x * v.x + v.y * v.y + v.z * v.z + v.w * v.w;
    ss = block_reduce_sum(ss);
    float s = rsqrtf(ss * (1.f / DD) + EPSV);
    float4 wv = ((const float4*)w)[threadIdx.x];
    int c0 = threadIdx.x * 4;
    int rt = (int)(row >> 4), fr = (int)(row & 7), rh = (int)((row >> 3) & 1);
    int kt = c0 >> 4, kk = c0 & 15, hi = kk >> 3, fc0 = (kk & 7) >> 1;
    size_t wb = ((size_t)(rt * NKT + kt) * 32 + fr * 4 + fc0) * 4 + rh + 2 * hi;
    out[wb]     = pack_h2(v.x * s * wv.x, v.y * s * wv.y);
    out[wb + 4] = pack_h2(v.z * s * wv.z, v.w * s * wv.w);
}

// ---------------- fp16 mma.sync GEMM (FM16 inputs) ----------------
// Block 128x128, BK=64 (4 k-tiles), 3-stage cp.async, 4 warps (2x2),
// warp tile 64x64, 2 CTA/SM.
// resid == null  -> C is fp16 (__half, row-major Nn)
// resid != null  -> C is fp32, C = acc + rs*resid
#define BKK 64
#define STG_WORDS 8192                     // A 4096 + B 4096 uint32
#define GSTG 3
#define GEMM_SMEM (GSTG * STG_WORDS * 4)   // 98304 B

__global__ __launch_bounds__(128, 2) void gemm_tc_kernel(
    int Nn, const uint32_t* __restrict__ A, const uint32_t* __restrict__ Bt,
    void* __restrict__ Cv,
    const float* __restrict__ resid, const float* __restrict__ rs_ptr)
{
    extern __shared__ float sm[];
    const int tid = threadIdx.x, lane = tid & 31, wid = tid >> 5;
    const int mtile = blockIdx.y * 128, ntile = blockIdx.x * 128;
    const int wmt = (wid & 1) * 4;      // A 16-row tile base
    const int wnt = (wid >> 1) * 8;     // B 8-col tile base

    uint32_t smb = smem_u32(sm);

    auto stage_load = [&](int s, int kc) {
        uint32_t as = smb + (uint32_t)s * (STG_WORDS * 4);
        uint32_t bs = as + 4096 * 4;
        #pragma unroll
        for (int rt = 0; rt < 8; rt++)
            cp16(as + (uint32_t)(rt * 2048 + tid * 16),
                 A + (size_t)(blockIdx.y * 8 + rt) * (NKT * 128) + kc * 512 + tid * 4);
        #pragma unroll
        for (int i = 0; i < 8; i++) {
            int nt = i * 2 + (tid >> 6);
            cp16(bs + (uint32_t)(nt * 1024 + (tid & 63) * 16),
                 Bt + (size_t)(blockIdx.x * 16 + nt) * (NKT * 64) + kc * 256 + (tid & 63) * 4);
        }
        cp_commit();
    };

    float acc[4][8][4];
    #pragma unroll
    for (int mi = 0; mi < 4; mi++)
        #pragma unroll
        for (int ni = 0; ni < 8; ni++)
            #pragma unroll
            for (int j = 0; j < 4; j++) acc[mi][ni][j] = 0.f;

    const int NKC = DD / BKK;           // 16
    stage_load(0, 0);
    stage_load(1, 1);

    for (int kc = 0; kc < NKC; kc++) {
        cp_wait1();
        __syncthreads();
        if (kc + 2 < NKC) stage_load((kc + 2) % GSTG, kc + 2);
        else cp_commit();

        const uint32_t* sA = (const uint32_t*)sm + (kc % GSTG) * STG_WORDS;
        const uint32_t* sB = sA + 4096;

        #pragma unroll
        for (int kt = 0; kt < 4; kt++) {
            uint32_t a[4][4];
            #pragma unroll
            for (int mi = 0; mi < 4; mi++) {
                uint4 av = *(const uint4*)(sA + (((wmt + mi) * 4 + kt) * 32 + lane) * 4);
                a[mi][0] = av.x; a[mi][1] = av.y; a[mi][2] = av.z; a[mi][3] = av.w;
            }
            #pragma unroll
            for (int ni = 0; ni < 8; ni++) {
                uint2 bv = *(const uint2*)(sB + (((wnt + ni) * 4 + kt) * 32 + lane) * 2);
                #pragma unroll
                for (int mi = 0; mi < 4; mi++)
                    mma_f16(acc[mi][ni], a[mi], bv.x, bv.y);
            }
        }
        __syncthreads();
    }
    cp_wait0();

    // epilogue
    const int fr = lane >> 2, fc = lane & 3;
    const int wm = (wid & 1) * 64, wn = (wid >> 1) * 64;
    if (resid) {
        float* C = (float*)Cv;
        float rs = __ldg(rs_ptr);
        #pragma unroll
        for (int mi = 0; mi < 4; mi++)
            #pragma unroll
            for (int half = 0; half < 2; half++) {
                int row = mtile + wm + mi * 16 + half * 8 + fr;
                #pragma unroll
                for (int ni = 0; ni < 8; ni++) {
                    int col = ntile + wn + ni * 8 + fc * 2;
                    size_t off = (size_t)row * Nn + col;
                    float2 rv = *(const float2*)(resid + off);
                    float2 v = make_float2(fmaf(rs, rv.x, acc[mi][ni][half * 2]),
                                           fmaf(rs, rv.y, acc[mi][ni][half * 2 + 1]));
                    *(float2*)(C + off) = v;
                }
            }
    } else {
        uint32_t* Ch = (uint32_t*)Cv;   // fp16 output, 2 cols per word
        #pragma unroll
        for (int mi = 0; mi < 4; mi++)
            #pragma unroll
            for (int half = 0; half < 2; half++) {
                int row = mtile + wm + mi * 16 + half * 8 + fr;
                #pragma unroll
                for (int ni = 0; ni < 8; ni++) {
                    int col = ntile + wn + ni * 8 + fc * 2;
                    Ch[(size_t)row * (Nn / 2) + col / 2] =
                        pack_h2(acc[mi][ni][half * 2], acc[mi][ni][half * 2 + 1]);
                }
            }
    }
}

// ---------------- scan phase 1: local conv+silu+scan per 128-chunk ----------------
__global__ __launch_bounds__(256) void conv_local_kernel(
    const __half* __restrict__ xz, const float* __restrict__ conv_w,
    const float* __restrict__ conv_b, const float* __restrict__ decay,
    __half* __restrict__ hs, float* __restrict__ last)
{
    int idx = blockIdx.x * blockDim.x + threadIdx.x;   // BB*NCH*DD
    int d = idx % DD;
    int ch = (idx / DD) % NCH;
    int b = idx / (DD * NCH);

    float w0 = conv_w[d * KW + 0], w1 = conv_w[d * KW + 1];
    float w2 = conv_w[d * KW + 2], w3 = conv_w[d * KW + 3];
    float bias = conv_b[d];
    float a = 1.f / (1.f + __expf(-decay[d]));

    int t0 = ch * LCH;
    const __half* xb = xz + ((size_t)b * SS + t0) * N1 + d;
    __half* out = hs + ((size_t)b * SS + t0) * DD + d;

    float x0 = 0.f, x1 = 0.f, x2 = 0.f;
    if (ch > 0) {
        x0 = __half2float(xb[-3 * (ptrdiff_t)N1]);
        x1 = __half2float(xb[-2 * (ptrdiff_t)N1]);
        x2 = __half2float(xb[-1 * (ptrdiff_t)N1]);
    }
    float h = 0.f;
    #pragma unroll 4
    for (int t = 0; t < LCH; t++) {
        float x3 = __half2float(xb[(size_t)t * N1]);
        float c = fmaf(w0, x0, fmaf(w1, x1, fmaf(w2, x2, fmaf(w3, x3, bias))));
        c = silu_f(c);
        h = fmaf(a, h, c);
        out[(size_t)t * DD] = __float2half_rn(h);
        x0 = x1; x1 = x2; x2 = x3;
    }
    last[((size_t)b * NCH + ch) * DD + d] = h;
}

// ---------------- scan phase 2: carry chain ----------------
__global__ __launch_bounds__(256) void carry_kernel(
    const float* __restrict__ decay, const float* __restrict__ last,
    float* __restrict__ sin_)
{
    int idx = blockIdx.x * blockDim.x + threadIdx.x;   // BB*DD
    int d = idx % DD, b = idx / DD;
    float a = 1.f / (1.f + __expf(-decay[d]));
    float aL = a;
    #pragma unroll
    for (int i = 0; i < 7; i++) aL *= aL;              // a^128
    float c = 0.f;
    for (int j = 0; j < NCH; j++) {
        size_t o = ((size_t)b * NCH + j) * DD + d;
        sin_[o] = c;
        c = fmaf(aL, c, last[o]);
    }
}

// ---------------- gated rmsnorm with fused carry (fp16 FM16 A output) ----------
__global__ __launch_bounds__(256) void gate_kernel(
    const __half* __restrict__ hs, const float* __restrict__ gate_w,
    const __half* __restrict__ xz, const float* __restrict__ decay,
    const float* __restrict__ sin_, uint32_t* __restrict__ y)
{
    size_t row = blockIdx.x;
    int b = (int)(row / SS);
    int sidx = (int)(row % SS);
    int chk = sidx / LCH, tt = sidx % LCH;

    // load 4 fp16 hs values
    uint2 hw = ((const uint2*)(hs + row * DD))[threadIdx.x];
    __half2 h01 = *(__half2*)&hw.x, h23 = *(__half2*)&hw.y;
    float4 v;
    { float2 f0 = __half22float2(h01), f1 = __half22float2(h23);
      v.x = f0.x; v.y = f0.y; v.z = f1.x; v.w = f1.y; }

    float4 sv = ((const float4*)(sin_ + ((size_t)b * NCH + chk) * DD))[threadIdx.x];
    float4 dc = ((const float4*)(decay))[threadIdx.x];
    float tp = (float)(tt + 1);
    {
        float a0 = 1.f / (1.f + __expf(-dc.x));
        float a1 = 1.f / (1.f + __expf(-dc.y));
        float a2 = 1.f / (1.f + __expf(-dc.z));
        float a3 = 1.f / (1.f + __expf(-dc.w));
        v.x += sv.x * exp2f(tp * __log2f(a0));
        v.y += sv.y * exp2f(tp * __log2f(a1));
        v.z += sv.z * exp2f(tp * __log2f(a2));
        v.w += sv.w * exp2f(tp * __log2f(a3));
    }
    float ss = v.x * v.x + v.y * v.y + v.z * v.z + v.w * v.w;
    ss = block_reduce_sum(ss);
    float s = rsqrtf(ss * (1.f / DD) + EPSV);
    float4 gw = ((const float4*)gate_w)[threadIdx.x];

    // load 4 fp16 z values
    uint2 zw = ((const uint2*)(xz + row * N1 + DD))[threadIdx.x];
    __half2 z01 = *(__half2*)&zw.x, z23 = *(__half2*)&zw.y;
    float4 zv;
    { float2 f0 = __half22float2(z01), f1 = __half22float2(z23);
      zv.x = f0.x; zv.y = f0.y; zv.z = f1.x; zv.w = f1.y; }

    int c0 = threadIdx.x * 4;
    int rt = (int)(row >> 4), fr = (int)(row & 7), rh = (int)((row >> 3) & 1);
    int kt = c0 >> 4, kk = c0 & 15, hi = kk >> 3, fc0 = (kk & 7) >> 1;
    size_t wb = ((size_t)(rt * NKT + kt) * 32 + fr * 4 + fc0) * 4 + rh + 2 * hi;
    y[wb]     = pack_h2(v.x * s * gw.x * silu_f(zv.x), v.y * s * gw.y * silu_f(zv.y));
    y[wb + 4] = pack_h2(v.z * s * gw.z * silu_f(zv.z), v.w * s * gw.w * silu_f(zv.w));
}

// ---------------- host ----------------
extern "C" void kernel_launch(void* const* d_in, const int* in_sizes, int n_in,
                              void* d_out, int out_size)
{
    const float* x         = (const float*)d_in[0];
    const float* norm_w    = (const float*)d_in[1];
    const float* in_w      = (const float*)d_in[2];
    const float* conv_w    = (const float*)d_in[3];
    const float* conv_b    = (const float*)d_in[4];
    const float* decay     = (const float*)d_in[5];
    const float* gate_w    = (const float*)d_in[6];
    const float* out_w     = (const float*)d_in[7];
    const float* res_scale = (const float*)d_in[8];
    float* out = (float*)d_out;

    uint32_t *p_h, *p_wt1, *p_wt2;
    __half *p_xz, *p_hs;
    float *p_last, *p_sin;
    cudaGetSymbolAddress((void**)&p_h,    g_h);
    cudaGetSymbolAddress((void**)&p_xz,   g_xz);
    cudaGetSymbolAddress((void**)&p_hs,   g_hs);
    cudaGetSymbolAddress((void**)&p_wt1,  g_wt1);
    cudaGetSymbolAddress((void**)&p_wt2,  g_wt2);
    cudaGetSymbolAddress((void**)&p_last, g_last);
    cudaGetSymbolAddress((void**)&p_sin,  g_sin);

    static bool smem_set = false;
    if (!smem_set) {
        cudaFuncSetAttribute(gemm_tc_kernel,
                             cudaFuncAttributeMaxDynamicSharedMemorySize, GEMM_SMEM);
        smem_set = true;
    }

    // 0. transpose weights -> fp16 FM16
    transpose_kernel<<<dim3(N1 / 32, DD / 32), 256>>>(in_w,  (__half*)p_wt1, N1);
    transpose_kernel<<<dim3(DD / 32, DD / 32), 256>>>(out_w, (__half*)p_wt2, DD);

    // 1. h = rmsnorm(x) (fp16 FM16)
    rmsnorm_kernel<<<MM, 256>>>(x, norm_w, p_h);

    // 2. xz = h @ in_w  (fp16 output)
    gemm_tc_kernel<<<dim3(N1 / 128, MM / 128), 128, GEMM_SMEM>>>(
        N1, p_h, p_wt1, p_xz, nullptr, nullptr);

    // 3. chunked conv + local scan + carry chain (fix fused into gate)
    conv_local_kernel<<<(BB * NCH * DD) / 256, 256>>>(p_xz, conv_w, conv_b, decay, p_hs, p_last);
    carry_kernel<<<(BB * DD) / 256, 256>>>(decay, p_last, p_sin);

    // 4. y = rmsnorm(hs + carry)*silu(z) (fp16 FM16) -> g_h
    gate_kernel<<<MM, 256>>>(p_hs, gate_w, p_xz, decay, p_sin, p_h);

    // 5. out = res_scale*x + y @ out_w  (fp32 + residual)
    gemm_tc_kernel<<<dim3(DD / 128, MM / 128), 128, GEMM_SMEM>>>(
        DD, p_h, p_wt2, out, x, res_scale);
}

// round 12
// speedup vs baseline: 2.5922x; 1.0485x over previous
#include <cuda_runtime.h>
#include <cuda_fp16.h>
#include <math.h>
#include <stdint.h>

// ---------------- problem constants ----------------
#define BB 4
#define SS 4096
#define DD 1024
#define KW 4
#define MM (BB * SS)      // 16384
#define N1 (2 * DD)       // 2048
#define EPSV 1e-6f
#define LCH 64            // scan chunk length
#define NCH (SS / LCH)    // 64
#define NKT (DD / 16)     // 64 fragment k-tiles

// ---------------- scratch (__device__ globals; no allocs) ----------------
__device__ uint32_t g_h  [(size_t)MM * DD / 2];   // rmsnorm(x) / gated y (FM16)
__device__ __half   g_xz [(size_t)MM * N1];       // GEMM1 out (fp16 row-major)
__device__ __half   g_hs [(size_t)MM * DD];       // local scan out (fp16)
__device__ uint32_t g_wt1[(size_t)N1 * DD / 2];   // in_w^T  FM16
__device__ uint32_t g_wt2[(size_t)DD * DD / 2];   // out_w^T FM16
__device__ float g_last[(size_t)BB * NCH * DD];
__device__ float g_sin [(size_t)BB * NCH * DD];

// FM16 A-type X[R][K] (m16n8k16 .row operand), 32-bit words:
//   word = ((rt*(K/16)+kt)*32 + (r&7)*4 + ((k&7)>>1))*4 + ((r>>3)&1) + 2*((k&15)>=8), half=k&1
// FM16 B-type Bt[N][K] (.col operand):
//   word = ((nt*(K/16)+kt)*32 + (n&7)*4 + ((k&7)>>1))*2 + ((k&15)>>3), half=k&1

// ---------------- helpers ----------------
__device__ __forceinline__ float silu_f(float v) { return v / (1.f + __expf(-v)); }

__device__ __forceinline__ uint32_t smem_u32(const void* p) {
    uint32_t a;
    asm("{ .reg .u64 t; cvta.to.shared.u64 t, %1; cvt.u32.u64 %0, t; }" : "=r"(a) : "l"(p));
    return a;
}
__device__ __forceinline__ void cp16(uint32_t s, const void* g) {
    asm volatile("cp.async.cg.shared.global [%0], [%1], 16;" :: "r"(s), "l"(g) : "memory");
}
__device__ __forceinline__ void cp_commit() {
    asm volatile("cp.async.commit_group;" ::: "memory");
}
__device__ __forceinline__ void cp_wait1() {
    asm volatile("cp.async.wait_group 1;" ::: "memory");
}
__device__ __forceinline__ void cp_wait0() {
    asm volatile("cp.async.wait_group 0;" ::: "memory");
}

__device__ __forceinline__ void mma_f16(float* c, const uint32_t* a, uint32_t b0, uint32_t b1) {
    asm volatile(
        "mma.sync.aligned.m16n8k16.row.col.f32.f16.f16.f32 "
        "{%0,%1,%2,%3}, {%4,%5,%6,%7}, {%8,%9}, {%0,%1,%2,%3};"
        : "+f"(c[0]), "+f"(c[1]), "+f"(c[2]), "+f"(c[3])
        : "r"(a[0]), "r"(a[1]), "r"(a[2]), "r"(a[3]), "r"(b0), "r"(b1));
}

__device__ __forceinline__ uint32_t pack_h2(float lo, float hi) {
    __half2 h = __floats2half2_rn(lo, hi);
    return *(uint32_t*)&h;
}

__device__ __forceinline__ float warp_reduce_sum(float v) {
    #pragma unroll
    for (int o = 16; o > 0; o >>= 1) v += __shfl_xor_sync(0xffffffffu, v, o);
    return v;
}

// ---------------- weight transpose -> FM16 B layout ----------------
__global__ __launch_bounds__(256) void transpose_kernel(
    const float* __restrict__ in, __half* __restrict__ out, int Nn)
{
    __shared__ float tile[32][33];
    int n0 = blockIdx.x * 32, k0 = blockIdx.y * 32;
    int tx = threadIdx.x & 31, ty = threadIdx.x >> 5;
    #pragma unroll
    for (int i = 0; i < 32; i += 8)
        tile[ty + i][tx] = in[(size_t)(k0 + ty + i) * Nn + n0 + tx];
    __syncthreads();
    int k = k0 + tx;
    int kt = k >> 4, kk = k & 15;
    int fc = (kk & 7) >> 1, hi = kk >> 3, lo = kk & 1;
    #pragma unroll
    for (int i = 0; i < 32; i += 8) {
        int n = n0 + ty + i;
        int nt = n >> 3, fn = n & 7;
        size_t hoff = (((size_t)(nt * NKT + kt) * 32 + fn * 4 + fc) * 2 + hi) * 2 + lo;
        out[hoff] = __float2half_rn(tile[tx][ty + i]);
    }
}

// ---------------- rmsnorm, warp-per-row (fp16 FM16 A output) ----------------
__global__ __launch_bounds__(256) void rmsnorm_kernel(
    const float* __restrict__ x, const float* __restrict__ w, uint32_t* __restrict__ out)
{
    int warp = threadIdx.x >> 5, lane = threadIdx.x & 31;
    size_t row = (size_t)blockIdx.x * 8 + warp;
    const float4* xr = (const float4*)(x + row * DD);

    float4 v[8];
    float ss = 0.f;
    #pragma unroll
    for (int j = 0; j < 8; j++) {
        v[j] = xr[j * 32 + lane];
        ss += v[j].x * v[j].x + v[j].y * v[j].y + v[j].z * v[j].z + v[j].w * v[j].w;
    }
    ss = warp_reduce_sum(ss);
    float s = rsqrtf(ss * (1.f / DD) + EPSV);

    int rt = (int)(row >> 4), fr = (int)(row & 7), rh = (int)((row >> 3) & 1);
    #pragma unroll
    for (int j = 0; j < 8; j++) {
        float4 wv = ((const float4*)w)[j * 32 + lane];
        int c0 = (j * 32 + lane) * 4;
        int kt = c0 >> 4, kk = c0 & 15, hi = kk >> 3, fc0 = (kk & 7) >> 1;
        size_t wb = ((size_t)(rt * NKT + kt) * 32 + fr * 4 + fc0) * 4 + rh + 2 * hi;
        out[wb]     = pack_h2(v[j].x * s * wv.x, v[j].y * s * wv.y);
        out[wb + 4] = pack_h2(v[j].z * s * wv.z, v[j].w * s * wv.w);
    }
}

// ---------------- fp16 mma.sync GEMM (FM16 inputs) ----------------
// Block 128x128, BK=64 (4 k-tiles), 3-stage cp.async, 4 warps (2x2),
// warp tile 64x64, 2 CTA/SM.
// resid == null  -> C is fp16 (__half, row-major Nn)
// resid != null  -> C is fp32, C = acc + rs*resid
#define BKK 64
#define STG_WORDS 8192                     // A 4096 + B 4096 uint32
#define GSTG 3
#define GEMM_SMEM (GSTG * STG_WORDS * 4)   // 98304 B

__global__ __launch_bounds__(128, 2) void gemm_tc_kernel(
    int Nn, const uint32_t* __restrict__ A, const uint32_t* __restrict__ Bt,
    void* __restrict__ Cv,
    const float* __restrict__ resid, const float* __restrict__ rs_ptr)
{
    extern __shared__ float sm[];
    const int tid = threadIdx.x, lane = tid & 31, wid = tid >> 5;
    const int mtile = blockIdx.y * 128, ntile = blockIdx.x * 128;
    const int wmt = (wid & 1) * 4;      // A 16-row tile base
    const int wnt = (wid >> 1) * 8;     // B 8-col tile base

    uint32_t smb = smem_u32(sm);

    auto stage_load = [&](int s, int kc) {
        uint32_t as = smb + (uint32_t)s * (STG_WORDS * 4);
        uint32_t bs = as + 4096 * 4;
        #pragma unroll
        for (int rt = 0; rt < 8; rt++)
            cp16(as + (uint32_t)(rt * 2048 + tid * 16),
                 A + (size_t)(blockIdx.y * 8 + rt) * (NKT * 128) + kc * 512 + tid * 4);
        #pragma unroll
        for (int i = 0; i < 8; i++) {
            int nt = i * 2 + (tid >> 6);
            cp16(bs + (uint32_t)(nt * 1024 + (tid & 63) * 16),
                 Bt + (size_t)(blockIdx.x * 16 + nt) * (NKT * 64) + kc * 256 + (tid & 63) * 4);
        }
        cp_commit();
    };

    float acc[4][8][4];
    #pragma unroll
    for (int mi = 0; mi < 4; mi++)
        #pragma unroll
        for (int ni = 0; ni < 8; ni++)
            #pragma unroll
            for (int j = 0; j < 4; j++) acc[mi][ni][j] = 0.f;

    const int NKC = DD / BKK;           // 16
    stage_load(0, 0);
    stage_load(1, 1);

    for (int kc = 0; kc < NKC; kc++) {
        cp_wait1();
        __syncthreads();
        if (kc + 2 < NKC) stage_load((kc + 2) % GSTG, kc + 2);
        else cp_commit();

        const uint32_t* sA = (const uint32_t*)sm + (kc % GSTG) * STG_WORDS;
        const uint32_t* sB = sA + 4096;

        #pragma unroll
        for (int kt = 0; kt < 4; kt++) {
            uint32_t a[4][4];
            #pragma unroll
            for (int mi = 0; mi < 4; mi++) {
                uint4 av = *(const uint4*)(sA + (((wmt + mi) * 4 + kt) * 32 + lane) * 4);
                a[mi][0] = av.x; a[mi][1] = av.y; a[mi][2] = av.z; a[mi][3] = av.w;
            }
            #pragma unroll
            for (int ni = 0; ni < 8; ni++) {
                uint2 bv = *(const uint2*)(sB + (((wnt + ni) * 4 + kt) * 32 + lane) * 2);
                #pragma unroll
                for (int mi = 0; mi < 4; mi++)
                    mma_f16(acc[mi][ni], a[mi], bv.x, bv.y);
            }
        }
        __syncthreads();
    }
    cp_wait0();

    // epilogue
    const int fr = lane >> 2, fc = lane & 3;
    const int wm = (wid & 1) * 64, wn = (wid >> 1) * 64;
    if (resid) {
        float* C = (float*)Cv;
        float rs = __ldg(rs_ptr);
        #pragma unroll
        for (int mi = 0; mi < 4; mi++)
            #pragma unroll
            for (int half = 0; half < 2; half++) {
                int row = mtile + wm + mi * 16 + half * 8 + fr;
                #pragma unroll
                for (int ni = 0; ni < 8; ni++) {
                    int col = ntile + wn + ni * 8 + fc * 2;
                    size_t off = (size_t)row * Nn + col;
                    float2 rv = *(const float2*)(resid + off);
                    float2 v = make_float2(fmaf(rs, rv.x, acc[mi][ni][half * 2]),
                                           fmaf(rs, rv.y, acc[mi][ni][half * 2 + 1]));
                    *(float2*)(C + off) = v;
                }
            }
    } else {
        uint32_t* Ch = (uint32_t*)Cv;   // fp16 output, 2 cols per word
        #pragma unroll
        for (int mi = 0; mi < 4; mi++)
            #pragma unroll
            for (int half = 0; half < 2; half++) {
                int row = mtile + wm + mi * 16 + half * 8 + fr;
                #pragma unroll
                for (int ni = 0; ni < 8; ni++) {
                    int col = ntile + wn + ni * 8 + fc * 2;
                    Ch[(size_t)row * (Nn / 2) + col / 2] =
                        pack_h2(acc[mi][ni][half * 2], acc[mi][ni][half * 2 + 1]);
                }
            }
    }
}

// ---------------- scan phase 1: local conv+silu+scan per 64-chunk ----------------
__global__ __launch_bounds__(256) void conv_local_kernel(
    const __half* __restrict__ xz, const float* __restrict__ conv_w,
    const float* __restrict__ conv_b, const float* __restrict__ decay,
    __half* __restrict__ hs, float* __restrict__ last)
{
    int idx = blockIdx.x * blockDim.x + threadIdx.x;   // BB*NCH*DD
    int d = idx % DD;
    int ch = (idx / DD) % NCH;
    int b = idx / (DD * NCH);

    float w0 = conv_w[d * KW + 0], w1 = conv_w[d * KW + 1];
    float w2 = conv_w[d * KW + 2], w3 = conv_w[d * KW + 3];
    float bias = conv_b[d];
    float a = 1.f / (1.f + __expf(-decay[d]));

    int t0 = ch * LCH;
    const __half* xb = xz + ((size_t)b * SS + t0) * N1 + d;
    __half* out = hs + ((size_t)b * SS + t0) * DD + d;

    float x0 = 0.f, x1 = 0.f, x2 = 0.f;
    if (ch > 0) {
        x0 = __half2float(xb[-3 * (ptrdiff_t)N1]);
        x1 = __half2float(xb[-2 * (ptrdiff_t)N1]);
        x2 = __half2float(xb[-1 * (ptrdiff_t)N1]);
    }
    float h = 0.f;
    #pragma unroll 4
    for (int t = 0; t < LCH; t++) {
        float x3 = __half2float(xb[(size_t)t * N1]);
        float c = fmaf(w0, x0, fmaf(w1, x1, fmaf(w2, x2, fmaf(w3, x3, bias))));
        c = silu_f(c);
        h = fmaf(a, h, c);
        out[(size_t)t * DD] = __float2half_rn(h);
        x0 = x1; x1 = x2; x2 = x3;
    }
    last[((size_t)b * NCH + ch) * DD + d] = h;
}

// ---------------- scan phase 2: carry chain ----------------
__global__ __launch_bounds__(256) void carry_kernel(
    const float* __restrict__ decay, const float* __restrict__ last,
    float* __restrict__ sin_)
{
    int idx = blockIdx.x * blockDim.x + threadIdx.x;   // BB*DD
    int d = idx % DD, b = idx / DD;
    float a = 1.f / (1.f + __expf(-decay[d]));
    float aL = a;
    #pragma unroll
    for (int i = 0; i < 6; i++) aL *= aL;              // a^64
    float c = 0.f;
    for (int j = 0; j < NCH; j++) {
        size_t o = ((size_t)b * NCH + j) * DD + d;
        sin_[o] = c;
        c = fmaf(aL, c, last[o]);
    }
}

// ---------------- gated rmsnorm with fused carry, warp-per-row (FM16 out) -----
__global__ __launch_bounds__(256) void gate_kernel(
    const __half* __restrict__ hs, const float* __restrict__ gate_w,
    const __half* __restrict__ xz, const float* __restrict__ decay,
    const float* __restrict__ sin_, uint32_t* __restrict__ y)
{
    int warp = threadIdx.x >> 5, lane = threadIdx.x & 31;
    size_t row = (size_t)blockIdx.x * 8 + warp;
    int b = (int)(row / SS);
    int sidx = (int)(row % SS);
    int chk = sidx / LCH, tt = sidx % LCH;
    float tp = (float)(tt + 1);

    const uint2* hr = (const uint2*)(hs + row * DD);
    const float4* sr = (const float4*)(sin_ + ((size_t)b * NCH + chk) * DD);
    const float4* dr = (const float4*)decay;

    float4 v[8];
    float ss = 0.f;
    #pragma unroll
    for (int j = 0; j < 8; j++) {
        uint2 hw = hr[j * 32 + lane];
        float2 f0 = __half22float2(*(__half2*)&hw.x);
        float2 f1 = __half22float2(*(__half2*)&hw.y);
        float4 sv = sr[j * 32 + lane];
        float4 dc = dr[j * 32 + lane];
        float a0 = 1.f / (1.f + __expf(-dc.x));
        float a1 = 1.f / (1.f + __expf(-dc.y));
        float a2 = 1.f / (1.f + __expf(-dc.z));
        float a3 = 1.f / (1.f + __expf(-dc.w));
        v[j].x = f0.x + sv.x * exp2f(tp * __log2f(a0));
        v[j].y = f0.y + sv.y * exp2f(tp * __log2f(a1));
        v[j].z = f1.x + sv.z * exp2f(tp * __log2f(a2));
        v[j].w = f1.y + sv.w * exp2f(tp * __log2f(a3));
        ss += v[j].x * v[j].x + v[j].y * v[j].y + v[j].z * v[j].z + v[j].w * v[j].w;
    }
    ss = warp_reduce_sum(ss);
    float s = rsqrtf(ss * (1.f / DD) + EPSV);

    const uint2* zr = (const uint2*)(xz + row * N1 + DD);
    int rt = (int)(row >> 4), fr = (int)(row & 7), rh = (int)((row >> 3) & 1);
    #pragma unroll
    for (int j = 0; j < 8; j++) {
        float4 gw = ((const float4*)gate_w)[j * 32 + lane];
        uint2 zw = zr[j * 32 + lane];
        float2 z0 = __half22float2(*(__half2*)&zw.x);
        float2 z1 = __half22float2(*(__half2*)&zw.y);
        int c0 = (j * 32 + lane) * 4;
        int kt = c0 >> 4, kk = c0 & 15, hi = kk >> 3, fc0 = (kk & 7) >> 1;
        size_t wb = ((size_t)(rt * NKT + kt) * 32 + fr * 4 + fc0) * 4 + rh + 2 * hi;
        y[wb]     = pack_h2(v[j].x * s * gw.x * silu_f(z0.x), v[j].y * s * gw.y * silu_f(z0.y));
        y[wb + 4] = pack_h2(v[j].z * s * gw.z * silu_f(z1.x), v[j].w * s * gw.w * silu_f(z1.y));
    }
}

// ---------------- host ----------------
extern "C" void kernel_launch(void* const* d_in, const int* in_sizes, int n_in,
                              void* d_out, int out_size)
{
    const float* x         = (const float*)d_in[0];
    const float* norm_w    = (const float*)d_in[1];
    const float* in_w      = (const float*)d_in[2];
    const float* conv_w    = (const float*)d_in[3];
    const float* conv_b    = (const float*)d_in[4];
    const float* decay     = (const float*)d_in[5];
    const float* gate_w    = (const float*)d_in[6];
    const float* out_w     = (const float*)d_in[7];
    const float* res_scale = (const float*)d_in[8];
    float* out = (float*)d_out;

    uint32_t *p_h, *p_wt1, *p_wt2;
    __half *p_xz, *p_hs;
    float *p_last, *p_sin;
    cudaGetSymbolAddress((void**)&p_h,    g_h);
    cudaGetSymbolAddress((void**)&p_xz,   g_xz);
    cudaGetSymbolAddress((void**)&p_hs,   g_hs);
    cudaGetSymbolAddress((void**)&p_wt1,  g_wt1);
    cudaGetSymbolAddress((void**)&p_wt2,  g_wt2);
    cudaGetSymbolAddress((void**)&p_last, g_last);
    cudaGetSymbolAddress((void**)&p_sin,  g_sin);

    static bool smem_set = false;
    if (!smem_set) {
        cudaFuncSetAttribute(gemm_tc_kernel,
                             cudaFuncAttributeMaxDynamicSharedMemorySize, GEMM_SMEM);
        smem_set = true;
    }

    // 0. transpose weights -> fp16 FM16
    transpose_kernel<<<dim3(N1 / 32, DD / 32), 256>>>(in_w,  (__half*)p_wt1, N1);
    transpose_kernel<<<dim3(DD / 32, DD / 32), 256>>>(out_w, (__half*)p_wt2, DD);

    // 1. h = rmsnorm(x) (fp16 FM16), warp-per-row
    rmsnorm_kernel<<<MM / 8, 256>>>(x, norm_w, p_h);

    // 2. xz = h @ in_w  (fp16 output)
    gemm_tc_kernel<<<dim3(N1 / 128, MM / 128), 128, GEMM_SMEM>>>(
        N1, p_h, p_wt1, p_xz, nullptr, nullptr);

    // 3. chunked conv + local scan (LCH=64) + carry chain
    conv_local_kernel<<<(BB * NCH * DD) / 256, 256>>>(p_xz, conv_w, conv_b, decay, p_hs, p_last);
    carry_kernel<<<(BB * DD) / 256, 256>>>(decay, p_last, p_sin);

    // 4. y = rmsnorm(hs + carry)*silu(z) (fp16 FM16), warp-per-row -> g_h
    gate_kernel<<<MM / 8, 256>>>(p_hs, gate_w, p_xz, decay, p_sin, p_h);

    // 5. out = res_scale*x + y @ out_w  (fp32 + residual)
    gemm_tc_kernel<<<dim3(DD / 128, MM / 128), 128, GEMM_SMEM>>>(
        DD, p_h, p_wt2, out, x, res_scale);
}

// round 13
// speedup vs baseline: 2.6886x; 1.0372x over previous
#include <cuda_runtime.h>
#include <cuda_fp16.h>
#include <math.h>
#include <stdint.h>

// ---------------- problem constants ----------------
#define BB 4
#define SS 4096
#define DD 1024
#define KW 4
#define MM (BB * SS)      // 16384
#define N1 (2 * DD)       // 2048
#define EPSV 1e-6f
#define LCH 64            // scan chunk length
#define NCH (SS / LCH)    // 64
#define NKT (DD / 16)     // 64 fragment k-tiles

// ---------------- scratch (__device__ globals; no allocs) ----------------
__device__ uint32_t g_h  [(size_t)MM * DD / 2];   // rmsnorm(x) / gated y (FM16)
__device__ __half   g_xz [(size_t)MM * N1];       // GEMM1 out (fp16 row-major)
__device__ __half   g_hs [(size_t)MM * DD];       // local scan out (fp16)
__device__ uint32_t g_wt1[(size_t)N1 * DD / 2];   // in_w^T  FM16
__device__ uint32_t g_wt2[(size_t)DD * DD / 2];   // out_w^T FM16
__device__ float g_last[(size_t)BB * NCH * DD];
__device__ float g_sin [(size_t)BB * NCH * DD];
__device__ float g_l2a [DD];                      // log2(sigmoid(decay))

// FM16 A-type X[R][K] (m16n8k16 .row operand), 32-bit words:
//   word = ((rt*(K/16)+kt)*32 + (r&7)*4 + ((k&7)>>1))*4 + ((r>>3)&1) + 2*((k&15)>=8), half=k&1
// FM16 B-type Bt[N][K] (.col operand):
//   word = ((nt*(K/16)+kt)*32 + (n&7)*4 + ((k&7)>>1))*2 + ((k&15)>>3), half=k&1

// ---------------- helpers ----------------
__device__ __forceinline__ float silu_f(float v) { return v / (1.f + __expf(-v)); }

__device__ __forceinline__ uint32_t smem_u32(const void* p) {
    uint32_t a;
    asm("{ .reg .u64 t; cvta.to.shared.u64 t, %1; cvt.u32.u64 %0, t; }" : "=r"(a) : "l"(p));
    return a;
}
__device__ __forceinline__ void cp16(uint32_t s, const void* g) {
    asm volatile("cp.async.cg.shared.global [%0], [%1], 16;" :: "r"(s), "l"(g) : "memory");
}
__device__ __forceinline__ void cp_commit() {
    asm volatile("cp.async.commit_group;" ::: "memory");
}
__device__ __forceinline__ void cp_wait1() {
    asm volatile("cp.async.wait_group 1;" ::: "memory");
}
__device__ __forceinline__ void cp_wait0() {
    asm volatile("cp.async.wait_group 0;" ::: "memory");
}

__device__ __forceinline__ void mma_f16(float* c, const uint32_t* a, uint32_t b0, uint32_t b1) {
    asm volatile(
        "mma.sync.aligned.m16n8k16.row.col.f32.f16.f16.f32 "
        "{%0,%1,%2,%3}, {%4,%5,%6,%7}, {%8,%9}, {%0,%1,%2,%3};"
        : "+f"(c[0]), "+f"(c[1]), "+f"(c[2]), "+f"(c[3])
        : "r"(a[0]), "r"(a[1]), "r"(a[2]), "r"(a[3]), "r"(b0), "r"(b1));
}

__device__ __forceinline__ uint32_t pack_h2(float lo, float hi) {
    __half2 h = __floats2half2_rn(lo, hi);
    return *(uint32_t*)&h;
}

__device__ __forceinline__ float warp_reduce_sum(float v) {
    #pragma unroll
    for (int o = 16; o > 0; o >>= 1) v += __shfl_xor_sync(0xffffffffu, v, o);
    return v;
}

// ---------------- weight transpose -> FM16 B layout (both weights, one launch) --
__global__ __launch_bounds__(256) void transpose_kernel(
    const float* __restrict__ in1, __half* __restrict__ out1,
    const float* __restrict__ in2, __half* __restrict__ out2)
{
    const float* in;
    __half* out;
    int Nn;
    if (blockIdx.z == 0) { in = in1; out = out1; Nn = N1; }
    else {
        if (blockIdx.x >= DD / 32) return;
        in = in2; out = out2; Nn = DD;
    }
    __shared__ float tile[32][33];
    int n0 = blockIdx.x * 32, k0 = blockIdx.y * 32;
    int tx = threadIdx.x & 31, ty = threadIdx.x >> 5;
    #pragma unroll
    for (int i = 0; i < 32; i += 8)
        tile[ty + i][tx] = in[(size_t)(k0 + ty + i) * Nn + n0 + tx];
    __syncthreads();
    int k = k0 + tx;
    int kt = k >> 4, kk = k & 15;
    int fc = (kk & 7) >> 1, hi = kk >> 3, lo = kk & 1;
    #pragma unroll
    for (int i = 0; i < 32; i += 8) {
        int n = n0 + ty + i;
        int nt = n >> 3, fn = n & 7;
        size_t hoff = (((size_t)(nt * NKT + kt) * 32 + fn * 4 + fc) * 2 + hi) * 2 + lo;
        out[hoff] = __float2half_rn(tile[tx][ty + i]);
    }
}

// ---------------- rmsnorm, warp-per-row (fp16 FM16 A output) ----------------
__global__ __launch_bounds__(256) void rmsnorm_kernel(
    const float* __restrict__ x, const float* __restrict__ w, uint32_t* __restrict__ out)
{
    int warp = threadIdx.x >> 5, lane = threadIdx.x & 31;
    size_t row = (size_t)blockIdx.x * 8 + warp;
    const float4* xr = (const float4*)(x + row * DD);

    float4 v[8];
    float ss = 0.f;
    #pragma unroll
    for (int j = 0; j < 8; j++) {
        v[j] = xr[j * 32 + lane];
        ss += v[j].x * v[j].x + v[j].y * v[j].y + v[j].z * v[j].z + v[j].w * v[j].w;
    }
    ss = warp_reduce_sum(ss);
    float s = rsqrtf(ss * (1.f / DD) + EPSV);

    int rt = (int)(row >> 4), fr = (int)(row & 7), rh = (int)((row >> 3) & 1);
    #pragma unroll
    for (int j = 0; j < 8; j++) {
        float4 wv = ((const float4*)w)[j * 32 + lane];
        int c0 = (j * 32 + lane) * 4;
        int kt = c0 >> 4, kk = c0 & 15, hi = kk >> 3, fc0 = (kk & 7) >> 1;
        size_t wb = ((size_t)(rt * NKT + kt) * 32 + fr * 4 + fc0) * 4 + rh + 2 * hi;
        out[wb]     = pack_h2(v[j].x * s * wv.x, v[j].y * s * wv.y);
        out[wb + 4] = pack_h2(v[j].z * s * wv.z, v[j].w * s * wv.w);
    }
}

// ---------------- fp16 mma.sync GEMM (FM16 inputs) ----------------
// Block 128x128, BK=64 (4 k-tiles), 3-stage cp.async, 4 warps (2x2),
// warp tile 64x64, 2 CTA/SM. ONE barrier per k-chunk (stage (kc+2)%3 ==
// (kc-1)%3 whose readers all passed this iteration's top barrier).
// resid == null  -> C is fp16 (__half, row-major Nn)
// resid != null  -> C is fp32, C = acc + rs*resid
#define BKK 64
#define STG_WORDS 8192                     // A 4096 + B 4096 uint32
#define GSTG 3
#define GEMM_SMEM (GSTG * STG_WORDS * 4)   // 98304 B

__global__ __launch_bounds__(128, 2) void gemm_tc_kernel(
    int Nn, const uint32_t* __restrict__ A, const uint32_t* __restrict__ Bt,
    void* __restrict__ Cv,
    const float* __restrict__ resid, const float* __restrict__ rs_ptr)
{
    extern __shared__ float sm[];
    const int tid = threadIdx.x, lane = tid & 31, wid = tid >> 5;
    const int mtile = blockIdx.y * 128, ntile = blockIdx.x * 128;
    const int wmt = (wid & 1) * 4;      // A 16-row tile base
    const int wnt = (wid >> 1) * 8;     // B 8-col tile base

    uint32_t smb = smem_u32(sm);

    auto stage_load = [&](int s, int kc) {
        uint32_t as = smb + (uint32_t)s * (STG_WORDS * 4);
        uint32_t bs = as + 4096 * 4;
        #pragma unroll
        for (int rt = 0; rt < 8; rt++)
            cp16(as + (uint32_t)(rt * 2048 + tid * 16),
                 A + (size_t)(blockIdx.y * 8 + rt) * (NKT * 128) + kc * 512 + tid * 4);
        #pragma unroll
        for (int i = 0; i < 8; i++) {
            int nt = i * 2 + (tid >> 6);
            cp16(bs + (uint32_t)(nt * 1024 + (tid & 63) * 16),
                 Bt + (size_t)(blockIdx.x * 16 + nt) * (NKT * 64) + kc * 256 + (tid & 63) * 4);
        }
        cp_commit();
    };

    float acc[4][8][4];
    #pragma unroll
    for (int mi = 0; mi < 4; mi++)
        #pragma unroll
        for (int ni = 0; ni < 8; ni++)
            #pragma unroll
            for (int j = 0; j < 4; j++) acc[mi][ni][j] = 0.f;

    const int NKC = DD / BKK;           // 16
    stage_load(0, 0);
    stage_load(1, 1);

    for (int kc = 0; kc < NKC; kc++) {
        cp_wait1();
        __syncthreads();                 // single barrier per chunk
        if (kc + 2 < NKC) stage_load((kc + 2) % GSTG, kc + 2);
        else cp_commit();

        const uint32_t* sA = (const uint32_t*)sm + (kc % GSTG) * STG_WORDS;
        const uint32_t* sB = sA + 4096;

        #pragma unroll
        for (int kt = 0; kt < 4; kt++) {
            uint32_t a[4][4];
            #pragma unroll
            for (int mi = 0; mi < 4; mi++) {
                uint4 av = *(const uint4*)(sA + (((wmt + mi) * 4 + kt) * 32 + lane) * 4);
                a[mi][0] = av.x; a[mi][1] = av.y; a[mi][2] = av.z; a[mi][3] = av.w;
            }
            #pragma unroll
            for (int ni = 0; ni < 8; ni++) {
                uint2 bv = *(const uint2*)(sB + (((wnt + ni) * 4 + kt) * 32 + lane) * 2);
                #pragma unroll
                for (int mi = 0; mi < 4; mi++)
                    mma_f16(acc[mi][ni], a[mi], bv.x, bv.y);
            }
        }
    }
    cp_wait0();

    // epilogue
    const int fr = lane >> 2, fc = lane & 3;
    const int wm = (wid & 1) * 64, wn = (wid >> 1) * 64;
    if (resid) {
        float* C = (float*)Cv;
        float rs = __ldg(rs_ptr);
        #pragma unroll
        for (int mi = 0; mi < 4; mi++)
            #pragma unroll
            for (int half = 0; half < 2; half++) {
                int row = mtile + wm + mi * 16 + half * 8 + fr;
                #pragma unroll
                for (int ni = 0; ni < 8; ni++) {
                    int col = ntile + wn + ni * 8 + fc * 2;
                    size_t off = (size_t)row * Nn + col;
                    float2 rv = *(const float2*)(resid + off);
                    float2 v = make_float2(fmaf(rs, rv.x, acc[mi][ni][half * 2]),
                                           fmaf(rs, rv.y, acc[mi][ni][half * 2 + 1]));
                    *(float2*)(C + off) = v;
                }
            }
    } else {
        uint32_t* Ch = (uint32_t*)Cv;   // fp16 output, 2 cols per word
        #pragma unroll
        for (int mi = 0; mi < 4; mi++)
            #pragma unroll
            for (int half = 0; half < 2; half++) {
                int row = mtile + wm + mi * 16 + half * 8 + fr;
                #pragma unroll
                for (int ni = 0; ni < 8; ni++) {
                    int col = ntile + wn + ni * 8 + fc * 2;
                    Ch[(size_t)row * (Nn / 2) + col / 2] =
                        pack_h2(acc[mi][ni][half * 2], acc[mi][ni][half * 2 + 1]);
                }
            }
    }
}

// ---------------- scan phase 1: local conv+silu+scan, 2 channels/thread -------
__global__ __launch_bounds__(256) void conv_local_kernel(
    const __half* __restrict__ xz, const float* __restrict__ conv_w,
    const float* __restrict__ conv_b, const float* __restrict__ decay,
    __half* __restrict__ hs, float* __restrict__ last)
{
    int idx = blockIdx.x * blockDim.x + threadIdx.x;   // BB*NCH*DD/2
    int d2 = idx % (DD / 2);                           // pair index
    int ch = (idx / (DD / 2)) % NCH;
    int b  = idx / ((DD / 2) * NCH);
    int d  = d2 * 2;

    float4 cw0 = *(const float4*)(conv_w + d * KW);        // w[d][0..3]
    float4 cw1 = *(const float4*)(conv_w + (d + 1) * KW);  // w[d+1][0..3]
    float2 bias = *(const float2*)(conv_b + d);
    float2 dc   = *(const float2*)(decay + d);
    float aA = 1.f / (1.f + __expf(-dc.x));
    float aB = 1.f / (1.f + __expf(-dc.y));

    int t0 = ch * LCH;
    const __half2* xb = (const __half2*)(xz + ((size_t)b * SS + t0) * N1) + d2;
    __half2* out = (__half2*)(hs + ((size_t)b * SS + t0) * DD) + d2;

    float x0A = 0.f, x1A = 0.f, x2A = 0.f;
    float x0B = 0.f, x1B = 0.f, x2B = 0.f;
    if (ch > 0) {
        float2 p3 = __half22float2(xb[-3 * (N1 / 2)]);
        float2 p2 = __half22float2(xb[-2 * (N1 / 2)]);
        float2 p1 = __half22float2(xb[-1 * (N1 / 2)]);
        x0A = p3.x; x1A = p2.x; x2A = p1.x;
        x0B = p3.y; x1B = p2.y; x2B = p1.y;
    }
    float hA = 0.f, hB = 0.f;
    #pragma unroll 4
    for (int t = 0; t < LCH; t++) {
        float2 xt = __half22float2(xb[(size_t)t * (N1 / 2)]);
        float cA = fmaf(cw0.x, x0A, fmaf(cw0.y, x1A, fmaf(cw0.z, x2A, fmaf(cw0.w, xt.x, bias.x))));
        float cB = fmaf(cw1.x, x0B, fmaf(cw1.y, x1B, fmaf(cw1.z, x2B, fmaf(cw1.w, xt.y, bias.y))));
        cA = silu_f(cA);
        cB = silu_f(cB);
        hA = fmaf(aA, hA, cA);
        hB = fmaf(aB, hB, cB);
        out[(size_t)t * (DD / 2)] = __floats2half2_rn(hA, hB);
        x0A = x1A; x1A = x2A; x2A = xt.x;
        x0B = x1B; x1B = x2B; x2B = xt.y;
    }
    *(float2*)(last + ((size_t)b * NCH + ch) * DD + d) = make_float2(hA, hB);
}

// ---------------- scan phase 2: carry chain + l2a precompute ----------------
__global__ __launch_bounds__(256) void carry_kernel(
    const float* __restrict__ decay, const float* __restrict__ last,
    float* __restrict__ sin_, float* __restrict__ l2a)
{
    int idx = blockIdx.x * blockDim.x + threadIdx.x;   // BB*DD
    int d = idx % DD, b = idx / DD;
    float a = 1.f / (1.f + __expf(-decay[d]));
    if (b == 0) l2a[d] = log2f(a);
    float aL = a;
    #pragma unroll
    for (int i = 0; i < 6; i++) aL *= aL;              // a^64
    float c = 0.f;
    for (int j = 0; j < NCH; j++) {
        size_t o = ((size_t)b * NCH + j) * DD + d;
        sin_[o] = c;
        c = fmaf(aL, c, last[o]);
    }
}

// ---------------- gated rmsnorm with fused carry, warp-per-row (FM16 out) -----
__global__ __launch_bounds__(256) void gate_kernel(
    const __half* __restrict__ hs, const float* __restrict__ gate_w,
    const __half* __restrict__ xz, const float* __restrict__ l2a,
    const float* __restrict__ sin_, uint32_t* __restrict__ y)
{
    int warp = threadIdx.x >> 5, lane = threadIdx.x & 31;
    size_t row = (size_t)blockIdx.x * 8 + warp;
    int b = (int)(row / SS);
    int sidx = (int)(row % SS);
    int chk = sidx / LCH, tt = sidx % LCH;
    float tp = (float)(tt + 1);

    const uint2* hr = (const uint2*)(hs + row * DD);
    const float4* sr = (const float4*)(sin_ + ((size_t)b * NCH + chk) * DD);
    const float4* lr = (const float4*)l2a;

    float4 v[8];
    float ss = 0.f;
    #pragma unroll
    for (int j = 0; j < 8; j++) {
        uint2 hw = hr[j * 32 + lane];
        float2 f0 = __half22float2(*(__half2*)&hw.x);
        float2 f1 = __half22float2(*(__half2*)&hw.y);
        float4 sv = sr[j * 32 + lane];
        float4 la = lr[j * 32 + lane];
        v[j].x = f0.x + sv.x * exp2f(tp * la.x);
        v[j].y = f0.y + sv.y * exp2f(tp * la.y);
        v[j].z = f1.x + sv.z * exp2f(tp * la.z);
        v[j].w = f1.y + sv.w * exp2f(tp * la.w);
        ss += v[j].x * v[j].x + v[j].y * v[j].y + v[j].z * v[j].z + v[j].w * v[j].w;
    }
    ss = warp_reduce_sum(ss);
    float s = rsqrtf(ss * (1.f / DD) + EPSV);

    const uint2* zr = (const uint2*)(xz + row * N1 + DD);
    int rt = (int)(row >> 4), fr = (int)(row & 7), rh = (int)((row >> 3) & 1);
    #pragma unroll
    for (int j = 0; j < 8; j++) {
        float4 gw = ((const float4*)gate_w)[j * 32 + lane];
        uint2 zw = zr[j * 32 + lane];
        float2 z0 = __half22float2(*(__half2*)&zw.x);
        float2 z1 = __half22float2(*(__half2*)&zw.y);
        int c0 = (j * 32 + lane) * 4;
        int kt = c0 >> 4, kk = c0 & 15, hi = kk >> 3, fc0 = (kk & 7) >> 1;
        size_t wb = ((size_t)(rt * NKT + kt) * 32 + fr * 4 + fc0) * 4 + rh + 2 * hi;
        y[wb]     = pack_h2(v[j].x * s * gw.x * silu_f(z0.x), v[j].y * s * gw.y * silu_f(z0.y));
        y[wb + 4] = pack_h2(v[j].z * s * gw.z * silu_f(z1.x), v[j].w * s * gw.w * silu_f(z1.y));
    }
}

// ---------------- host ----------------
extern "C" void kernel_launch(void* const* d_in, const int* in_sizes, int n_in,
                              void* d_out, int out_size)
{
    const float* x         = (const float*)d_in[0];
    const float* norm_w    = (const float*)d_in[1];
    const float* in_w      = (const float*)d_in[2];
    const float* conv_w    = (const float*)d_in[3];
    const float* conv_b    = (const float*)d_in[4];
    const float* decay     = (const float*)d_in[5];
    const float* gate_w    = (const float*)d_in[6];
    const float* out_w     = (const float*)d_in[7];
    const float* res_scale = (const float*)d_in[8];
    float* out = (float*)d_out;

    uint32_t *p_h, *p_wt1, *p_wt2;
    __half *p_xz, *p_hs;
    float *p_last, *p_sin, *p_l2a;
    cudaGetSymbolAddress((void**)&p_h,    g_h);
    cudaGetSymbolAddress((void**)&p_xz,   g_xz);
    cudaGetSymbolAddress((void**)&p_hs,   g_hs);
    cudaGetSymbolAddress((void**)&p_wt1,  g_wt1);
    cudaGetSymbolAddress((void**)&p_wt2,  g_wt2);
    cudaGetSymbolAddress((void**)&p_last, g_last);
    cudaGetSymbolAddress((void**)&p_sin,  g_sin);
    cudaGetSymbolAddress((void**)&p_l2a,  g_l2a);

    static bool smem_set = false;
    if (!smem_set) {
        cudaFuncSetAttribute(gemm_tc_kernel,
                             cudaFuncAttributeMaxDynamicSharedMemorySize, GEMM_SMEM);
        smem_set = true;
    }

    // 0. transpose both weights -> fp16 FM16 (one launch)
    transpose_kernel<<<dim3(N1 / 32, DD / 32, 2), 256>>>(
        in_w, (__half*)p_wt1, out_w, (__half*)p_wt2);

    // 1. h = rmsnorm(x) (fp16 FM16), warp-per-row
    rmsnorm_kernel<<<MM / 8, 256>>>(x, norm_w, p_h);

    // 2. xz = h @ in_w  (fp16 output)
    gemm_tc_kernel<<<dim3(N1 / 128, MM / 128), 128, GEMM_SMEM>>>(
        N1, p_h, p_wt1, p_xz, nullptr, nullptr);

    // 3. chunked conv + local scan (LCH=64, 2ch/thread) + carry chain
    conv_local_kernel<<<(BB * NCH * DD / 2) / 256, 256>>>(
        p_xz, conv_w, conv_b, decay, p_hs, p_last);
    carry_kernel<<<(BB * DD) / 256, 256>>>(decay, p_last, p_sin, p_l2a);

    // 4. y = rmsnorm(hs + carry)*silu(z) (fp16 FM16), warp-per-row -> g_h
    gate_kernel<<<MM / 8, 256>>>(p_hs, gate_w, p_xz, p_l2a, p_sin, p_h);

    // 5. out = res_scale*x + y @ out_w  (fp32 + residual)
    gemm_tc_kernel<<<dim3(DD / 128, MM / 128), 128, GEMM_SMEM>>>(
        DD, p_h, p_wt2, out, x, res_scale);
}

// round 14
// speedup vs baseline: 2.6950x; 1.0024x over previous
#include <cuda_runtime.h>
#include <cuda_fp16.h>
#include <math.h>
#include <stdint.h>

// ---------------- problem constants ----------------
#define BB 4
#define SS 4096
#define DD 1024
#define KW 4
#define MM (BB * SS)      // 16384
#define N1 (2 * DD)       // 2048
#define EPSV 1e-6f
#define LCH 32            // scan chunk length
#define NCH (SS / LCH)    // 128
#define NKT (DD / 16)     // 64 fragment k-tiles

// ---------------- scratch (__device__ globals; no allocs) ----------------
__device__ uint32_t g_h  [(size_t)MM * DD / 2];   // rmsnorm(x) / gated y (FM16)
__device__ __half   g_xz [(size_t)MM * N1];       // GEMM1 out (fp16 row-major)
__device__ __half   g_hs [(size_t)MM * DD];       // local scan out (fp16)
__device__ uint32_t g_wt1[(size_t)N1 * DD / 2];   // in_w^T  FM16
__device__ uint32_t g_wt2[(size_t)DD * DD / 2];   // out_w^T FM16
__device__ float g_last[(size_t)BB * NCH * DD];
__device__ float g_sin [(size_t)BB * NCH * DD];
__device__ float g_l2a [DD];                      // log2(sigmoid(decay))

// FM16 A-type X[R][K] (m16n8k16 .row operand), 32-bit words:
//   word = ((rt*(K/16)+kt)*32 + (r&7)*4 + ((k&7)>>1))*4 + ((r>>3)&1) + 2*((k&15)>=8), half=k&1
// FM16 B-type Bt[N][K] (.col operand):
//   word = ((nt*(K/16)+kt)*32 + (n&7)*4 + ((k&7)>>1))*2 + ((k&15)>>3), half=k&1

// ---------------- helpers ----------------
__device__ __forceinline__ float silu_f(float v) { return v / (1.f + __expf(-v)); }

__device__ __forceinline__ uint32_t smem_u32(const void* p) {
    uint32_t a;
    asm("{ .reg .u64 t; cvta.to.shared.u64 t, %1; cvt.u32.u64 %0, t; }" : "=r"(a) : "l"(p));
    return a;
}
__device__ __forceinline__ void cp16(uint32_t s, const void* g) {
    asm volatile("cp.async.cg.shared.global [%0], [%1], 16;" :: "r"(s), "l"(g) : "memory");
}
__device__ __forceinline__ void cp_commit() {
    asm volatile("cp.async.commit_group;" ::: "memory");
}
__device__ __forceinline__ void cp_wait1() {
    asm volatile("cp.async.wait_group 1;" ::: "memory");
}
__device__ __forceinline__ void cp_wait0() {
    asm volatile("cp.async.wait_group 0;" ::: "memory");
}

__device__ __forceinline__ void mma_f16(float* c, const uint32_t* a, uint32_t b0, uint32_t b1) {
    asm volatile(
        "mma.sync.aligned.m16n8k16.row.col.f32.f16.f16.f32 "
        "{%0,%1,%2,%3}, {%4,%5,%6,%7}, {%8,%9}, {%0,%1,%2,%3};"
        : "+f"(c[0]), "+f"(c[1]), "+f"(c[2]), "+f"(c[3])
        : "r"(a[0]), "r"(a[1]), "r"(a[2]), "r"(a[3]), "r"(b0), "r"(b1));
}

__device__ __forceinline__ uint32_t pack_h2(float lo, float hi) {
    __half2 h = __floats2half2_rn(lo, hi);
    return *(uint32_t*)&h;
}

__device__ __forceinline__ float warp_reduce_sum(float v) {
    #pragma unroll
    for (int o = 16; o > 0; o >>= 1) v += __shfl_xor_sync(0xffffffffu, v, o);
    return v;
}

// ---------------- weight transpose -> FM16 B layout (both weights, one launch) --
__global__ __launch_bounds__(256) void transpose_kernel(
    const float* __restrict__ in1, __half* __restrict__ out1,
    const float* __restrict__ in2, __half* __restrict__ out2)
{
    const float* in;
    __half* out;
    int Nn;
    if (blockIdx.z == 0) { in = in1; out = out1; Nn = N1; }
    else {
        if (blockIdx.x >= DD / 32) return;
        in = in2; out = out2; Nn = DD;
    }
    __shared__ float tile[32][33];
    int n0 = blockIdx.x * 32, k0 = blockIdx.y * 32;
    int tx = threadIdx.x & 31, ty = threadIdx.x >> 5;
    #pragma unroll
    for (int i = 0; i < 32; i += 8)
        tile[ty + i][tx] = in[(size_t)(k0 + ty + i) * Nn + n0 + tx];
    __syncthreads();
    int k = k0 + tx;
    int kt = k >> 4, kk = k & 15;
    int fc = (kk & 7) >> 1, hi = kk >> 3, lo = kk & 1;
    #pragma unroll
    for (int i = 0; i < 32; i += 8) {
        int n = n0 + ty + i;
        int nt = n >> 3, fn = n & 7;
        size_t hoff = (((size_t)(nt * NKT + kt) * 32 + fn * 4 + fc) * 2 + hi) * 2 + lo;
        out[hoff] = __float2half_rn(tile[tx][ty + i]);
    }
}

// ---------------- rmsnorm, warp-per-row (fp16 FM16 A output) ----------------
__global__ __launch_bounds__(256) void rmsnorm_kernel(
    const float* __restrict__ x, const float* __restrict__ w, uint32_t* __restrict__ out)
{
    int warp = threadIdx.x >> 5, lane = threadIdx.x & 31;
    size_t row = (size_t)blockIdx.x * 8 + warp;
    const float4* xr = (const float4*)(x + row * DD);

    float4 v[8];
    float ss = 0.f;
    #pragma unroll
    for (int j = 0; j < 8; j++) {
        v[j] = xr[j * 32 + lane];
        ss += v[j].x * v[j].x + v[j].y * v[j].y + v[j].z * v[j].z + v[j].w * v[j].w;
    }
    ss = warp_reduce_sum(ss);
    float s = rsqrtf(ss * (1.f / DD) + EPSV);

    int rt = (int)(row >> 4), fr = (int)(row & 7), rh = (int)((row >> 3) & 1);
    #pragma unroll
    for (int j = 0; j < 8; j++) {
        float4 wv = ((const float4*)w)[j * 32 + lane];
        int c0 = (j * 32 + lane) * 4;
        int kt = c0 >> 4, kk = c0 & 15, hi = kk >> 3, fc0 = (kk & 7) >> 1;
        size_t wb = ((size_t)(rt * NKT + kt) * 32 + fr * 4 + fc0) * 4 + rh + 2 * hi;
        out[wb]     = pack_h2(v[j].x * s * wv.x, v[j].y * s * wv.y);
        out[wb + 4] = pack_h2(v[j].z * s * wv.z, v[j].w * s * wv.w);
    }
}

// ---------------- fp16 mma.sync GEMM (FM16 inputs) ----------------
// Block 128x128, BK=64 (4 k-tiles), 3-stage cp.async, 4 warps (2x2),
// warp tile 64x64, 2 CTA/SM, single barrier per k-chunk.
// resid == null  -> C is fp16 (__half, row-major Nn)
// resid != null  -> C is fp32, C = acc + rs*resid
#define BKK 64
#define STG_WORDS 8192                     // A 4096 + B 4096 uint32
#define GSTG 3
#define GEMM_SMEM (GSTG * STG_WORDS * 4)   // 98304 B

__global__ __launch_bounds__(128, 2) void gemm_tc_kernel(
    int Nn, const uint32_t* __restrict__ A, const uint32_t* __restrict__ Bt,
    void* __restrict__ Cv,
    const float* __restrict__ resid, const float* __restrict__ rs_ptr)
{
    extern __shared__ float sm[];
    const int tid = threadIdx.x, lane = tid & 31, wid = tid >> 5;
    const int mtile = blockIdx.y * 128, ntile = blockIdx.x * 128;
    const int wmt = (wid & 1) * 4;      // A 16-row tile base
    const int wnt = (wid >> 1) * 8;     // B 8-col tile base

    uint32_t smb = smem_u32(sm);

    auto stage_load = [&](int s, int kc) {
        uint32_t as = smb + (uint32_t)s * (STG_WORDS * 4);
        uint32_t bs = as + 4096 * 4;
        #pragma unroll
        for (int rt = 0; rt < 8; rt++)
            cp16(as + (uint32_t)(rt * 2048 + tid * 16),
                 A + (size_t)(blockIdx.y * 8 + rt) * (NKT * 128) + kc * 512 + tid * 4);
        #pragma unroll
        for (int i = 0; i < 8; i++) {
            int nt = i * 2 + (tid >> 6);
            cp16(bs + (uint32_t)(nt * 1024 + (tid & 63) * 16),
                 Bt + (size_t)(blockIdx.x * 16 + nt) * (NKT * 64) + kc * 256 + (tid & 63) * 4);
        }
        cp_commit();
    };

    float acc[4][8][4];
    #pragma unroll
    for (int mi = 0; mi < 4; mi++)
        #pragma unroll
        for (int ni = 0; ni < 8; ni++)
            #pragma unroll
            for (int j = 0; j < 4; j++) acc[mi][ni][j] = 0.f;

    const int NKC = DD / BKK;           // 16
    stage_load(0, 0);
    stage_load(1, 1);

    for (int kc = 0; kc < NKC; kc++) {
        cp_wait1();
        __syncthreads();                 // single barrier per chunk
        if (kc + 2 < NKC) stage_load((kc + 2) % GSTG, kc + 2);
        else cp_commit();

        const uint32_t* sA = (const uint32_t*)sm + (kc % GSTG) * STG_WORDS;
        const uint32_t* sB = sA + 4096;

        #pragma unroll
        for (int kt = 0; kt < 4; kt++) {
            uint32_t a[4][4];
            #pragma unroll
            for (int mi = 0; mi < 4; mi++) {
                uint4 av = *(const uint4*)(sA + (((wmt + mi) * 4 + kt) * 32 + lane) * 4);
                a[mi][0] = av.x; a[mi][1] = av.y; a[mi][2] = av.z; a[mi][3] = av.w;
            }
            #pragma unroll
            for (int ni = 0; ni < 8; ni++) {
                uint2 bv = *(const uint2*)(sB + (((wnt + ni) * 4 + kt) * 32 + lane) * 2);
                #pragma unroll
                for (int mi = 0; mi < 4; mi++)
                    mma_f16(acc[mi][ni], a[mi], bv.x, bv.y);
            }
        }
    }
    cp_wait0();

    // epilogue
    const int fr = lane >> 2, fc = lane & 3;
    const int wm = (wid & 1) * 64, wn = (wid >> 1) * 64;
    if (resid) {
        float* C = (float*)Cv;
        float rs = __ldg(rs_ptr);
        #pragma unroll
        for (int mi = 0; mi < 4; mi++)
            #pragma unroll
            for (int half = 0; half < 2; half++) {
                int row = mtile + wm + mi * 16 + half * 8 + fr;
                #pragma unroll
                for (int ni = 0; ni < 8; ni++) {
                    int col = ntile + wn + ni * 8 + fc * 2;
                    size_t off = (size_t)row * Nn + col;
                    float2 rv = *(const float2*)(resid + off);
                    float2 v = make_float2(fmaf(rs, rv.x, acc[mi][ni][half * 2]),
                                           fmaf(rs, rv.y, acc[mi][ni][half * 2 + 1]));
                    *(float2*)(C + off) = v;
                }
            }
    } else {
        uint32_t* Ch = (uint32_t*)Cv;   // fp16 output, 2 cols per word
        #pragma unroll
        for (int mi = 0; mi < 4; mi++)
            #pragma unroll
            for (int half = 0; half < 2; half++) {
                int row = mtile + wm + mi * 16 + half * 8 + fr;
                #pragma unroll
                for (int ni = 0; ni < 8; ni++) {
                    int col = ntile + wn + ni * 8 + fc * 2;
                    Ch[(size_t)row * (Nn / 2) + col / 2] =
                        pack_h2(acc[mi][ni][half * 2], acc[mi][ni][half * 2 + 1]);
                }
            }
    }
}

// ---------------- scan phase 1: local conv+silu+scan, 2 channels/thread -------
__global__ __launch_bounds__(256) void conv_local_kernel(
    const __half* __restrict__ xz, const float* __restrict__ conv_w,
    const float* __restrict__ conv_b, const float* __restrict__ decay,
    __half* __restrict__ hs, float* __restrict__ last)
{
    int idx = blockIdx.x * blockDim.x + threadIdx.x;   // BB*NCH*DD/2
    int d2 = idx % (DD / 2);                           // pair index
    int ch = (idx / (DD / 2)) % NCH;
    int b  = idx / ((DD / 2) * NCH);
    int d  = d2 * 2;

    float4 cw0 = *(const float4*)(conv_w + d * KW);        // w[d][0..3]
    float4 cw1 = *(const float4*)(conv_w + (d + 1) * KW);  // w[d+1][0..3]
    float2 bias = *(const float2*)(conv_b + d);
    float2 dc   = *(const float2*)(decay + d);
    float aA = 1.f / (1.f + __expf(-dc.x));
    float aB = 1.f / (1.f + __expf(-dc.y));

    int t0 = ch * LCH;
    const __half2* xb = (const __half2*)(xz + ((size_t)b * SS + t0) * N1) + d2;
    __half2* out = (__half2*)(hs + ((size_t)b * SS + t0) * DD) + d2;

    float x0A = 0.f, x1A = 0.f, x2A = 0.f;
    float x0B = 0.f, x1B = 0.f, x2B = 0.f;
    if (ch > 0) {
        float2 p3 = __half22float2(xb[-3 * (N1 / 2)]);
        float2 p2 = __half22float2(xb[-2 * (N1 / 2)]);
        float2 p1 = __half22float2(xb[-1 * (N1 / 2)]);
        x0A = p3.x; x1A = p2.x; x2A = p1.x;
        x0B = p3.y; x1B = p2.y; x2B = p1.y;
    }
    float hA = 0.f, hB = 0.f;
    #pragma unroll 4
    for (int t = 0; t < LCH; t++) {
        float2 xt = __half22float2(xb[(size_t)t * (N1 / 2)]);
        float cA = fmaf(cw0.x, x0A, fmaf(cw0.y, x1A, fmaf(cw0.z, x2A, fmaf(cw0.w, xt.x, bias.x))));
        float cB = fmaf(cw1.x, x0B, fmaf(cw1.y, x1B, fmaf(cw1.z, x2B, fmaf(cw1.w, xt.y, bias.y))));
        cA = silu_f(cA);
        cB = silu_f(cB);
        hA = fmaf(aA, hA, cA);
        hB = fmaf(aB, hB, cB);
        out[(size_t)t * (DD / 2)] = __floats2half2_rn(hA, hB);
        x0A = x1A; x1A = x2A; x2A = xt.x;
        x0B = x1B; x1B = x2B; x2B = xt.y;
    }
    *(float2*)(last + ((size_t)b * NCH + ch) * DD + d) = make_float2(hA, hB);
}

// ---------------- scan phase 2: carry chain + l2a precompute ----------------
__global__ __launch_bounds__(256) void carry_kernel(
    const float* __restrict__ decay, const float* __restrict__ last,
    float* __restrict__ sin_, float* __restrict__ l2a)
{
    int idx = blockIdx.x * blockDim.x + threadIdx.x;   // BB*DD
    int d = idx % DD, b = idx / DD;
    float a = 1.f / (1.f + __expf(-decay[d]));
    if (b == 0) l2a[d] = log2f(a);
    float aL = a;
    #pragma unroll
    for (int i = 0; i < 5; i++) aL *= aL;              // a^32
    float c = 0.f;
    #pragma unroll 4
    for (int j = 0; j < NCH; j++) {
        size_t o = ((size_t)b * NCH + j) * DD + d;
        sin_[o] = c;
        c = fmaf(aL, c, last[o]);
    }
}

// ---------------- gated rmsnorm with fused carry, warp-per-row (FM16 out) -----
__global__ __launch_bounds__(256) void gate_kernel(
    const __half* __restrict__ hs, const float* __restrict__ gate_w,
    const __half* __restrict__ xz, const float* __restrict__ l2a,
    const float* __restrict__ sin_, uint32_t* __restrict__ y)
{
    int warp = threadIdx.x >> 5, lane = threadIdx.x & 31;
    size_t row = (size_t)blockIdx.x * 8 + warp;
    int b = (int)(row / SS);
    int sidx = (int)(row % SS);
    int chk = sidx / LCH, tt = sidx % LCH;
    float tp = (float)(tt + 1);

    const uint2* hr = (const uint2*)(hs + row * DD);
    const float4* sr = (const float4*)(sin_ + ((size_t)b * NCH + chk) * DD);
    const float4* lr = (const float4*)l2a;

    float4 v[8];
    float ss = 0.f;
    #pragma unroll
    for (int j = 0; j < 8; j++) {
        uint2 hw = hr[j * 32 + lane];
        float2 f0 = __half22float2(*(__half2*)&hw.x);
        float2 f1 = __half22float2(*(__half2*)&hw.y);
        float4 sv = sr[j * 32 + lane];
        float4 la = lr[j * 32 + lane];
        v[j].x = f0.x + sv.x * exp2f(tp * la.x);
        v[j].y = f0.y + sv.y * exp2f(tp * la.y);
        v[j].z = f1.x + sv.z * exp2f(tp * la.z);
        v[j].w = f1.y + sv.w * exp2f(tp * la.w);
        ss += v[j].x * v[j].x + v[j].y * v[j].y + v[j].z * v[j].z + v[j].w * v[j].w;
    }
    ss = warp_reduce_sum(ss);
    float s = rsqrtf(ss * (1.f / DD) + EPSV);

    const uint2* zr = (const uint2*)(xz + row * N1 + DD);
    int rt = (int)(row >> 4), fr = (int)(row & 7), rh = (int)((row >> 3) & 1);
    #pragma unroll
    for (int j = 0; j < 8; j++) {
        float4 gw = ((const float4*)gate_w)[j * 32 + lane];
        uint2 zw = zr[j * 32 + lane];
        float2 z0 = __half22float2(*(__half2*)&zw.x);
        float2 z1 = __half22float2(*(__half2*)&zw.y);
        int c0 = (j * 32 + lane) * 4;
        int kt = c0 >> 4, kk = c0 & 15, hi = kk >> 3, fc0 = (kk & 7) >> 1;
        size_t wb = ((size_t)(rt * NKT + kt) * 32 + fr * 4 + fc0) * 4 + rh + 2 * hi;
        y[wb]     = pack_h2(v[j].x * s * gw.x * silu_f(z0.x), v[j].y * s * gw.y * silu_f(z0.y));
        y[wb + 4] = pack_h2(v[j].z * s * gw.z * silu_f(z1.x), v[j].w * s * gw.w * silu_f(z1.y));
    }
}

// ---------------- host ----------------
extern "C" void kernel_launch(void* const* d_in, const int* in_sizes, int n_in,
                              void* d_out, int out_size)
{
    const float* x         = (const float*)d_in[0];
    const float* norm_w    = (const float*)d_in[1];
    const float* in_w      = (const float*)d_in[2];
    const float* conv_w    = (const float*)d_in[3];
    const float* conv_b    = (const float*)d_in[4];
    const float* decay     = (const float*)d_in[5];
    const float* gate_w    = (const float*)d_in[6];
    const float* out_w     = (const float*)d_in[7];
    const float* res_scale = (const float*)d_in[8];
    float* out = (float*)d_out;

    uint32_t *p_h, *p_wt1, *p_wt2;
    __half *p_xz, *p_hs;
    float *p_last, *p_sin, *p_l2a;
    cudaGetSymbolAddress((void**)&p_h,    g_h);
    cudaGetSymbolAddress((void**)&p_xz,   g_xz);
    cudaGetSymbolAddress((void**)&p_hs,   g_hs);
    cudaGetSymbolAddress((void**)&p_wt1,  g_wt1);
    cudaGetSymbolAddress((void**)&p_wt2,  g_wt2);
    cudaGetSymbolAddress((void**)&p_last, g_last);
    cudaGetSymbolAddress((void**)&p_sin,  g_sin);
    cudaGetSymbolAddress((void**)&p_l2a,  g_l2a);

    static bool smem_set = false;
    if (!smem_set) {
        cudaFuncSetAttribute(gemm_tc_kernel,
                             cudaFuncAttributeMaxDynamicSharedMemorySize, GEMM_SMEM);
        smem_set = true;
    }

    // 0. transpose both weights -> fp16 FM16 (one launch)
    transpose_kernel<<<dim3(N1 / 32, DD / 32, 2), 256>>>(
        in_w, (__half*)p_wt1, out_w, (__half*)p_wt2);

    // 1. h = rmsnorm(x) (fp16 FM16), warp-per-row
    rmsnorm_kernel<<<MM / 8, 256>>>(x, norm_w, p_h);

    // 2. xz = h @ in_w  (fp16 output)
    gemm_tc_kernel<<<dim3(N1 / 128, MM / 128), 128, GEMM_SMEM>>>(
        N1, p_h, p_wt1, p_xz, nullptr, nullptr);

    // 3. chunked conv + local scan (LCH=32, 2ch/thread) + carry chain
    conv_local_kernel<<<(BB * NCH * DD / 2) / 256, 256>>>(
        p_xz, conv_w, conv_b, decay, p_hs, p_last);
    carry_kernel<<<(BB * DD) / 256, 256>>>(decay, p_last, p_sin, p_l2a);

    // 4. y = rmsnorm(hs + carry)*silu(z) (fp16 FM16), warp-per-row -> g_h
    gate_kernel<<<MM / 8, 256>>>(p_hs, gate_w, p_xz, p_l2a, p_sin, p_h);

    // 5. out = res_scale*x + y @ out_w  (fp32 + residual)
    gemm_tc_kernel<<<dim3(DD / 128, MM / 128), 128, GEMM_SMEM>>>(
        DD, p_h, p_wt2, out, x, res_scale);
}